// round 2
// baseline (speedup 1.0000x reference)
#include <cuda_runtime.h>
#include <math.h>
#include <stdint.h>

// Problem constants
#define V_ 8000
#define B_ 64
#define T_ 256
#define R_ 1024
#define U_ 512
#define S_ 1024
#define N_ (B_ * T_)   // 16384 rows

// ---------------------------------------------------------------------------
// Scratch (device globals; no allocation allowed)
// ---------------------------------------------------------------------------
__device__ float g_Ph[(size_t)N_ * R_];      // x-part of layer0 h preact, [t*B+b, R]
__device__ float g_Pt[(size_t)N_ * R_];      // x-part of layer0 t preact
__device__ float g_states[(size_t)T_ * B_ * R_]; // state after each step, [t*B+b, R]
__device__ float g_tmpA[B_ * R_];
__device__ float g_tmpB[B_ * R_];
__device__ float g_zero[B_ * R_];
__device__ float g_outb[(size_t)N_ * U_];    // outputs [b*T+t, U]
__device__ float g_logits[(size_t)N_ * S_];  // sampled logits
__device__ float g_sbv[S_];                  // softmax_b[sampled] - log(sampled_counts)
__device__ float g_loss[N_];

// ---------------------------------------------------------------------------
// Small utility kernels
// ---------------------------------------------------------------------------
__global__ void zero_kernel(float* p, int n) {
    int i = blockIdx.x * 256 + threadIdx.x;
    if (i < n) p[i] = 0.f;
}

__global__ void sb_kernel(const int* __restrict__ sampled,
                          const float* __restrict__ softmax_b,
                          const float* __restrict__ scounts,
                          float* __restrict__ sbv) {
    int j = blockIdx.x * 256 + threadIdx.x;
    if (j < S_) sbv[j] = softmax_b[sampled[j]] - logf(scounts[j]);
}

// ---------------------------------------------------------------------------
// Generic fp32 tiled GEMM: C[M,N] = op(A)[M,K] @ op(B)[K,N] + bias
//   AMODE 0: A[row*lda + k]
//   AMODE 2: A[((row % T_)*B_ + row/T_)*lda + k]       (outproj row remap)
//   AMODE 3: A[a_idx[(row % B_)*T_ + row/B_]*lda + k]  (embedding gather)
//   BTRANS 0: B[k*ldb + n]
//   BTRANS 1: B[(b_idx? b_idx[n] : n)*ldb + k]         (softmax_w sampled gather)
// BM=BN=64, BK=16, 256 threads, 4x4 micro-tile.
// ---------------------------------------------------------------------------
template <int AMODE, int BTRANS>
__global__ __launch_bounds__(256)
void sgemm_kernel(const float* __restrict__ A, const float* __restrict__ Bm,
                  const float* __restrict__ bias, float* __restrict__ C,
                  int M, int N, int K, int lda, int ldb, int ldc,
                  const int* __restrict__ a_idx, const int* __restrict__ b_idx) {
    __shared__ float As[16][68];
    __shared__ float Bs[16][68];
    const int bm = blockIdx.y * 64;
    const int bn = blockIdx.x * 64;
    const int tid = threadIdx.x;
    const int tx = tid & 15;
    const int ty = tid >> 4;

    float acc[4][4];
#pragma unroll
    for (int i = 0; i < 4; i++)
#pragma unroll
        for (int j = 0; j < 4; j++) acc[i][j] = 0.f;

    // A-tile loader assignment: each thread loads one float4 of one row
    const int arow_local = tid >> 2;       // 0..63
    const int akk = (tid & 3) * 4;         // 0,4,8,12
    const int grow = bm + arow_local;
    const float* arow_ptr;
    if (AMODE == 0)      arow_ptr = A + (size_t)grow * lda;
    else if (AMODE == 2) arow_ptr = A + (size_t)((grow % T_) * B_ + grow / T_) * lda;
    else                 arow_ptr = A + (size_t)a_idx[(grow % B_) * T_ + grow / B_] * lda;

    const float* brow_ptr = nullptr;
    if (BTRANS == 1) {
        int bncol = bn + (tid >> 2);
        int ridx = b_idx ? b_idx[bncol] : bncol;
        brow_ptr = Bm + (size_t)ridx * ldb;
    }

    for (int k0 = 0; k0 < K; k0 += 16) {
        {   // A tile -> As[k][m]
            float4 va = *(const float4*)(arow_ptr + k0 + akk);
            As[akk + 0][arow_local] = va.x;
            As[akk + 1][arow_local] = va.y;
            As[akk + 2][arow_local] = va.z;
            As[akk + 3][arow_local] = va.w;
        }
        if (BTRANS == 0) {
            int kr = tid >> 4;             // 0..15
            int nn = (tid & 15) * 4;       // 0..60
            float4 vb = *(const float4*)(Bm + (size_t)(k0 + kr) * ldb + bn + nn);
            *(float4*)&Bs[kr][nn] = vb;
        } else {
            float4 vb = *(const float4*)(brow_ptr + k0 + akk);
            int nl = tid >> 2;             // 0..63
            Bs[akk + 0][nl] = vb.x;
            Bs[akk + 1][nl] = vb.y;
            Bs[akk + 2][nl] = vb.z;
            Bs[akk + 3][nl] = vb.w;
        }
        __syncthreads();
#pragma unroll
        for (int k = 0; k < 16; k++) {
            float a[4], b[4];
            *(float4*)a = *(const float4*)&As[k][ty * 4];
            *(float4*)b = *(const float4*)&Bs[k][tx * 4];
#pragma unroll
            for (int i = 0; i < 4; i++)
#pragma unroll
                for (int j = 0; j < 4; j++)
                    acc[i][j] = fmaf(a[i], b[j], acc[i][j]);
        }
        __syncthreads();
    }

#pragma unroll
    for (int i = 0; i < 4; i++) {
        int row = bm + ty * 4 + i;
#pragma unroll
        for (int j = 0; j < 4; j++) {
            int col = bn + tx * 4 + j;
            float v = acc[i][j] + (bias ? bias[col] : 0.f);
            C[(size_t)row * ldc + col] = v;
        }
    }
}

// ---------------------------------------------------------------------------
// Highway stage: given s_in [64,1024] compute
//   zh = s_in @ Wh + addh ; zt = s_in @ Wt + addt
//   s_out = (tanh(zh) - s_in) * sigmoid(zt) + s_in
// addh/addt are per-row [64,1024] when add_per_row=1 (layer 0, precomputed
// x-part + bias) or broadcast [1024] biases otherwise.
// Grid: 128 blocks (8 output cols each, both gates), 256 threads.
// ---------------------------------------------------------------------------
__global__ __launch_bounds__(256)
void stage_kernel(const float* __restrict__ s_in,
                  const float* __restrict__ Wh,
                  const float* __restrict__ Wt,
                  const float* __restrict__ addh,
                  const float* __restrict__ addt,
                  int add_per_row,
                  float* __restrict__ s_out) {
    __shared__ float ss[64][68];
    __shared__ float whs[8][68];
    __shared__ float wts[8][68];
    const int tid = threadIdx.x;
    const int n0 = blockIdx.x * 8;
    const int ms = tid >> 3;   // 0..31
    const int nn = tid & 7;    // 0..7

    float ah0 = 0.f, ah1 = 0.f, at0 = 0.f, at1 = 0.f;

    for (int k0 = 0; k0 < R_; k0 += 64) {
        // state tile 64 x 64
#pragma unroll
        for (int r = tid; r < 1024; r += 256) {
            int m = r >> 4;
            int kq = (r & 15) * 4;
            float4 v = *(const float4*)(s_in + (size_t)m * R_ + k0 + kq);
            *(float4*)&ss[m][kq] = v;
        }
        // weight tiles: threads 0..127 -> Wh, 128..255 -> Wt
        {
            int half = tid >> 7;
            int r = tid & 127;
            int kk = r >> 1;          // 0..63
            int j4 = (r & 1) * 4;     // 0 or 4
            const float* W = half ? Wt : Wh;
            float4 v = *(const float4*)(W + (size_t)(k0 + kk) * R_ + n0 + j4);
            float(*dst)[68] = half ? wts : whs;
            dst[j4 + 0][kk] = v.x;
            dst[j4 + 1][kk] = v.y;
            dst[j4 + 2][kk] = v.z;
            dst[j4 + 3][kk] = v.w;
        }
        __syncthreads();
#pragma unroll
        for (int k = 0; k < 64; k += 4) {
            float4 a0 = *(const float4*)&ss[ms][k];
            float4 a1 = *(const float4*)&ss[ms + 32][k];
            float4 h4 = *(const float4*)&whs[nn][k];
            float4 t4 = *(const float4*)&wts[nn][k];
            ah0 = fmaf(a0.x, h4.x, ah0); ah0 = fmaf(a0.y, h4.y, ah0);
            ah0 = fmaf(a0.z, h4.z, ah0); ah0 = fmaf(a0.w, h4.w, ah0);
            ah1 = fmaf(a1.x, h4.x, ah1); ah1 = fmaf(a1.y, h4.y, ah1);
            ah1 = fmaf(a1.z, h4.z, ah1); ah1 = fmaf(a1.w, h4.w, ah1);
            at0 = fmaf(a0.x, t4.x, at0); at0 = fmaf(a0.y, t4.y, at0);
            at0 = fmaf(a0.z, t4.z, at0); at0 = fmaf(a0.w, t4.w, at0);
            at1 = fmaf(a1.x, t4.x, at1); at1 = fmaf(a1.y, t4.y, at1);
            at1 = fmaf(a1.z, t4.z, at1); at1 = fmaf(a1.w, t4.w, at1);
        }
        __syncthreads();
    }

    const int col = n0 + nn;
#pragma unroll
    for (int half = 0; half < 2; half++) {
        int m = ms + half * 32;
        float zh = (half ? ah1 : ah0);
        float zt = (half ? at1 : at0);
        if (add_per_row) {
            zh += addh[(size_t)m * R_ + col];
            zt += addt[(size_t)m * R_ + col];
        } else {
            zh += addh[col];
            zt += addt[col];
        }
        float h = tanhf(zh);
        float tg = 1.f / (1.f + expf(-zt));
        float sv = s_in[(size_t)m * R_ + col];
        s_out[(size_t)m * R_ + col] = (h - sv) * tg + sv;
    }
}

// ---------------------------------------------------------------------------
// Per-row sampled-softmax loss. One block per row (i = b*T + t).
// ---------------------------------------------------------------------------
__global__ __launch_bounds__(256)
void loss_kernel(const float* __restrict__ outb,
                 const float* __restrict__ logits,
                 const int* __restrict__ targets,
                 const int* __restrict__ sampled,
                 const float* __restrict__ true_counts,
                 const float* __restrict__ sw,
                 const float* __restrict__ softmax_b,
                 float* __restrict__ loss) {
    __shared__ float red[256];
    __shared__ float sh_true, sh_max;
    const int i = blockIdx.x;
    const int tid = threadIdx.x;
    const int label = targets[i];

    // true logit
    float p = 0.f;
    for (int u = tid; u < U_; u += 256)
        p += outb[(size_t)i * U_ + u] * sw[(size_t)label * U_ + u];
    red[tid] = p; __syncthreads();
    for (int s = 128; s > 0; s >>= 1) {
        if (tid < s) red[tid] += red[tid + s];
        __syncthreads();
    }
    if (tid == 0) sh_true = red[0] + softmax_b[label] - logf(true_counts[i]);
    __syncthreads();
    const float tl = sh_true;

    // max over masked logits
    float mx = -1e30f;
    for (int j = tid; j < S_; j += 256) {
        float v = logits[(size_t)i * S_ + j];
        if (sampled[j] == label) v -= 1e9f;
        mx = fmaxf(mx, v);
    }
    red[tid] = mx; __syncthreads();
    for (int s = 128; s > 0; s >>= 1) {
        if (tid < s) red[tid] = fmaxf(red[tid], red[tid + s]);
        __syncthreads();
    }
    if (tid == 0) sh_max = fmaxf(red[0], tl);
    __syncthreads();
    const float m = sh_max;

    // sum of exps
    float sm = 0.f;
    for (int j = tid; j < S_; j += 256) {
        float v = logits[(size_t)i * S_ + j];
        if (sampled[j] == label) v -= 1e9f;
        sm += expf(v - m);
    }
    red[tid] = sm; __syncthreads();
    for (int s = 128; s > 0; s >>= 1) {
        if (tid < s) red[tid] += red[tid + s];
        __syncthreads();
    }
    if (tid == 0) {
        float total = red[0] + expf(tl - m);
        loss[i] = m + logf(total) - tl;   // lse - true_logit
    }
}

__global__ void reduce_mean_kernel(const float* __restrict__ loss, float* __restrict__ out) {
    __shared__ float red[256];
    const int tid = threadIdx.x;
    float s = 0.f;
    for (int i = tid; i < N_; i += 256) s += loss[i];
    red[tid] = s; __syncthreads();
    for (int st = 128; st > 0; st >>= 1) {
        if (tid < st) red[tid] += red[tid + st];
        __syncthreads();
    }
    if (tid == 0) out[0] = red[0] / (float)N_;
}

// ---------------------------------------------------------------------------
// Launch
// ---------------------------------------------------------------------------
extern "C" void kernel_launch(void* const* d_in, const int* in_sizes, int n_in,
                              void* d_out, int out_size) {
    const int*   input_data = (const int*)d_in[0];
    const int*   targets    = (const int*)d_in[1];
    const int*   sampled    = (const int*)d_in[2];
    const float* true_cnt   = (const float*)d_in[3];
    const float* samp_cnt   = (const float*)d_in[4];
    const float* embedding  = (const float*)d_in[5];
    const float* Wh0        = (const float*)d_in[6];
    const float* bh0        = (const float*)d_in[7];
    const float* Wt0        = (const float*)d_in[8];
    const float* bt0        = (const float*)d_in[9];
    const float* Wh         = (const float*)d_in[10];
    const float* bh         = (const float*)d_in[11];
    const float* Wt         = (const float*)d_in[12];
    const float* bt         = (const float*)d_in[13];
    const float* Wp         = (const float*)d_in[14];
    const float* bp         = (const float*)d_in[15];
    const float* sw         = (const float*)d_in[16];
    const float* smb        = (const float*)d_in[17];
    float* out = (float*)d_out;

    float *Ph, *Pt, *states, *tmpA, *tmpB, *zerobuf, *outb, *logits, *sbv, *lossv;
    cudaGetSymbolAddress((void**)&Ph, g_Ph);
    cudaGetSymbolAddress((void**)&Pt, g_Pt);
    cudaGetSymbolAddress((void**)&states, g_states);
    cudaGetSymbolAddress((void**)&tmpA, g_tmpA);
    cudaGetSymbolAddress((void**)&tmpB, g_tmpB);
    cudaGetSymbolAddress((void**)&zerobuf, g_zero);
    cudaGetSymbolAddress((void**)&outb, g_outb);
    cudaGetSymbolAddress((void**)&logits, g_logits);
    cudaGetSymbolAddress((void**)&sbv, g_sbv);
    cudaGetSymbolAddress((void**)&lossv, g_loss);

    zero_kernel<<<(B_ * R_ + 255) / 256, 256>>>(zerobuf, B_ * R_);
    sb_kernel<<<(S_ + 255) / 256, 256>>>(sampled, smb, samp_cnt, sbv);

    // x-part precompute for layer 0 (fully parallel):
    // P_h[t*B+b,:] = embedding[input_data[b,t]] @ Wh0[0:U,:] + bh0
    {
        dim3 grid(R_ / 64, N_ / 64);
        sgemm_kernel<3, 0><<<grid, 256>>>(embedding, Wh0, bh0, Ph,
                                          N_, R_, U_, U_, R_, R_, input_data, nullptr);
        sgemm_kernel<3, 0><<<grid, 256>>>(embedding, Wt0, bt0, Pt,
                                          N_, R_, U_, U_, R_, R_, input_data, nullptr);
    }

    // Serial recurrence: 256 steps x 3 highway layers
    const float* sprev = zerobuf;
    for (int t = 0; t < T_; t++) {
        stage_kernel<<<128, 256>>>(sprev, Wh0 + (size_t)U_ * R_, Wt0 + (size_t)U_ * R_,
                                   Ph + (size_t)t * B_ * R_, Pt + (size_t)t * B_ * R_,
                                   1, tmpA);
        stage_kernel<<<128, 256>>>(tmpA, Wh, Wt, bh, bt, 0, tmpB);
        float* sout = states + (size_t)t * B_ * R_;
        stage_kernel<<<128, 256>>>(tmpB, Wh + (size_t)R_ * R_, Wt + (size_t)R_ * R_,
                                   bh + R_, bt + R_, 0, sout);
        sprev = sout;
    }

    // outputs[b*T+t,:] = states[t*B+b,:] @ Wp + bp
    {
        dim3 grid(U_ / 64, N_ / 64);
        sgemm_kernel<2, 0><<<grid, 256>>>(states, Wp, bp, outb,
                                          N_, U_, R_, R_, U_, U_, nullptr, nullptr);
    }

    // sampled logits: outputs @ softmax_w[sampled].T + (softmax_b[sampled] - log(counts))
    {
        dim3 grid(S_ / 64, N_ / 64);
        sgemm_kernel<0, 1><<<grid, 256>>>(outb, sw, sbv, logits,
                                          N_, S_, U_, U_, U_, S_, nullptr, sampled);
    }

    loss_kernel<<<N_, 256>>>(outb, logits, targets, sampled, true_cnt, sw, smb, lossv);
    reduce_mean_kernel<<<1, 256>>>(lossv, out);
}

// round 3
// speedup vs baseline: 1.5035x; 1.5035x over previous
#include <cuda_runtime.h>
#include <math.h>
#include <stdint.h>

// Problem constants
#define V_ 8000
#define B_ 64
#define T_ 256
#define R_ 1024
#define U_ 512
#define S_ 1024
#define N_ (B_ * T_)   // 16384 rows

// Persistent recurrence config
#define NBLK 128
#define NTHR 256
#define CPB  8          // state columns per block (x2 gates)
#define PHASES (T_ * 3)

// ---------------------------------------------------------------------------
// Scratch (device globals; no allocation allowed)
// ---------------------------------------------------------------------------
__device__ float g_Eh[(size_t)V_ * R_];       // embedding @ Wh0[0:U] + bh0   [V,R]
__device__ float g_Et[(size_t)V_ * R_];       // embedding @ Wt0[0:U] + bt0   [V,R]
__device__ float g_states[(size_t)T_ * B_ * R_]; // state after each step, [t*B+b, R]
__device__ float g_sT[2 * R_ * B_];           // transposed state ping-pong [buf][col][row]
__device__ float g_outb[(size_t)N_ * U_];     // outputs [b*T+t, U]
__device__ float g_logits[(size_t)N_ * S_];   // sampled logits
__device__ float g_sbv[S_];                   // softmax_b[sampled] - log(sampled_counts)
__device__ float g_loss[N_];
__device__ unsigned int g_bar;                // global barrier counter

// ---------------------------------------------------------------------------
// Packed fp32x2 helpers (Blackwell)
// ---------------------------------------------------------------------------
__device__ __forceinline__ unsigned long long fma2(unsigned long long a,
                                                   unsigned long long b,
                                                   unsigned long long c) {
    unsigned long long d;
    asm("fma.rn.f32x2 %0, %1, %2, %3;" : "=l"(d) : "l"(a), "l"(b), "l"(c));
    return d;
}
__device__ __forceinline__ unsigned long long pack2(float x) {
    unsigned long long d;
    asm("mov.b64 %0, {%1, %1};" : "=l"(d) : "f"(x));
    return d;
}
__device__ __forceinline__ void unpack2(unsigned long long v, float& lo, float& hi) {
    asm("mov.b64 {%0, %1}, %2;" : "=f"(lo), "=f"(hi) : "l"(v));
}

// ---------------------------------------------------------------------------
// Small utility kernels
// ---------------------------------------------------------------------------
__global__ void reset_kernel() { g_bar = 0u; }

__global__ void sb_kernel(const int* __restrict__ sampled,
                          const float* __restrict__ softmax_b,
                          const float* __restrict__ scounts,
                          float* __restrict__ sbv) {
    int j = blockIdx.x * 256 + threadIdx.x;
    if (j < S_) sbv[j] = softmax_b[sampled[j]] - logf(scounts[j]);
}

// ---------------------------------------------------------------------------
// Generic fp32 tiled GEMM: C[M,N] = op(A)[M,K] @ op(B)[K,N] + bias
//   AMODE 0: A[row*lda + k]
//   AMODE 2: A[((row % T_)*B_ + row/T_)*lda + k]       (outproj row remap)
//   BTRANS 0: B[k*ldb + n]
//   BTRANS 1: B[(b_idx? b_idx[n] : n)*ldb + k]         (softmax_w sampled gather)
// ---------------------------------------------------------------------------
template <int AMODE, int BTRANS>
__global__ __launch_bounds__(256)
void sgemm_kernel(const float* __restrict__ A, const float* __restrict__ Bm,
                  const float* __restrict__ bias, float* __restrict__ C,
                  int M, int N, int K, int lda, int ldb, int ldc,
                  const int* __restrict__ b_idx) {
    __shared__ float As[16][68];
    __shared__ float Bs[16][68];
    const int bm = blockIdx.y * 64;
    const int bn = blockIdx.x * 64;
    const int tid = threadIdx.x;
    const int tx = tid & 15;
    const int ty = tid >> 4;

    float acc[4][4];
#pragma unroll
    for (int i = 0; i < 4; i++)
#pragma unroll
        for (int j = 0; j < 4; j++) acc[i][j] = 0.f;

    const int arow_local = tid >> 2;       // 0..63
    const int akk = (tid & 3) * 4;         // 0,4,8,12
    const int grow = bm + arow_local;
    const float* arow_ptr;
    if (AMODE == 0)      arow_ptr = A + (size_t)grow * lda;
    else                 arow_ptr = A + (size_t)((grow % T_) * B_ + grow / T_) * lda;

    const float* brow_ptr = nullptr;
    if (BTRANS == 1) {
        int bncol = bn + (tid >> 2);
        int ridx = b_idx ? b_idx[bncol] : bncol;
        brow_ptr = Bm + (size_t)ridx * ldb;
    }

    for (int k0 = 0; k0 < K; k0 += 16) {
        {
            float4 va = *(const float4*)(arow_ptr + k0 + akk);
            As[akk + 0][arow_local] = va.x;
            As[akk + 1][arow_local] = va.y;
            As[akk + 2][arow_local] = va.z;
            As[akk + 3][arow_local] = va.w;
        }
        if (BTRANS == 0) {
            int kr = tid >> 4;
            int nn = (tid & 15) * 4;
            float4 vb = *(const float4*)(Bm + (size_t)(k0 + kr) * ldb + bn + nn);
            *(float4*)&Bs[kr][nn] = vb;
        } else {
            float4 vb = *(const float4*)(brow_ptr + k0 + akk);
            int nl = tid >> 2;
            Bs[akk + 0][nl] = vb.x;
            Bs[akk + 1][nl] = vb.y;
            Bs[akk + 2][nl] = vb.z;
            Bs[akk + 3][nl] = vb.w;
        }
        __syncthreads();
#pragma unroll
        for (int k = 0; k < 16; k++) {
            float a[4], b[4];
            *(float4*)a = *(const float4*)&As[k][ty * 4];
            *(float4*)b = *(const float4*)&Bs[k][tx * 4];
#pragma unroll
            for (int i = 0; i < 4; i++)
#pragma unroll
                for (int j = 0; j < 4; j++)
                    acc[i][j] = fmaf(a[i], b[j], acc[i][j]);
        }
        __syncthreads();
    }

#pragma unroll
    for (int i = 0; i < 4; i++) {
        int row = bm + ty * 4 + i;
#pragma unroll
        for (int j = 0; j < 4; j++) {
            int col = bn + tx * 4 + j;
            float v = acc[i][j] + (bias ? bias[col] : 0.f);
            C[(size_t)row * ldc + col] = v;
        }
    }
}

// ---------------------------------------------------------------------------
// Persistent recurrence kernel.
// 128 blocks, each owns 8 columns of R (both gates, all 3 layers).
// Weights resident in shared memory. 768 phases with a global barrier each.
// State kept transposed sT[col][row], ping-pong buffers, read via L2 (.cg).
// ---------------------------------------------------------------------------
__device__ __forceinline__ void grid_sync(unsigned int target) {
    __threadfence();
    __syncthreads();
    if (threadIdx.x == 0) {
        atomicAdd(&g_bar, 1u);
        volatile unsigned int* vb = &g_bar;
        while (*vb < target) { }
        __threadfence();
    }
    __syncthreads();
}

__global__ __launch_bounds__(NTHR, 1)
void recurrence_kernel(const float* __restrict__ Wh0, const float* __restrict__ Wt0,
                       const float* __restrict__ Wh,  const float* __restrict__ Wt,
                       const float* __restrict__ bh,  const float* __restrict__ bt,
                       const int*   __restrict__ input_data,
                       const float* __restrict__ Eh,  const float* __restrict__ Et,
                       float* __restrict__ sT, float* __restrict__ states) {
    extern __shared__ float smem[];
    float* smw = smem;              // [3][1024][16] weights: per k, 8 h-cols then 8 t-cols
    float* smp = smem + 3 * 1024 * 16;  // partials [4][64][18]

    const int tid  = threadIdx.x;
    const int lane = tid & 31;
    const int w    = tid >> 5;
    const int rh   = w & 1;         // row half: rows rh*32..rh*32+31
    const int ks   = w >> 1;        // K quarter: k in [ks*256, ks*256+256)
    const int colbase = blockIdx.x * CPB;
    const int m    = rh * 32 + lane;
    const int k0   = ks * 256;

    // ---- load weights into smem (once) ----
    const int wtotal = 3 * 1024 * 16;
    for (int i = tid; i < wtotal; i += NTHR) {
        int l   = i >> 14;              // / 16384
        int rem = i & 16383;
        int k   = rem >> 4;
        int cg  = rem & 15;
        int g   = cg >> 3;
        int c   = cg & 7;
        int gcol = colbase + c;
        float v;
        if (l == 0) {
            v = g ? Wt0[(size_t)(U_ + k) * R_ + gcol]
                  : Wh0[(size_t)(U_ + k) * R_ + gcol];
        } else {
            const float* W = g ? Wt : Wh;
            v = W[(size_t)(l - 1) * R_ * R_ + (size_t)k * R_ + gcol];
        }
        smw[i] = v;
    }

    // ---- zero both state buffers ----
    for (int i = blockIdx.x * NTHR + tid; i < 2 * R_ * B_; i += NBLK * NTHR)
        sT[i] = 0.f;

    unsigned int pc = 1;
    grid_sync(NBLK * pc);

    int t = 0, l = 0;
    for (int p = 0; p < PHASES; p++) {
        const int rcur = p & 1;
        const float* sin = sT + rcur * (R_ * B_);
        float* sout = sT + (rcur ^ 1) * (R_ * B_);

        // ---- main dot products: 32 rows x 16 outs over K quarter ----
        unsigned long long acc[8];
#pragma unroll
        for (int j = 0; j < 8; j++) acc[j] = 0ull;

        const float* sp = sin + (size_t)k0 * B_ + m;
        const ulonglong2* wp = (const ulonglong2*)(smw + ((size_t)l * 1024 + k0) * 16);

#pragma unroll 8
        for (int k = 0; k < 256; k++) {
            float sv = __ldcg(sp + k * B_);
            unsigned long long sv2 = pack2(sv);
            ulonglong2 wa = wp[k * 4 + 0];
            ulonglong2 wb = wp[k * 4 + 1];
            ulonglong2 wc = wp[k * 4 + 2];
            ulonglong2 wd = wp[k * 4 + 3];
            acc[0] = fma2(sv2, wa.x, acc[0]);
            acc[1] = fma2(sv2, wa.y, acc[1]);
            acc[2] = fma2(sv2, wb.x, acc[2]);
            acc[3] = fma2(sv2, wb.y, acc[3]);
            acc[4] = fma2(sv2, wc.x, acc[4]);
            acc[5] = fma2(sv2, wc.y, acc[5]);
            acc[6] = fma2(sv2, wd.x, acc[6]);
            acc[7] = fma2(sv2, wd.y, acc[7]);
        }

        // ---- store K-partials to smem ----
        float* pr = smp + (ks * 64 + m) * 18;
#pragma unroll
        for (int j = 0; j < 8; j++) {
            float lo, hi;
            unpack2(acc[j], lo, hi);
            pr[2 * j]     = lo;
            pr[2 * j + 1] = hi;
        }
        __syncthreads();

        // ---- reduce across K-splits + activation + state update ----
#pragma unroll
        for (int it = 0; it < 2; it++) {
            int idx = tid + it * 256;
            int row = idx & 63;
            int c   = idx >> 6;
            float zh = 0.f, zt = 0.f;
#pragma unroll
            for (int q = 0; q < 4; q++) {
                zh += smp[(q * 64 + row) * 18 + c];
                zt += smp[(q * 64 + row) * 18 + 8 + c];
            }
            int gcol = colbase + c;
            if (l == 0) {
                int vid = __ldg(&input_data[row * T_ + t]);
                zh += __ldg(&Eh[(size_t)vid * R_ + gcol]);
                zt += __ldg(&Et[(size_t)vid * R_ + gcol]);
            } else {
                zh += __ldg(&bh[(l - 1) * R_ + gcol]);
                zt += __ldg(&bt[(l - 1) * R_ + gcol]);
            }
            float sold = __ldcg(sin + gcol * B_ + row);
            float hh = tanhf(zh);
            float tg = 1.f / (1.f + expf(-zt));
            float sn = (hh - sold) * tg + sold;
            __stcg(sout + gcol * B_ + row, sn);
            if (l == 2)
                states[((size_t)t * B_ + row) * R_ + gcol] = sn;
        }

        pc++;
        grid_sync(NBLK * pc);

        if (++l == 3) { l = 0; t++; }
    }
}

// ---------------------------------------------------------------------------
// Per-row sampled-softmax loss. One block per row (i = b*T + t).
// ---------------------------------------------------------------------------
__global__ __launch_bounds__(256)
void loss_kernel(const float* __restrict__ outb,
                 const float* __restrict__ logits,
                 const int* __restrict__ targets,
                 const int* __restrict__ sampled,
                 const float* __restrict__ true_counts,
                 const float* __restrict__ sw,
                 const float* __restrict__ softmax_b,
                 float* __restrict__ loss) {
    __shared__ float red[256];
    __shared__ float sh_true, sh_max;
    const int i = blockIdx.x;
    const int tid = threadIdx.x;
    const int label = targets[i];

    float p = 0.f;
    for (int u = tid; u < U_; u += 256)
        p += outb[(size_t)i * U_ + u] * sw[(size_t)label * U_ + u];
    red[tid] = p; __syncthreads();
    for (int s = 128; s > 0; s >>= 1) {
        if (tid < s) red[tid] += red[tid + s];
        __syncthreads();
    }
    if (tid == 0) sh_true = red[0] + softmax_b[label] - logf(true_counts[i]);
    __syncthreads();
    const float tl = sh_true;

    float mx = -1e30f;
    for (int j = tid; j < S_; j += 256) {
        float v = logits[(size_t)i * S_ + j];
        if (sampled[j] == label) v -= 1e9f;
        mx = fmaxf(mx, v);
    }
    red[tid] = mx; __syncthreads();
    for (int s = 128; s > 0; s >>= 1) {
        if (tid < s) red[tid] = fmaxf(red[tid], red[tid + s]);
        __syncthreads();
    }
    if (tid == 0) sh_max = fmaxf(red[0], tl);
    __syncthreads();
    const float mval = sh_max;

    float sm = 0.f;
    for (int j = tid; j < S_; j += 256) {
        float v = logits[(size_t)i * S_ + j];
        if (sampled[j] == label) v -= 1e9f;
        sm += expf(v - mval);
    }
    red[tid] = sm; __syncthreads();
    for (int s = 128; s > 0; s >>= 1) {
        if (tid < s) red[tid] += red[tid + s];
        __syncthreads();
    }
    if (tid == 0) {
        float total = red[0] + expf(tl - mval);
        loss[i] = mval + logf(total) - tl;
    }
}

__global__ void reduce_mean_kernel(const float* __restrict__ loss, float* __restrict__ out) {
    __shared__ float red[256];
    const int tid = threadIdx.x;
    float s = 0.f;
    for (int i = tid; i < N_; i += 256) s += loss[i];
    red[tid] = s; __syncthreads();
    for (int st = 128; st > 0; st >>= 1) {
        if (tid < st) red[tid] += red[tid + st];
        __syncthreads();
    }
    if (tid == 0) out[0] = red[0] / (float)N_;
}

// ---------------------------------------------------------------------------
// Launch
// ---------------------------------------------------------------------------
extern "C" void kernel_launch(void* const* d_in, const int* in_sizes, int n_in,
                              void* d_out, int out_size) {
    const int*   input_data = (const int*)d_in[0];
    const int*   targets    = (const int*)d_in[1];
    const int*   sampled    = (const int*)d_in[2];
    const float* true_cnt   = (const float*)d_in[3];
    const float* samp_cnt   = (const float*)d_in[4];
    const float* embedding  = (const float*)d_in[5];
    const float* Wh0        = (const float*)d_in[6];
    const float* bh0        = (const float*)d_in[7];
    const float* Wt0        = (const float*)d_in[8];
    const float* bt0        = (const float*)d_in[9];
    const float* Wh         = (const float*)d_in[10];
    const float* bh         = (const float*)d_in[11];
    const float* Wt         = (const float*)d_in[12];
    const float* bt         = (const float*)d_in[13];
    const float* Wp         = (const float*)d_in[14];
    const float* bp         = (const float*)d_in[15];
    const float* sw         = (const float*)d_in[16];
    const float* smb        = (const float*)d_in[17];
    float* out = (float*)d_out;

    float *Eh, *Et, *states, *sT, *outb, *logits, *sbv, *lossv;
    cudaGetSymbolAddress((void**)&Eh, g_Eh);
    cudaGetSymbolAddress((void**)&Et, g_Et);
    cudaGetSymbolAddress((void**)&states, g_states);
    cudaGetSymbolAddress((void**)&sT, g_sT);
    cudaGetSymbolAddress((void**)&outb, g_outb);
    cudaGetSymbolAddress((void**)&logits, g_logits);
    cudaGetSymbolAddress((void**)&sbv, g_sbv);
    cudaGetSymbolAddress((void**)&lossv, g_loss);

    static int smem_set = 0;
    if (!smem_set) {
        cudaFuncSetAttribute(recurrence_kernel,
                             cudaFuncAttributeMaxDynamicSharedMemorySize,
                             (3 * 1024 * 16 + 4 * 64 * 18) * 4);
        smem_set = 1;
    }

    reset_kernel<<<1, 1>>>();
    sb_kernel<<<(S_ + 255) / 256, 256>>>(sampled, smb, samp_cnt, sbv);

    // Vocab-space x-part precompute for layer 0:
    // Eh[v,:] = embedding[v] @ Wh0[0:U,:] + bh0 ; Et similarly with Wt0/bt0
    {
        dim3 grid(R_ / 64, V_ / 64);
        sgemm_kernel<0, 0><<<grid, 256>>>(embedding, Wh0, bh0, Eh,
                                          V_, R_, U_, U_, R_, R_, nullptr);
        sgemm_kernel<0, 0><<<grid, 256>>>(embedding, Wt0, bt0, Et,
                                          V_, R_, U_, U_, R_, R_, nullptr);
    }

    // Entire serial recurrence in ONE persistent kernel
    recurrence_kernel<<<NBLK, NTHR, (3 * 1024 * 16 + 4 * 64 * 18) * 4>>>(
        Wh0, Wt0, Wh, Wt, bh, bt, input_data, Eh, Et, sT, states);

    // outputs[b*T+t,:] = states[t*B+b,:] @ Wp + bp
    {
        dim3 grid(U_ / 64, N_ / 64);
        sgemm_kernel<2, 0><<<grid, 256>>>(states, Wp, bp, outb,
                                          N_, U_, R_, R_, U_, U_, nullptr);
    }

    // sampled logits: outputs @ softmax_w[sampled].T + (softmax_b[sampled] - log(counts))
    {
        dim3 grid(S_ / 64, N_ / 64);
        sgemm_kernel<0, 1><<<grid, 256>>>(outb, sw, sbv, logits,
                                          N_, S_, U_, U_, U_, S_, sampled);
    }

    loss_kernel<<<N_, 256>>>(outb, logits, targets, sampled, true_cnt, sw, smb, lossv);
    reduce_mean_kernel<<<1, 256>>>(lossv, out);
}

// round 4
// speedup vs baseline: 1.7169x; 1.1419x over previous
#include <cuda_runtime.h>
#include <math.h>
#include <stdint.h>

// Problem constants
#define V_ 8000
#define B_ 64
#define T_ 256
#define R_ 1024
#define U_ 512
#define S_ 1024
#define N_ (B_ * T_)   // 16384 rows

// Persistent recurrence config
#define NBLK 128
#define NTHR 512
#define CPB  8          // state columns per block (x2 gates = 16 outputs)
#define PHASES (T_ * 3)
#define KSPLIT 8
#define KITER (R_ / KSPLIT)   // 128

// ---------------------------------------------------------------------------
// Scratch (device globals; no allocation allowed)
// ---------------------------------------------------------------------------
__device__ float g_Eh[(size_t)V_ * R_];       // embedding @ Wh0[0:U] + bh0   [V,R]
__device__ float g_Et[(size_t)V_ * R_];       // embedding @ Wt0[0:U] + bt0   [V,R]
__device__ float g_states[(size_t)T_ * B_ * R_]; // state after each step, [t*B+b, R]
__device__ float g_sT[2 * R_ * B_];           // transposed state ping-pong [buf][col][row]
__device__ float g_outb[(size_t)N_ * U_];     // outputs [b*T+t, U]
__device__ float g_logits[(size_t)N_ * S_];   // sampled logits
__device__ float g_sbv[S_];                   // softmax_b[sampled] - log(sampled_counts)
__device__ float g_loss[N_];
__device__ unsigned int g_bar;                // global barrier counter

// ---------------------------------------------------------------------------
// Packed fp32x2 helpers (Blackwell)
// ---------------------------------------------------------------------------
__device__ __forceinline__ unsigned long long fma2(unsigned long long a,
                                                   unsigned long long b,
                                                   unsigned long long c) {
    unsigned long long d;
    asm("fma.rn.f32x2 %0, %1, %2, %3;" : "=l"(d) : "l"(a), "l"(b), "l"(c));
    return d;
}
__device__ __forceinline__ unsigned long long pack2(float x) {
    unsigned long long d;
    asm("mov.b64 %0, {%1, %1};" : "=l"(d) : "f"(x));
    return d;
}
__device__ __forceinline__ void unpack2(unsigned long long v, float& lo, float& hi) {
    asm("mov.b64 {%0, %1}, %2;" : "=f"(lo), "=f"(hi) : "l"(v));
}

// ---------------------------------------------------------------------------
// Small utility kernels
// ---------------------------------------------------------------------------
__global__ void reset_kernel() { g_bar = 0u; }

__global__ void sb_kernel(const int* __restrict__ sampled,
                          const float* __restrict__ softmax_b,
                          const float* __restrict__ scounts,
                          float* __restrict__ sbv) {
    int j = blockIdx.x * 256 + threadIdx.x;
    if (j < S_) sbv[j] = softmax_b[sampled[j]] - logf(scounts[j]);
}

// ---------------------------------------------------------------------------
// Generic fp32 tiled GEMM: C[M,N] = op(A)[M,K] @ op(B)[K,N] + bias
// ---------------------------------------------------------------------------
template <int AMODE, int BTRANS>
__global__ __launch_bounds__(256)
void sgemm_kernel(const float* __restrict__ A, const float* __restrict__ Bm,
                  const float* __restrict__ bias, float* __restrict__ C,
                  int M, int N, int K, int lda, int ldb, int ldc,
                  const int* __restrict__ b_idx) {
    __shared__ float As[16][68];
    __shared__ float Bs[16][68];
    const int bm = blockIdx.y * 64;
    const int bn = blockIdx.x * 64;
    const int tid = threadIdx.x;
    const int tx = tid & 15;
    const int ty = tid >> 4;

    float acc[4][4];
#pragma unroll
    for (int i = 0; i < 4; i++)
#pragma unroll
        for (int j = 0; j < 4; j++) acc[i][j] = 0.f;

    const int arow_local = tid >> 2;
    const int akk = (tid & 3) * 4;
    const int grow = bm + arow_local;
    const float* arow_ptr;
    if (AMODE == 0)      arow_ptr = A + (size_t)grow * lda;
    else                 arow_ptr = A + (size_t)((grow % T_) * B_ + grow / T_) * lda;

    const float* brow_ptr = nullptr;
    if (BTRANS == 1) {
        int bncol = bn + (tid >> 2);
        int ridx = b_idx ? b_idx[bncol] : bncol;
        brow_ptr = Bm + (size_t)ridx * ldb;
    }

    for (int k0 = 0; k0 < K; k0 += 16) {
        {
            float4 va = *(const float4*)(arow_ptr + k0 + akk);
            As[akk + 0][arow_local] = va.x;
            As[akk + 1][arow_local] = va.y;
            As[akk + 2][arow_local] = va.z;
            As[akk + 3][arow_local] = va.w;
        }
        if (BTRANS == 0) {
            int kr = tid >> 4;
            int nn = (tid & 15) * 4;
            float4 vb = *(const float4*)(Bm + (size_t)(k0 + kr) * ldb + bn + nn);
            *(float4*)&Bs[kr][nn] = vb;
        } else {
            float4 vb = *(const float4*)(brow_ptr + k0 + akk);
            int nl = tid >> 2;
            Bs[akk + 0][nl] = vb.x;
            Bs[akk + 1][nl] = vb.y;
            Bs[akk + 2][nl] = vb.z;
            Bs[akk + 3][nl] = vb.w;
        }
        __syncthreads();
#pragma unroll
        for (int k = 0; k < 16; k++) {
            float a[4], b[4];
            *(float4*)a = *(const float4*)&As[k][ty * 4];
            *(float4*)b = *(const float4*)&Bs[k][tx * 4];
#pragma unroll
            for (int i = 0; i < 4; i++)
#pragma unroll
                for (int j = 0; j < 4; j++)
                    acc[i][j] = fmaf(a[i], b[j], acc[i][j]);
        }
        __syncthreads();
    }

#pragma unroll
    for (int i = 0; i < 4; i++) {
        int row = bm + ty * 4 + i;
#pragma unroll
        for (int j = 0; j < 4; j++) {
            int col = bn + tx * 4 + j;
            float v = acc[i][j] + (bias ? bias[col] : 0.f);
            C[(size_t)row * ldc + col] = v;
        }
    }
}

// ---------------------------------------------------------------------------
// Persistent recurrence kernel. 128 blocks x 512 threads.
// Each block owns 8 state columns (16 gate outputs, all 3 layers' weights in
// shared memory). 768 phases; light release/acquire global barrier per phase.
// Warp partition: 16 warps = (row-half rh in {0,1}) x (K-eighth ks in 0..7).
// ---------------------------------------------------------------------------
__device__ __forceinline__ void grid_sync(unsigned int target, unsigned int* bar) {
    __syncthreads();
    if (threadIdx.x == 0) {
        asm volatile("red.release.gpu.global.add.u32 [%0], 1;" :: "l"(bar) : "memory");
        unsigned int v;
        do {
            asm volatile("ld.acquire.gpu.global.u32 %0, [%1];" : "=r"(v) : "l"(bar) : "memory");
        } while (v < target);
    }
    __syncthreads();
}

__global__ __launch_bounds__(NTHR, 1)
void recurrence_kernel(const float* __restrict__ Wh0, const float* __restrict__ Wt0,
                       const float* __restrict__ Wh,  const float* __restrict__ Wt,
                       const float* __restrict__ bh,  const float* __restrict__ bt,
                       const int*   __restrict__ input_data,
                       const float* __restrict__ Eh,  const float* __restrict__ Et,
                       float* __restrict__ sT, float* __restrict__ states) {
    extern __shared__ float smem[];
    float* smw = smem;                   // [3][1024][16]
    float* smp = smem + 3 * 1024 * 16;   // partials [KSPLIT][64][17]

    const int tid  = threadIdx.x;
    const int lane = tid & 31;
    const int w    = tid >> 5;           // 0..15
    const int rh   = w & 1;              // row half
    const int ks   = w >> 1;             // 0..7 K-eighth
    const int colbase = blockIdx.x * CPB;
    const int m    = rh * 32 + lane;     // 0..63 row
    const int k0   = ks * KITER;

    unsigned int* bar = &g_bar;

    // ---- load weights into smem (once) ----
    const int wtotal = 3 * 1024 * 16;
    for (int i = tid; i < wtotal; i += NTHR) {
        int l   = i >> 14;
        int rem = i & 16383;
        int k   = rem >> 4;
        int cg  = rem & 15;
        int g   = cg >> 3;
        int c   = cg & 7;
        int gcol = colbase + c;
        float v;
        if (l == 0) {
            v = g ? Wt0[(size_t)(U_ + k) * R_ + gcol]
                  : Wh0[(size_t)(U_ + k) * R_ + gcol];
        } else {
            const float* W = g ? Wt : Wh;
            v = W[(size_t)(l - 1) * R_ * R_ + (size_t)k * R_ + gcol];
        }
        smw[i] = v;
    }

    // ---- zero both state buffers ----
    for (int i = blockIdx.x * NTHR + tid; i < 2 * R_ * B_; i += NBLK * NTHR)
        sT[i] = 0.f;

    unsigned int pc = 1;
    grid_sync(NBLK * pc, bar);

    int t = 0, l = 0;
    for (int p = 0; p < PHASES; p++) {
        const int rcur = p & 1;
        const float* sin = sT + rcur * (R_ * B_);
        float* sout = sT + (rcur ^ 1) * (R_ * B_);

        // ---- main dot products: 64 rows x 16 outs over K-eighth ----
        unsigned long long acc[8];
#pragma unroll
        for (int j = 0; j < 8; j++) acc[j] = 0ull;

        const float* sp = sin + (size_t)k0 * B_ + m;
        const ulonglong2* wp = (const ulonglong2*)(smw + ((size_t)l * 1024 + k0) * 16);

#pragma unroll 4
        for (int k = 0; k < KITER; k++) {
            float sv = __ldcg(sp + k * B_);
            unsigned long long sv2 = pack2(sv);
            ulonglong2 wa = wp[k * 4 + 0];
            ulonglong2 wb = wp[k * 4 + 1];
            ulonglong2 wc = wp[k * 4 + 2];
            ulonglong2 wd = wp[k * 4 + 3];
            acc[0] = fma2(sv2, wa.x, acc[0]);
            acc[1] = fma2(sv2, wa.y, acc[1]);
            acc[2] = fma2(sv2, wb.x, acc[2]);
            acc[3] = fma2(sv2, wb.y, acc[3]);
            acc[4] = fma2(sv2, wc.x, acc[4]);
            acc[5] = fma2(sv2, wc.y, acc[5]);
            acc[6] = fma2(sv2, wd.x, acc[6]);
            acc[7] = fma2(sv2, wd.y, acc[7]);
        }

        // ---- store K-partials to smem ----
        float* pr = smp + (ks * 64 + m) * 17;
#pragma unroll
        for (int j = 0; j < 8; j++) {
            float lo, hi;
            unpack2(acc[j], lo, hi);
            pr[2 * j]     = lo;
            pr[2 * j + 1] = hi;
        }
        __syncthreads();

        // ---- reduce across K-splits + activation + state update ----
        {
            int row = tid & 63;
            int c   = tid >> 6;            // 0..7
            float zh = 0.f, zt = 0.f;
#pragma unroll
            for (int q = 0; q < KSPLIT; q++) {
                zh += smp[(q * 64 + row) * 17 + c];
                zt += smp[(q * 64 + row) * 17 + 8 + c];
            }
            int gcol = colbase + c;
            if (l == 0) {
                int vid = __ldg(&input_data[row * T_ + t]);
                zh += __ldg(&Eh[(size_t)vid * R_ + gcol]);
                zt += __ldg(&Et[(size_t)vid * R_ + gcol]);
            } else {
                zh += __ldg(&bh[(l - 1) * R_ + gcol]);
                zt += __ldg(&bt[(l - 1) * R_ + gcol]);
            }
            float sold = __ldcg(sin + gcol * B_ + row);
            float hh = tanhf(zh);
            float tg = 1.f / (1.f + expf(-zt));
            float sn = (hh - sold) * tg + sold;
            __stcg(sout + gcol * B_ + row, sn);
            if (l == 2)
                states[((size_t)t * B_ + row) * R_ + gcol] = sn;
        }

        pc++;
        grid_sync(NBLK * pc, bar);

        if (++l == 3) { l = 0; t++; }
    }
}

// ---------------------------------------------------------------------------
// Per-row sampled-softmax loss. One block per row (i = b*T + t).
// ---------------------------------------------------------------------------
__global__ __launch_bounds__(256)
void loss_kernel(const float* __restrict__ outb,
                 const float* __restrict__ logits,
                 const int* __restrict__ targets,
                 const int* __restrict__ sampled,
                 const float* __restrict__ true_counts,
                 const float* __restrict__ sw,
                 const float* __restrict__ softmax_b,
                 float* __restrict__ loss) {
    __shared__ float red[256];
    __shared__ float sh_true, sh_max;
    const int i = blockIdx.x;
    const int tid = threadIdx.x;
    const int label = targets[i];

    float p = 0.f;
    for (int u = tid; u < U_; u += 256)
        p += outb[(size_t)i * U_ + u] * sw[(size_t)label * U_ + u];
    red[tid] = p; __syncthreads();
    for (int s = 128; s > 0; s >>= 1) {
        if (tid < s) red[tid] += red[tid + s];
        __syncthreads();
    }
    if (tid == 0) sh_true = red[0] + softmax_b[label] - logf(true_counts[i]);
    __syncthreads();
    const float tl = sh_true;

    float mx = -1e30f;
    for (int j = tid; j < S_; j += 256) {
        float v = logits[(size_t)i * S_ + j];
        if (sampled[j] == label) v -= 1e9f;
        mx = fmaxf(mx, v);
    }
    red[tid] = mx; __syncthreads();
    for (int s = 128; s > 0; s >>= 1) {
        if (tid < s) red[tid] = fmaxf(red[tid], red[tid + s]);
        __syncthreads();
    }
    if (tid == 0) sh_max = fmaxf(red[0], tl);
    __syncthreads();
    const float mval = sh_max;

    float sm = 0.f;
    for (int j = tid; j < S_; j += 256) {
        float v = logits[(size_t)i * S_ + j];
        if (sampled[j] == label) v -= 1e9f;
        sm += expf(v - mval);
    }
    red[tid] = sm; __syncthreads();
    for (int s = 128; s > 0; s >>= 1) {
        if (tid < s) red[tid] += red[tid + s];
        __syncthreads();
    }
    if (tid == 0) {
        float total = red[0] + expf(tl - mval);
        loss[i] = mval + logf(total) - tl;
    }
}

__global__ void reduce_mean_kernel(const float* __restrict__ loss, float* __restrict__ out) {
    __shared__ float red[256];
    const int tid = threadIdx.x;
    float s = 0.f;
    for (int i = tid; i < N_; i += 256) s += loss[i];
    red[tid] = s; __syncthreads();
    for (int st = 128; st > 0; st >>= 1) {
        if (tid < st) red[tid] += red[tid + st];
        __syncthreads();
    }
    if (tid == 0) out[0] = red[0] / (float)N_;
}

// ---------------------------------------------------------------------------
// Launch
// ---------------------------------------------------------------------------
extern "C" void kernel_launch(void* const* d_in, const int* in_sizes, int n_in,
                              void* d_out, int out_size) {
    const int*   input_data = (const int*)d_in[0];
    const int*   targets    = (const int*)d_in[1];
    const int*   sampled    = (const int*)d_in[2];
    const float* true_cnt   = (const float*)d_in[3];
    const float* samp_cnt   = (const float*)d_in[4];
    const float* embedding  = (const float*)d_in[5];
    const float* Wh0        = (const float*)d_in[6];
    const float* bh0        = (const float*)d_in[7];
    const float* Wt0        = (const float*)d_in[8];
    const float* bt0        = (const float*)d_in[9];
    const float* Wh         = (const float*)d_in[10];
    const float* bh         = (const float*)d_in[11];
    const float* Wt         = (const float*)d_in[12];
    const float* bt         = (const float*)d_in[13];
    const float* Wp         = (const float*)d_in[14];
    const float* bp         = (const float*)d_in[15];
    const float* sw         = (const float*)d_in[16];
    const float* smb        = (const float*)d_in[17];
    float* out = (float*)d_out;

    float *Eh, *Et, *states, *sT, *outb, *logits, *sbv, *lossv;
    cudaGetSymbolAddress((void**)&Eh, g_Eh);
    cudaGetSymbolAddress((void**)&Et, g_Et);
    cudaGetSymbolAddress((void**)&states, g_states);
    cudaGetSymbolAddress((void**)&sT, g_sT);
    cudaGetSymbolAddress((void**)&outb, g_outb);
    cudaGetSymbolAddress((void**)&logits, g_logits);
    cudaGetSymbolAddress((void**)&sbv, g_sbv);
    cudaGetSymbolAddress((void**)&lossv, g_loss);

    const int rec_smem = (3 * 1024 * 16 + KSPLIT * 64 * 17) * 4;  // 231424 B
    static int smem_set = 0;
    if (!smem_set) {
        cudaFuncSetAttribute(recurrence_kernel,
                             cudaFuncAttributeMaxDynamicSharedMemorySize, rec_smem);
        smem_set = 1;
    }

    reset_kernel<<<1, 1>>>();
    sb_kernel<<<(S_ + 255) / 256, 256>>>(sampled, smb, samp_cnt, sbv);

    // Vocab-space x-part precompute for layer 0
    {
        dim3 grid(R_ / 64, V_ / 64);
        sgemm_kernel<0, 0><<<grid, 256>>>(embedding, Wh0, bh0, Eh,
                                          V_, R_, U_, U_, R_, R_, nullptr);
        sgemm_kernel<0, 0><<<grid, 256>>>(embedding, Wt0, bt0, Et,
                                          V_, R_, U_, U_, R_, R_, nullptr);
    }

    // Entire serial recurrence in ONE persistent kernel
    recurrence_kernel<<<NBLK, NTHR, rec_smem>>>(
        Wh0, Wt0, Wh, Wt, bh, bt, input_data, Eh, Et, sT, states);

    // outputs[b*T+t,:] = states[t*B+b,:] @ Wp + bp
    {
        dim3 grid(U_ / 64, N_ / 64);
        sgemm_kernel<2, 0><<<grid, 256>>>(states, Wp, bp, outb,
                                          N_, U_, R_, R_, U_, U_, nullptr);
    }

    // sampled logits
    {
        dim3 grid(S_ / 64, N_ / 64);
        sgemm_kernel<0, 1><<<grid, 256>>>(outb, sw, sbv, logits,
                                          N_, S_, U_, U_, U_, S_, sampled);
    }

    loss_kernel<<<N_, 256>>>(outb, logits, targets, sampled, true_cnt, sw, smb, lossv);
    reduce_mean_kernel<<<1, 256>>>(lossv, out);
}

// round 5
// speedup vs baseline: 1.7189x; 1.0012x over previous
#include <cuda_runtime.h>
#include <math.h>
#include <stdint.h>

// Problem constants
#define V_ 8000
#define B_ 64
#define T_ 256
#define R_ 1024
#define U_ 512
#define S_ 1024
#define N_ (B_ * T_)   // 16384 rows

// Persistent recurrence config
#define NBLK 128
#define NTHR 512
#define CPB  8          // state columns per block (x2 gates = 16 outputs)
#define PHASES (T_ * 3)
#define KSPLIT 8
#define KITER (R_ / KSPLIT)   // 128

// ---------------------------------------------------------------------------
// Scratch (device globals; no allocation allowed)
// ---------------------------------------------------------------------------
__device__ float g_Eh[(size_t)V_ * R_];       // embedding @ Wh0[0:U] + bh0   [V,R]
__device__ float g_Et[(size_t)V_ * R_];       // embedding @ Wt0[0:U] + bt0   [V,R]
__device__ float g_states[(size_t)T_ * B_ * R_]; // state after each step, [t*B+b, R]
__device__ float g_sT[2 * R_ * B_];           // transposed state ping-pong [buf][col][row]
__device__ float g_outb[(size_t)N_ * U_];     // outputs [b*T+t, U]
__device__ float g_logits[(size_t)N_ * S_];   // sampled logits
__device__ float g_sbv[S_];                   // softmax_b[sampled] - log(sampled_counts)
__device__ float g_loss[N_];
__device__ unsigned int g_bar;                // global barrier counter

// ---------------------------------------------------------------------------
// Packed fp32x2 helpers (Blackwell)
// ---------------------------------------------------------------------------
__device__ __forceinline__ unsigned long long fma2(unsigned long long a,
                                                   unsigned long long b,
                                                   unsigned long long c) {
    unsigned long long d;
    asm("fma.rn.f32x2 %0, %1, %2, %3;" : "=l"(d) : "l"(a), "l"(b), "l"(c));
    return d;
}
__device__ __forceinline__ unsigned long long pack2(float x) {
    unsigned long long d;
    asm("mov.b64 %0, {%1, %1};" : "=l"(d) : "f"(x));
    return d;
}
__device__ __forceinline__ void unpack2(unsigned long long v, float& lo, float& hi) {
    asm("mov.b64 {%0, %1}, %2;" : "=f"(lo), "=f"(hi) : "l"(v));
}

// ---------------------------------------------------------------------------
// Small utility kernels
// ---------------------------------------------------------------------------
__global__ void reset_kernel() { g_bar = 0u; }

__global__ void sb_kernel(const int* __restrict__ sampled,
                          const float* __restrict__ softmax_b,
                          const float* __restrict__ scounts,
                          float* __restrict__ sbv) {
    int j = blockIdx.x * 256 + threadIdx.x;
    if (j < S_) sbv[j] = softmax_b[sampled[j]] - logf(scounts[j]);
}

// ---------------------------------------------------------------------------
// Generic fp32 tiled GEMM: C[M,N] = op(A)[M,K] @ op(B)[K,N] + bias
// ---------------------------------------------------------------------------
template <int AMODE, int BTRANS>
__global__ __launch_bounds__(256)
void sgemm_kernel(const float* __restrict__ A, const float* __restrict__ Bm,
                  const float* __restrict__ bias, float* __restrict__ C,
                  int M, int N, int K, int lda, int ldb, int ldc,
                  const int* __restrict__ b_idx) {
    __shared__ float As[16][68];
    __shared__ float Bs[16][68];
    const int bm = blockIdx.y * 64;
    const int bn = blockIdx.x * 64;
    const int tid = threadIdx.x;
    const int tx = tid & 15;
    const int ty = tid >> 4;

    float acc[4][4];
#pragma unroll
    for (int i = 0; i < 4; i++)
#pragma unroll
        for (int j = 0; j < 4; j++) acc[i][j] = 0.f;

    const int arow_local = tid >> 2;
    const int akk = (tid & 3) * 4;
    const int grow = bm + arow_local;
    const float* arow_ptr;
    if (AMODE == 0)      arow_ptr = A + (size_t)grow * lda;
    else                 arow_ptr = A + (size_t)((grow % T_) * B_ + grow / T_) * lda;

    const float* brow_ptr = nullptr;
    if (BTRANS == 1) {
        int bncol = bn + (tid >> 2);
        int ridx = b_idx ? b_idx[bncol] : bncol;
        brow_ptr = Bm + (size_t)ridx * ldb;
    }

    for (int k0 = 0; k0 < K; k0 += 16) {
        {
            float4 va = *(const float4*)(arow_ptr + k0 + akk);
            As[akk + 0][arow_local] = va.x;
            As[akk + 1][arow_local] = va.y;
            As[akk + 2][arow_local] = va.z;
            As[akk + 3][arow_local] = va.w;
        }
        if (BTRANS == 0) {
            int kr = tid >> 4;
            int nn = (tid & 15) * 4;
            float4 vb = *(const float4*)(Bm + (size_t)(k0 + kr) * ldb + bn + nn);
            *(float4*)&Bs[kr][nn] = vb;
        } else {
            float4 vb = *(const float4*)(brow_ptr + k0 + akk);
            int nl = tid >> 2;
            Bs[akk + 0][nl] = vb.x;
            Bs[akk + 1][nl] = vb.y;
            Bs[akk + 2][nl] = vb.z;
            Bs[akk + 3][nl] = vb.w;
        }
        __syncthreads();
#pragma unroll
        for (int k = 0; k < 16; k++) {
            float a[4], b[4];
            *(float4*)a = *(const float4*)&As[k][ty * 4];
            *(float4*)b = *(const float4*)&Bs[k][tx * 4];
#pragma unroll
            for (int i = 0; i < 4; i++)
#pragma unroll
                for (int j = 0; j < 4; j++)
                    acc[i][j] = fmaf(a[i], b[j], acc[i][j]);
        }
        __syncthreads();
    }

#pragma unroll
    for (int i = 0; i < 4; i++) {
        int row = bm + ty * 4 + i;
#pragma unroll
        for (int j = 0; j < 4; j++) {
            int col = bn + tx * 4 + j;
            float v = acc[i][j] + (bias ? bias[col] : 0.f);
            C[(size_t)row * ldc + col] = v;
        }
    }
}

// ---------------------------------------------------------------------------
// Persistent recurrence kernel. 128 blocks x 512 threads.
// Each block owns 8 state columns (16 gate outputs, all 3 layers' weights in
// shared memory). 768 phases; light release/acquire global barrier per phase.
// Warp partition: 16 warps = (row-half rh in {0,1}) x (K-eighth ks in 0..7).
// ---------------------------------------------------------------------------
__device__ __forceinline__ void grid_sync(unsigned int target, unsigned int* bar) {
    __syncthreads();
    if (threadIdx.x == 0) {
        asm volatile("red.release.gpu.global.add.u32 [%0], 1;" :: "l"(bar) : "memory");
        unsigned int v;
        do {
            asm volatile("ld.acquire.gpu.global.u32 %0, [%1];" : "=r"(v) : "l"(bar) : "memory");
        } while (v < target);
    }
    __syncthreads();
}

__global__ __launch_bounds__(NTHR, 1)
void recurrence_kernel(const float* __restrict__ Wh0, const float* __restrict__ Wt0,
                       const float* __restrict__ Wh,  const float* __restrict__ Wt,
                       const float* __restrict__ bh,  const float* __restrict__ bt,
                       const int*   __restrict__ input_data,
                       const float* __restrict__ Eh,  const float* __restrict__ Et,
                       float* __restrict__ sT, float* __restrict__ states) {
    extern __shared__ float smem[];
    float* smw = smem;                   // [3][1024][16]
    float* smp = smem + 3 * 1024 * 16;   // partials [KSPLIT][64][17]

    const int tid  = threadIdx.x;
    const int lane = tid & 31;
    const int w    = tid >> 5;           // 0..15
    const int rh   = w & 1;              // row half
    const int ks   = w >> 1;             // 0..7 K-eighth
    const int colbase = blockIdx.x * CPB;
    const int m    = rh * 32 + lane;     // 0..63 row
    const int k0   = ks * KITER;

    unsigned int* bar = &g_bar;

    // ---- load weights into smem (once) ----
    const int wtotal = 3 * 1024 * 16;
    for (int i = tid; i < wtotal; i += NTHR) {
        int l   = i >> 14;
        int rem = i & 16383;
        int k   = rem >> 4;
        int cg  = rem & 15;
        int g   = cg >> 3;
        int c   = cg & 7;
        int gcol = colbase + c;
        float v;
        if (l == 0) {
            v = g ? Wt0[(size_t)(U_ + k) * R_ + gcol]
                  : Wh0[(size_t)(U_ + k) * R_ + gcol];
        } else {
            const float* W = g ? Wt : Wh;
            v = W[(size_t)(l - 1) * R_ * R_ + (size_t)k * R_ + gcol];
        }
        smw[i] = v;
    }

    // ---- zero both state buffers ----
    for (int i = blockIdx.x * NTHR + tid; i < 2 * R_ * B_; i += NBLK * NTHR)
        sT[i] = 0.f;

    unsigned int pc = 1;
    grid_sync(NBLK * pc, bar);

    int t = 0, l = 0;
    for (int p = 0; p < PHASES; p++) {
        const int rcur = p & 1;
        const float* sin = sT + rcur * (R_ * B_);
        float* sout = sT + (rcur ^ 1) * (R_ * B_);

        // ---- main dot products: 64 rows x 16 outs over K-eighth ----
        unsigned long long acc[8];
#pragma unroll
        for (int j = 0; j < 8; j++) acc[j] = 0ull;

        const float* sp = sin + (size_t)k0 * B_ + m;
        const ulonglong2* wp = (const ulonglong2*)(smw + ((size_t)l * 1024 + k0) * 16);

#pragma unroll 4
        for (int k = 0; k < KITER; k++) {
            float sv = __ldcg(sp + k * B_);
            unsigned long long sv2 = pack2(sv);
            ulonglong2 wa = wp[k * 4 + 0];
            ulonglong2 wb = wp[k * 4 + 1];
            ulonglong2 wc = wp[k * 4 + 2];
            ulonglong2 wd = wp[k * 4 + 3];
            acc[0] = fma2(sv2, wa.x, acc[0]);
            acc[1] = fma2(sv2, wa.y, acc[1]);
            acc[2] = fma2(sv2, wb.x, acc[2]);
            acc[3] = fma2(sv2, wb.y, acc[3]);
            acc[4] = fma2(sv2, wc.x, acc[4]);
            acc[5] = fma2(sv2, wc.y, acc[5]);
            acc[6] = fma2(sv2, wd.x, acc[6]);
            acc[7] = fma2(sv2, wd.y, acc[7]);
        }

        // ---- store K-partials to smem ----
        float* pr = smp + (ks * 64 + m) * 17;
#pragma unroll
        for (int j = 0; j < 8; j++) {
            float lo, hi;
            unpack2(acc[j], lo, hi);
            pr[2 * j]     = lo;
            pr[2 * j + 1] = hi;
        }
        __syncthreads();

        // ---- reduce across K-splits + activation + state update ----
        {
            int row = tid & 63;
            int c   = tid >> 6;            // 0..7
            float zh = 0.f, zt = 0.f;
#pragma unroll
            for (int q = 0; q < KSPLIT; q++) {
                zh += smp[(q * 64 + row) * 17 + c];
                zt += smp[(q * 64 + row) * 17 + 8 + c];
            }
            int gcol = colbase + c;
            if (l == 0) {
                int vid = __ldg(&input_data[row * T_ + t]);
                zh += __ldg(&Eh[(size_t)vid * R_ + gcol]);
                zt += __ldg(&Et[(size_t)vid * R_ + gcol]);
            } else {
                zh += __ldg(&bh[(l - 1) * R_ + gcol]);
                zt += __ldg(&bt[(l - 1) * R_ + gcol]);
            }
            float sold = __ldcg(sin + gcol * B_ + row);
            float hh = tanhf(zh);
            float tg = 1.f / (1.f + expf(-zt));
            float sn = (hh - sold) * tg + sold;
            __stcg(sout + gcol * B_ + row, sn);
            if (l == 2)
                states[((size_t)t * B_ + row) * R_ + gcol] = sn;
        }

        pc++;
        grid_sync(NBLK * pc, bar);

        if (++l == 3) { l = 0; t++; }
    }
}

// ---------------------------------------------------------------------------
// Per-row sampled-softmax loss. One block per row (i = b*T + t).
// ---------------------------------------------------------------------------
__global__ __launch_bounds__(256)
void loss_kernel(const float* __restrict__ outb,
                 const float* __restrict__ logits,
                 const int* __restrict__ targets,
                 const int* __restrict__ sampled,
                 const float* __restrict__ true_counts,
                 const float* __restrict__ sw,
                 const float* __restrict__ softmax_b,
                 float* __restrict__ loss) {
    __shared__ float red[256];
    __shared__ float sh_true, sh_max;
    const int i = blockIdx.x;
    const int tid = threadIdx.x;
    const int label = targets[i];

    float p = 0.f;
    for (int u = tid; u < U_; u += 256)
        p += outb[(size_t)i * U_ + u] * sw[(size_t)label * U_ + u];
    red[tid] = p; __syncthreads();
    for (int s = 128; s > 0; s >>= 1) {
        if (tid < s) red[tid] += red[tid + s];
        __syncthreads();
    }
    if (tid == 0) sh_true = red[0] + softmax_b[label] - logf(true_counts[i]);
    __syncthreads();
    const float tl = sh_true;

    float mx = -1e30f;
    for (int j = tid; j < S_; j += 256) {
        float v = logits[(size_t)i * S_ + j];
        if (sampled[j] == label) v -= 1e9f;
        mx = fmaxf(mx, v);
    }
    red[tid] = mx; __syncthreads();
    for (int s = 128; s > 0; s >>= 1) {
        if (tid < s) red[tid] = fmaxf(red[tid], red[tid + s]);
        __syncthreads();
    }
    if (tid == 0) sh_max = fmaxf(red[0], tl);
    __syncthreads();
    const float mval = sh_max;

    float sm = 0.f;
    for (int j = tid; j < S_; j += 256) {
        float v = logits[(size_t)i * S_ + j];
        if (sampled[j] == label) v -= 1e9f;
        sm += expf(v - mval);
    }
    red[tid] = sm; __syncthreads();
    for (int s = 128; s > 0; s >>= 1) {
        if (tid < s) red[tid] += red[tid + s];
        __syncthreads();
    }
    if (tid == 0) {
        float total = red[0] + expf(tl - mval);
        loss[i] = mval + logf(total) - tl;
    }
}

__global__ void reduce_mean_kernel(const float* __restrict__ loss, float* __restrict__ out) {
    __shared__ float red[256];
    const int tid = threadIdx.x;
    float s = 0.f;
    for (int i = tid; i < N_; i += 256) s += loss[i];
    red[tid] = s; __syncthreads();
    for (int st = 128; st > 0; st >>= 1) {
        if (tid < st) red[tid] += red[tid + st];
        __syncthreads();
    }
    if (tid == 0) out[0] = red[0] / (float)N_;
}

// ---------------------------------------------------------------------------
// Launch
// ---------------------------------------------------------------------------
extern "C" void kernel_launch(void* const* d_in, const int* in_sizes, int n_in,
                              void* d_out, int out_size) {
    const int*   input_data = (const int*)d_in[0];
    const int*   targets    = (const int*)d_in[1];
    const int*   sampled    = (const int*)d_in[2];
    const float* true_cnt   = (const float*)d_in[3];
    const float* samp_cnt   = (const float*)d_in[4];
    const float* embedding  = (const float*)d_in[5];
    const float* Wh0        = (const float*)d_in[6];
    const float* bh0        = (const float*)d_in[7];
    const float* Wt0        = (const float*)d_in[8];
    const float* bt0        = (const float*)d_in[9];
    const float* Wh         = (const float*)d_in[10];
    const float* bh         = (const float*)d_in[11];
    const float* Wt         = (const float*)d_in[12];
    const float* bt         = (const float*)d_in[13];
    const float* Wp         = (const float*)d_in[14];
    const float* bp         = (const float*)d_in[15];
    const float* sw         = (const float*)d_in[16];
    const float* smb        = (const float*)d_in[17];
    float* out = (float*)d_out;

    float *Eh, *Et, *states, *sT, *outb, *logits, *sbv, *lossv;
    cudaGetSymbolAddress((void**)&Eh, g_Eh);
    cudaGetSymbolAddress((void**)&Et, g_Et);
    cudaGetSymbolAddress((void**)&states, g_states);
    cudaGetSymbolAddress((void**)&sT, g_sT);
    cudaGetSymbolAddress((void**)&outb, g_outb);
    cudaGetSymbolAddress((void**)&logits, g_logits);
    cudaGetSymbolAddress((void**)&sbv, g_sbv);
    cudaGetSymbolAddress((void**)&lossv, g_loss);

    const int rec_smem = (3 * 1024 * 16 + KSPLIT * 64 * 17) * 4;  // 231424 B
    static int smem_set = 0;
    if (!smem_set) {
        cudaFuncSetAttribute(recurrence_kernel,
                             cudaFuncAttributeMaxDynamicSharedMemorySize, rec_smem);
        smem_set = 1;
    }

    reset_kernel<<<1, 1>>>();
    sb_kernel<<<(S_ + 255) / 256, 256>>>(sampled, smb, samp_cnt, sbv);

    // Vocab-space x-part precompute for layer 0
    {
        dim3 grid(R_ / 64, V_ / 64);
        sgemm_kernel<0, 0><<<grid, 256>>>(embedding, Wh0, bh0, Eh,
                                          V_, R_, U_, U_, R_, R_, nullptr);
        sgemm_kernel<0, 0><<<grid, 256>>>(embedding, Wt0, bt0, Et,
                                          V_, R_, U_, U_, R_, R_, nullptr);
    }

    // Entire serial recurrence in ONE persistent kernel
    recurrence_kernel<<<NBLK, NTHR, rec_smem>>>(
        Wh0, Wt0, Wh, Wt, bh, bt, input_data, Eh, Et, sT, states);

    // outputs[b*T+t,:] = states[t*B+b,:] @ Wp + bp
    {
        dim3 grid(U_ / 64, N_ / 64);
        sgemm_kernel<2, 0><<<grid, 256>>>(states, Wp, bp, outb,
                                          N_, U_, R_, R_, U_, U_, nullptr);
    }

    // sampled logits
    {
        dim3 grid(S_ / 64, N_ / 64);
        sgemm_kernel<0, 1><<<grid, 256>>>(outb, sw, sbv, logits,
                                          N_, S_, U_, U_, U_, S_, sampled);
    }

    loss_kernel<<<N_, 256>>>(outb, logits, targets, sampled, true_cnt, sw, smb, lossv);
    reduce_mean_kernel<<<1, 256>>>(lossv, out);
}

// round 7
// speedup vs baseline: 2.1900x; 1.2741x over previous
#include <cuda_runtime.h>
#include <cuda_bf16.h>
#include <math.h>
#include <stdint.h>

#define V_ 8000
#define B_ 64
#define T_ 256
#define R_ 1024
#define U_ 512
#define S_ 1024
#define N_ (B_ * T_)

// Recurrence config: 64 persistent CTAs x 256 threads, warp-level bf16 MMA.
#define RCTA 64
#define RTHR 256

// Shared memory layout (dynamic) for the recurrence kernel
#define OFFS_S    0                       // S chunks: 2 bufs x 32768 B
#define OFFS_W    65536                   // W chunks: 2 bufs x 16384 B
#define OFFS_Z    98304                   // zbuf: 32 x 68 f32 = 8704 B
#define OFFS_SOLD 107008                  // sold: 64 x 17 f32 = 4352 B
#define OFFS_BIAS 111360                  // 64 f32
#define OFFS_VID  111616                  // 64 int
#define RSMEM     111872

// ---------------------------------------------------------------------------
// Device global scratch (no allocation allowed)
// ---------------------------------------------------------------------------
__device__ float g_Eh[(size_t)V_ * R_];
__device__ float g_Et[(size_t)V_ * R_];
__device__ float g_states[(size_t)T_ * B_ * R_];
// W fragments: [l][cta][ks 64][term 2][mh 2][lane 32][4 u32]
__device__ uint32_t g_Wf[(size_t)3 * 64 * 32768];
// S fragments (ping-pong): [buf][ks 64][term 2][g 8][lane 32][2 u32]
__device__ uint32_t g_Sf[2 * 65536];
__device__ float g_outb[(size_t)N_ * U_];
__device__ float g_logits[(size_t)N_ * S_];
__device__ float g_sbv[S_];
__device__ float g_loss[N_];
__device__ unsigned int g_bar;

// ---------------------------------------------------------------------------
// PTX helpers
// ---------------------------------------------------------------------------
__device__ __forceinline__ uint32_t smem_u32(const void* p) {
    uint32_t a;
    asm("{ .reg .u64 t; cvta.to.shared.u64 t, %1; cvt.u32.u64 %0, t; }" : "=r"(a) : "l"(p));
    return a;
}
__device__ __forceinline__ void cpa16(uint32_t dst, const void* src) {
    asm volatile("cp.async.cg.shared.global [%0], [%1], 16;" :: "r"(dst), "l"(src));
}
#define CPA_COMMIT() asm volatile("cp.async.commit_group;" ::: "memory")
template <int NN> __device__ __forceinline__ void cpa_wait() {
    asm volatile("cp.async.wait_group %0;" :: "n"(NN) : "memory");
}
__device__ __forceinline__ uint4 lds128(uint32_t a) {
    uint4 v;
    asm volatile("ld.shared.v4.u32 {%0,%1,%2,%3}, [%4];"
                 : "=r"(v.x), "=r"(v.y), "=r"(v.z), "=r"(v.w) : "r"(a));
    return v;
}
__device__ __forceinline__ uint2 lds64(uint32_t a) {
    uint2 v;
    asm volatile("ld.shared.v2.u32 {%0,%1}, [%2];" : "=r"(v.x), "=r"(v.y) : "r"(a));
    return v;
}
__device__ __forceinline__ void mma_acc(float* d, const uint4& a, const uint2& b) {
    asm volatile(
        "mma.sync.aligned.m16n8k16.row.col.f32.bf16.bf16.f32 "
        "{%0,%1,%2,%3},{%4,%5,%6,%7},{%8,%9},{%0,%1,%2,%3};"
        : "+f"(d[0]), "+f"(d[1]), "+f"(d[2]), "+f"(d[3])
        : "r"(a.x), "r"(a.y), "r"(a.z), "r"(a.w), "r"(b.x), "r"(b.y));
}
__device__ __forceinline__ void grid_sync(unsigned int target, unsigned int* bar) {
    __syncthreads();
    if (threadIdx.x == 0) {
        asm volatile("red.release.gpu.global.add.u32 [%0], 1;" :: "l"(bar) : "memory");
        unsigned int v;
        do {
            asm volatile("ld.acquire.gpu.global.u32 %0, [%1];" : "=r"(v) : "l"(bar) : "memory");
        } while (v < target);
    }
    __syncthreads();
}

// ---------------------------------------------------------------------------
// Setup kernels
// ---------------------------------------------------------------------------
__global__ void init_kernel(uint32_t* sf) {
    int i = blockIdx.x * 256 + threadIdx.x;
    if (i == 0) g_bar = 0u;
    if (i < 2 * 65536) sf[i] = 0u;
}

__global__ void sb_kernel(const int* __restrict__ sampled,
                          const float* __restrict__ softmax_b,
                          const float* __restrict__ scounts,
                          float* __restrict__ sbv) {
    int j = blockIdx.x * 256 + threadIdx.x;
    if (j < S_) sbv[j] = softmax_b[sampled[j]] - logf(scounts[j]);
}

// Weight -> fragment-linear bf16 hi/lo layout.
// Block id = ((l*64 + cta)*2 + gate). Each block handles 16 columns, one gate.
__global__ __launch_bounds__(256)
void wcvt_kernel(const float* __restrict__ Wh0, const float* __restrict__ Wt0,
                 const float* __restrict__ Wh,  const float* __restrict__ Wt,
                 uint32_t* __restrict__ Wf) {
    __shared__ float ws[128 * 17];
    int b = blockIdx.x;
    int g = b & 1;
    int cta = (b >> 1) & 63;
    int l = b >> 7;
    int cbase = cta * 16;
    int tid = threadIdx.x;
    uint32_t* outp = Wf + (size_t)(l * 64 + cta) * 32768;

    for (int kb = 0; kb < 8; kb++) {
        int kbase = kb * 128;
        // load 128 k x 16 cols
#pragma unroll
        for (int e = 0; e < 8; e++) {
            int idx = tid + e * 256;
            int k = idx >> 4, c = idx & 15;
            int kg = kbase + k;
            float v;
            if (l == 0) v = (g ? Wt0 : Wh0)[(size_t)(U_ + kg) * R_ + cbase + c];
            else        v = (g ? Wt : Wh)[((size_t)(l - 1) * R_ + kg) * R_ + cbase + c];
            ws[k * 17 + c] = v;
        }
        __syncthreads();
        // emit fragments for 8 ksteps
#pragma unroll
        for (int e = 0; e < 8; e++) {
            int o = tid + e * 256;
            int ksl = o >> 8;
            int rem = o & 255;
            int term = rem >> 7;
            int rem2 = rem & 127;
            int lane = rem2 >> 2;
            int r = rem2 & 3;
            int row = (lane >> 2) + (r & 1) * 8;       // column within CTA (A row)
            int kk = (lane & 3) * 2 + (r >> 1) * 8;    // k within kstep
            int kl = ksl * 16 + kk;
            float w0 = ws[kl * 17 + row];
            float w1 = ws[(kl + 1) * 17 + row];
            uint16_t p0, p1;
            if (term == 0) {
                p0 = __bfloat16_as_ushort(__float2bfloat16(w0));
                p1 = __bfloat16_as_ushort(__float2bfloat16(w1));
            } else {
                float h0 = __bfloat162float(__float2bfloat16(w0));
                float h1 = __bfloat162float(__float2bfloat16(w1));
                p0 = __bfloat16_as_ushort(__float2bfloat16(w0 - h0));
                p1 = __bfloat16_as_ushort(__float2bfloat16(w1 - h1));
            }
            uint32_t val = ((uint32_t)p1 << 16) | p0;
            outp[(size_t)(((kb * 8 + ksl) * 2 + term) * 2 + g) * 128 + lane * 4 + r] = val;
        }
        __syncthreads();
    }
}

// ---------------------------------------------------------------------------
// fp32 tiled GEMM (parallel pre/post parts)
// ---------------------------------------------------------------------------
template <int AMODE, int BTRANS>
__global__ __launch_bounds__(256)
void sgemm_kernel(const float* __restrict__ A, const float* __restrict__ Bm,
                  const float* __restrict__ bias, float* __restrict__ C,
                  int M, int N, int K, int lda, int ldb, int ldc,
                  const int* __restrict__ b_idx) {
    __shared__ float As[16][68];
    __shared__ float Bs[16][68];
    const int bm = blockIdx.y * 64;
    const int bn = blockIdx.x * 64;
    const int tid = threadIdx.x;
    const int tx = tid & 15;
    const int ty = tid >> 4;

    float acc[4][4];
#pragma unroll
    for (int i = 0; i < 4; i++)
#pragma unroll
        for (int j = 0; j < 4; j++) acc[i][j] = 0.f;

    const int arow_local = tid >> 2;
    const int akk = (tid & 3) * 4;
    const int grow = bm + arow_local;
    const float* arow_ptr;
    if (AMODE == 0)      arow_ptr = A + (size_t)grow * lda;
    else                 arow_ptr = A + (size_t)((grow % T_) * B_ + grow / T_) * lda;

    const float* brow_ptr = nullptr;
    if (BTRANS == 1) {
        int bncol = bn + (tid >> 2);
        int ridx = b_idx ? b_idx[bncol] : bncol;
        brow_ptr = Bm + (size_t)ridx * ldb;
    }

    for (int k0 = 0; k0 < K; k0 += 16) {
        {
            float4 va = *(const float4*)(arow_ptr + k0 + akk);
            As[akk + 0][arow_local] = va.x;
            As[akk + 1][arow_local] = va.y;
            As[akk + 2][arow_local] = va.z;
            As[akk + 3][arow_local] = va.w;
        }
        if (BTRANS == 0) {
            int kr = tid >> 4;
            int nn = (tid & 15) * 4;
            float4 vb = *(const float4*)(Bm + (size_t)(k0 + kr) * ldb + bn + nn);
            *(float4*)&Bs[kr][nn] = vb;
        } else {
            float4 vb = *(const float4*)(brow_ptr + k0 + akk);
            int nl = tid >> 2;
            Bs[akk + 0][nl] = vb.x;
            Bs[akk + 1][nl] = vb.y;
            Bs[akk + 2][nl] = vb.z;
            Bs[akk + 3][nl] = vb.w;
        }
        __syncthreads();
#pragma unroll
        for (int k = 0; k < 16; k++) {
            float a[4], b[4];
            *(float4*)a = *(const float4*)&As[k][ty * 4];
            *(float4*)b = *(const float4*)&Bs[k][tx * 4];
#pragma unroll
            for (int i = 0; i < 4; i++)
#pragma unroll
                for (int j = 0; j < 4; j++)
                    acc[i][j] = fmaf(a[i], b[j], acc[i][j]);
        }
        __syncthreads();
    }

#pragma unroll
    for (int i = 0; i < 4; i++) {
        int row = bm + ty * 4 + i;
#pragma unroll
        for (int j = 0; j < 4; j++) {
            int col = bn + tx * 4 + j;
            C[(size_t)row * ldc + col] = acc[i][j] + (bias ? bias[col] : 0.f);
        }
    }
}

// ---------------------------------------------------------------------------
// Persistent warp-MMA recurrence: 64 CTAs x 256 threads.
// CTA owns 16 state columns; per phase D[32,64] via m16n8k16 bf16 hi/lo split.
// ---------------------------------------------------------------------------
__device__ __forceinline__ void load_chunk(uint32_t sm, int buf,
                                           const uint32_t* sG, const uint32_t* wG,
                                           int ck, int tid) {
    const char* s = (const char*)(sG + (size_t)ck * 8192);
    const char* w = (const char*)(wG + (size_t)ck * 4096);
    uint32_t ds = sm + OFFS_S + buf * 32768;
    uint32_t dw = sm + OFFS_W + buf * 16384;
#pragma unroll
    for (int r = 0; r < 8; r++) {
        int e = tid + r * 256;
        cpa16(ds + e * 16, s + e * 16);
    }
#pragma unroll
    for (int r = 0; r < 4; r++) {
        int e = tid + r * 256;
        cpa16(dw + e * 16, w + e * 16);
    }
}

__global__ __launch_bounds__(RTHR, 1)
void rec_mma_kernel(const uint32_t* __restrict__ Wf,
                    uint32_t* __restrict__ Sf,
                    const int* __restrict__ input_data,
                    const float* __restrict__ Eh, const float* __restrict__ Et,
                    const float* __restrict__ bh, const float* __restrict__ bt,
                    float* __restrict__ states) {
    extern __shared__ char smem[];
    const int tid = threadIdx.x;
    const int lane = tid & 31;
    const int wid = tid >> 5;
    const int mh = wid >> 2;        // row half (0: h-gate rows, 1: t-gate rows)
    const int nq = wid & 3;         // n quarter (16 batch cols)
    const int cta = blockIdx.x;
    const int cbase = cta * 16;
    uint32_t sb = smem_u32(smem);

    float* zbuf = (float*)(smem + OFFS_Z);     // [32][68]
    float* sold = (float*)(smem + OFFS_SOLD);  // [64][17]
    float* bias_s = (float*)(smem + OFFS_BIAS);
    int* vids = (int*)(smem + OFFS_VID);

    for (int i = tid; i < 64 * 17; i += RTHR) sold[i] = 0.f;
    if (tid < 64) {
        int l2 = tid >> 5, g = (tid >> 4) & 1, c = tid & 15;
        bias_s[tid] = (g ? bt : bh)[l2 * R_ + cbase + c];
    }
    __syncthreads();

    unsigned int pc = 0;
    int t = 0, l = 0;

    for (int p = 0; p < 3 * T_; p++) {
        const int rbuf = p & 1;
        const uint32_t* sG = Sf + rbuf * 65536;
        uint32_t* sOut = Sf + (rbuf ^ 1) * 65536;
        const uint32_t* wG = Wf + (size_t)(l * 64 + cta) * 32768;

        if (l == 0 && tid < 64) vids[tid] = input_data[tid * T_ + t];

        float dhh[2][4], dhl[2][4], dlh[2][4];
#pragma unroll
        for (int g = 0; g < 2; g++)
#pragma unroll
            for (int r = 0; r < 4; r++) { dhh[g][r] = 0.f; dhl[g][r] = 0.f; dlh[g][r] = 0.f; }

        load_chunk(sb, 0, sG, wG, 0, tid);
        CPA_COMMIT();

        const uint32_t wbB = sb + OFFS_W + mh * 512 + lane * 16;
        const uint32_t sbB = sb + OFFS_S + (nq * 2) * 256 + lane * 8;

        for (int j = 0; j < 8; j++) {
            if (j < 7) {
                load_chunk(sb, (j + 1) & 1, sG, wG, j + 1, tid);
                CPA_COMMIT();
                cpa_wait<1>();
            } else {
                cpa_wait<0>();
            }
            __syncthreads();
            const uint32_t wb = wbB + (j & 1) * 16384;
            const uint32_t sbx = sbB + (j & 1) * 32768;
#pragma unroll
            for (int ksl = 0; ksl < 8; ksl++) {
                uint4 ah = lds128(wb + ksl * 2048);
                uint4 al = lds128(wb + ksl * 2048 + 1024);
                uint2 bh0 = lds64(sbx + ksl * 4096);
                uint2 bh1 = lds64(sbx + ksl * 4096 + 256);
                uint2 bl0 = lds64(sbx + ksl * 4096 + 2048);
                uint2 bl1 = lds64(sbx + ksl * 4096 + 2048 + 256);
                mma_acc(dhh[0], ah, bh0);
                mma_acc(dhh[1], ah, bh1);
                mma_acc(dhl[0], ah, bl0);
                mma_acc(dhl[1], ah, bl1);
                mma_acc(dlh[0], al, bh0);
                mma_acc(dlh[1], al, bh1);
            }
            __syncthreads();   // protect smem buffer reuse
        }

        // combine terms + write D to zbuf
        {
            int gid = lane >> 2, q = lane & 3;
            int r0 = mh * 16 + gid;
            int n0 = nq * 16 + q * 2;
#pragma unroll
            for (int g = 0; g < 2; g++) {
                int n = n0 + g * 8;
                zbuf[r0 * 68 + n]            = dhh[g][0] + dhl[g][0] + dlh[g][0];
                zbuf[r0 * 68 + n + 1]        = dhh[g][1] + dhl[g][1] + dlh[g][1];
                zbuf[(r0 + 8) * 68 + n]      = dhh[g][2] + dhl[g][2] + dlh[g][2];
                zbuf[(r0 + 8) * 68 + n + 1]  = dhh[g][3] + dhl[g][3] + dlh[g][3];
            }
        }
        __syncthreads();

        // epilogue: 512 column-pairs (cc 0..7, b 0..63); thread handles pp = tid, tid+256
#pragma unroll
        for (int it = 0; it < 2; it++) {
            int pp = tid + it * 256;
            int cc = pp >> 6;
            int b = pp & 63;
            int c0 = cc * 2;
            uint16_t sh[2], sl[2];
#pragma unroll
            for (int s = 0; s < 2; s++) {
                int c = c0 + s;
                float zh = zbuf[c * 68 + b];
                float zt = zbuf[(16 + c) * 68 + b];
                if (l == 0) {
                    int vid = vids[b];
                    zh += __ldg(&Eh[(size_t)vid * R_ + cbase + c]);
                    zt += __ldg(&Et[(size_t)vid * R_ + cbase + c]);
                } else {
                    zh += bias_s[((l - 1) * 2 + 0) * 16 + c];
                    zt += bias_s[((l - 1) * 2 + 1) * 16 + c];
                }
                float so = sold[b * 17 + c];
                float hh = tanhf(zh);
                float tg = 1.f / (1.f + expf(-zt));
                float sn = (hh - so) * tg + so;
                sold[b * 17 + c] = sn;
                __nv_bfloat16 hb = __float2bfloat16(sn);
                sh[s] = __bfloat16_as_ushort(hb);
                sl[s] = __bfloat16_as_ushort(__float2bfloat16(sn - __bfloat162float(hb)));
                if (l == 2)
                    states[((size_t)t * B_ + b) * R_ + cbase + c] = sn;
            }
            // scatter into B-fragment layout: ks = cta, k-row = c0 (pair)
            int reg = (c0 & 8) ? 1 : 0;
            int q = (c0 >> 1) & 3;
            int g = b >> 3;
            int lt = (b & 7) * 4 + q;
            size_t base = (size_t)((cta * 2 + 0) * 8 + g) * 64 + lt * 2 + reg;
            sOut[base]       = ((uint32_t)sh[1] << 16) | sh[0];
            sOut[base + 512] = ((uint32_t)sl[1] << 16) | sl[0];   // term1 offset: 8g*32l*2 = 512
        }

        pc++;
        grid_sync(RCTA * pc, &g_bar);
        if (++l == 3) { l = 0; t++; }
    }
}

// ---------------------------------------------------------------------------
// Loss + mean
// ---------------------------------------------------------------------------
__global__ __launch_bounds__(256)
void loss_kernel(const float* __restrict__ outb,
                 const float* __restrict__ logits,
                 const int* __restrict__ targets,
                 const int* __restrict__ sampled,
                 const float* __restrict__ true_counts,
                 const float* __restrict__ sw,
                 const float* __restrict__ softmax_b,
                 float* __restrict__ loss) {
    __shared__ float red[256];
    __shared__ float sh_true, sh_max;
    const int i = blockIdx.x;
    const int tid = threadIdx.x;
    const int label = targets[i];

    float p = 0.f;
    for (int u = tid; u < U_; u += 256)
        p += outb[(size_t)i * U_ + u] * sw[(size_t)label * U_ + u];
    red[tid] = p; __syncthreads();
    for (int s = 128; s > 0; s >>= 1) {
        if (tid < s) red[tid] += red[tid + s];
        __syncthreads();
    }
    if (tid == 0) sh_true = red[0] + softmax_b[label] - logf(true_counts[i]);
    __syncthreads();
    const float tl = sh_true;

    float mx = -1e30f;
    for (int j = tid; j < S_; j += 256) {
        float v = logits[(size_t)i * S_ + j];
        if (sampled[j] == label) v -= 1e9f;
        mx = fmaxf(mx, v);
    }
    red[tid] = mx; __syncthreads();
    for (int s = 128; s > 0; s >>= 1) {
        if (tid < s) red[tid] = fmaxf(red[tid], red[tid + s]);
        __syncthreads();
    }
    if (tid == 0) sh_max = fmaxf(red[0], tl);
    __syncthreads();
    const float mval = sh_max;

    float sm = 0.f;
    for (int j = tid; j < S_; j += 256) {
        float v = logits[(size_t)i * S_ + j];
        if (sampled[j] == label) v -= 1e9f;
        sm += expf(v - mval);
    }
    red[tid] = sm; __syncthreads();
    for (int s = 128; s > 0; s >>= 1) {
        if (tid < s) red[tid] += red[tid + s];
        __syncthreads();
    }
    if (tid == 0) {
        float total = red[0] + expf(tl - mval);
        loss[i] = mval + logf(total) - tl;
    }
}

__global__ void reduce_mean_kernel(const float* __restrict__ loss, float* __restrict__ out) {
    __shared__ float red[256];
    const int tid = threadIdx.x;
    float s = 0.f;
    for (int i = tid; i < N_; i += 256) s += loss[i];
    red[tid] = s; __syncthreads();
    for (int st = 128; st > 0; st >>= 1) {
        if (tid < st) red[tid] += red[tid + st];
        __syncthreads();
    }
    if (tid == 0) out[0] = red[0] / (float)N_;
}

// ---------------------------------------------------------------------------
// Launch
// ---------------------------------------------------------------------------
extern "C" void kernel_launch(void* const* d_in, const int* in_sizes, int n_in,
                              void* d_out, int out_size) {
    const int*   input_data = (const int*)d_in[0];
    const int*   targets    = (const int*)d_in[1];
    const int*   sampled    = (const int*)d_in[2];
    const float* true_cnt   = (const float*)d_in[3];
    const float* samp_cnt   = (const float*)d_in[4];
    const float* embedding  = (const float*)d_in[5];
    const float* Wh0        = (const float*)d_in[6];
    const float* bh0        = (const float*)d_in[7];
    const float* Wt0        = (const float*)d_in[8];
    const float* bt0        = (const float*)d_in[9];
    const float* Wh         = (const float*)d_in[10];
    const float* bh         = (const float*)d_in[11];
    const float* Wt         = (const float*)d_in[12];
    const float* bt         = (const float*)d_in[13];
    const float* Wp         = (const float*)d_in[14];
    const float* bp         = (const float*)d_in[15];
    const float* sw         = (const float*)d_in[16];
    const float* smb        = (const float*)d_in[17];
    float* out = (float*)d_out;

    float *Eh, *Et, *states, *outb, *logits, *sbv, *lossv;
    uint32_t *Wf, *Sf;
    cudaGetSymbolAddress((void**)&Eh, g_Eh);
    cudaGetSymbolAddress((void**)&Et, g_Et);
    cudaGetSymbolAddress((void**)&states, g_states);
    cudaGetSymbolAddress((void**)&outb, g_outb);
    cudaGetSymbolAddress((void**)&logits, g_logits);
    cudaGetSymbolAddress((void**)&sbv, g_sbv);
    cudaGetSymbolAddress((void**)&lossv, g_loss);
    cudaGetSymbolAddress((void**)&Wf, g_Wf);
    cudaGetSymbolAddress((void**)&Sf, g_Sf);

    static int smem_set = 0;
    if (!smem_set) {
        cudaFuncSetAttribute(rec_mma_kernel,
                             cudaFuncAttributeMaxDynamicSharedMemorySize, RSMEM);
        smem_set = 1;
    }

    init_kernel<<<(2 * 65536 + 255) / 256, 256>>>(Sf);
    sb_kernel<<<(S_ + 255) / 256, 256>>>(sampled, smb, samp_cnt, sbv);
    wcvt_kernel<<<384, 256>>>(Wh0, Wt0, Wh, Wt, Wf);

    // Vocab-space x-part precompute for layer 0
    {
        dim3 grid(R_ / 64, V_ / 64);
        sgemm_kernel<0, 0><<<grid, 256>>>(embedding, Wh0, bh0, Eh,
                                          V_, R_, U_, U_, R_, R_, nullptr);
        sgemm_kernel<0, 0><<<grid, 256>>>(embedding, Wt0, bt0, Et,
                                          V_, R_, U_, U_, R_, R_, nullptr);
    }

    // Persistent warp-MMA recurrence
    rec_mma_kernel<<<RCTA, RTHR, RSMEM>>>(Wf, Sf, input_data, Eh, Et, bh, bt, states);

    // outputs[b*T+t,:] = states[t*B+b,:] @ Wp + bp
    {
        dim3 grid(U_ / 64, N_ / 64);
        sgemm_kernel<2, 0><<<grid, 256>>>(states, Wp, bp, outb,
                                          N_, U_, R_, R_, U_, U_, nullptr);
    }
    // sampled logits
    {
        dim3 grid(S_ / 64, N_ / 64);
        sgemm_kernel<0, 1><<<grid, 256>>>(outb, sw, sbv, logits,
                                          N_, S_, U_, U_, U_, S_, sampled);
    }

    loss_kernel<<<N_, 256>>>(outb, logits, targets, sampled, true_cnt, sw, smb, lossv);
    reduce_mean_kernel<<<1, 256>>>(lossv, out);
}

// round 8
// speedup vs baseline: 2.3186x; 1.0587x over previous
#include <cuda_runtime.h>
#include <cuda_bf16.h>
#include <math.h>
#include <stdint.h>

#define V_ 8000
#define B_ 64
#define T_ 256
#define R_ 1024
#define U_ 512
#define S_ 1024
#define N_ (B_ * T_)

// Recurrence: 128 persistent CTAs x 256 threads; CTA owns 8 state columns.
// M=16 gate rows (8 h + 8 t), N=64 batch, K=1024 split across 8 warps.
#define RCTA 128
#define RTHR 256

// ---------------------------------------------------------------------------
// Device global scratch
// ---------------------------------------------------------------------------
__device__ float g_Eh[(size_t)V_ * R_];
__device__ float g_Et[(size_t)V_ * R_];
__device__ float g_states[(size_t)T_ * B_ * R_];
// W fragments: [l][cta 128][ks 64][term 2][lane 32][4 u32]
__device__ uint32_t g_Wf[(size_t)3 * 128 * 16384];
// S fragments ping-pong: [buf][ks 64][term 2][gp 4][lane 32][4 u32]
__device__ uint32_t g_Sf[2 * 65536];
__device__ float g_outb[(size_t)N_ * U_];
__device__ float g_logits[(size_t)N_ * S_];
__device__ float g_sbv[S_];
__device__ float g_loss[N_];
__device__ unsigned int g_bar;

// ---------------------------------------------------------------------------
// PTX helpers
// ---------------------------------------------------------------------------
__device__ __forceinline__ void mma_acc(float* d, const uint4& a, uint32_t b0, uint32_t b1) {
    asm volatile(
        "mma.sync.aligned.m16n8k16.row.col.f32.bf16.bf16.f32 "
        "{%0,%1,%2,%3},{%4,%5,%6,%7},{%8,%9},{%0,%1,%2,%3};"
        : "+f"(d[0]), "+f"(d[1]), "+f"(d[2]), "+f"(d[3])
        : "r"(a.x), "r"(a.y), "r"(a.z), "r"(a.w), "r"(b0), "r"(b1));
}
__device__ __forceinline__ uint4 ldg128cg(const uint4* p) {
    uint4 v;
    asm volatile("ld.global.cg.v4.u32 {%0,%1,%2,%3}, [%4];"
                 : "=r"(v.x), "=r"(v.y), "=r"(v.z), "=r"(v.w) : "l"(p));
    return v;
}
__device__ __forceinline__ void grid_sync(unsigned int target, unsigned int* bar) {
    __syncthreads();
    if (threadIdx.x == 0) {
        asm volatile("red.release.gpu.global.add.u32 [%0], 1;" :: "l"(bar) : "memory");
        unsigned int v;
        do {
            asm volatile("ld.acquire.gpu.global.u32 %0, [%1];" : "=r"(v) : "l"(bar) : "memory");
        } while (v < target);
    }
    __syncthreads();
}

// ---------------------------------------------------------------------------
// Setup kernels
// ---------------------------------------------------------------------------
__global__ void init_kernel(uint32_t* sf) {
    int i = blockIdx.x * 256 + threadIdx.x;
    if (i == 0) g_bar = 0u;
    if (i < 2 * 65536) sf[i] = 0u;
}

__global__ void sb_kernel(const int* __restrict__ sampled,
                          const float* __restrict__ softmax_b,
                          const float* __restrict__ scounts,
                          float* __restrict__ sbv) {
    int j = blockIdx.x * 256 + threadIdx.x;
    if (j < S_) sbv[j] = softmax_b[sampled[j]] - logf(scounts[j]);
}

// Weight -> fragment-linear bf16 hi/lo. Block = (l*128 + cta); 8 cols, 2 gates.
__global__ __launch_bounds__(256)
void wcvt_kernel(const float* __restrict__ Wh0, const float* __restrict__ Wt0,
                 const float* __restrict__ Wh,  const float* __restrict__ Wt,
                 uint32_t* __restrict__ Wf) {
    __shared__ float ws[256][17];
    int b = blockIdx.x;
    int cta = b & 127;
    int l = b >> 7;
    int cbase = cta * 8;
    int tid = threadIdx.x;
    uint32_t* outp = Wf + (size_t)(l * 128 + cta) * 16384;

    for (int kb = 0; kb < 4; kb++) {
#pragma unroll
        for (int e = 0; e < 16; e++) {
            int idx = tid + e * 256;
            int k = idx >> 4, cg = idx & 15;
            int g = cg >> 3, c = cg & 7;
            int kg = kb * 256 + k;
            float v;
            if (l == 0) v = (g ? Wt0 : Wh0)[(size_t)(U_ + kg) * R_ + cbase + c];
            else        v = (g ? Wt : Wh)[((size_t)(l - 1) * R_ + kg) * R_ + cbase + c];
            ws[k][g * 8 + c] = v;
        }
        __syncthreads();
#pragma unroll
        for (int e = 0; e < 16; e++) {
            int o = tid + e * 256;
            int ksl = o >> 8;
            int rem = o & 255;
            int term = rem >> 7;
            int rem2 = rem & 127;
            int lane = rem2 >> 2;
            int r = rem2 & 3;
            int gate = r & 1;
            int c = lane >> 2;
            int kk = (lane & 3) * 2 + (r >> 1) * 8;
            int kl = ksl * 16 + kk;
            float w0 = ws[kl][gate * 8 + c];
            float w1 = ws[kl + 1][gate * 8 + c];
            uint16_t p0, p1;
            if (term == 0) {
                p0 = __bfloat16_as_ushort(__float2bfloat16(w0));
                p1 = __bfloat16_as_ushort(__float2bfloat16(w1));
            } else {
                float h0 = __bfloat162float(__float2bfloat16(w0));
                float h1 = __bfloat162float(__float2bfloat16(w1));
                p0 = __bfloat16_as_ushort(__float2bfloat16(w0 - h0));
                p1 = __bfloat16_as_ushort(__float2bfloat16(w1 - h1));
            }
            int ks = kb * 16 + ksl;
            outp[((ks * 2 + term) * 32 + lane) * 4 + r] = ((uint32_t)p1 << 16) | p0;
        }
        __syncthreads();
    }
}

// ---------------------------------------------------------------------------
// fp32 tiled GEMM (parallel pre/post parts)
// ---------------------------------------------------------------------------
template <int AMODE, int BTRANS>
__global__ __launch_bounds__(256)
void sgemm_kernel(const float* __restrict__ A, const float* __restrict__ Bm,
                  const float* __restrict__ bias, float* __restrict__ C,
                  int M, int N, int K, int lda, int ldb, int ldc,
                  const int* __restrict__ b_idx) {
    __shared__ float As[16][68];
    __shared__ float Bs[16][68];
    const int bm = blockIdx.y * 64;
    const int bn = blockIdx.x * 64;
    const int tid = threadIdx.x;
    const int tx = tid & 15;
    const int ty = tid >> 4;

    float acc[4][4];
#pragma unroll
    for (int i = 0; i < 4; i++)
#pragma unroll
        for (int j = 0; j < 4; j++) acc[i][j] = 0.f;

    const int arow_local = tid >> 2;
    const int akk = (tid & 3) * 4;
    const int grow = bm + arow_local;
    const float* arow_ptr;
    if (AMODE == 0)      arow_ptr = A + (size_t)grow * lda;
    else                 arow_ptr = A + (size_t)((grow % T_) * B_ + grow / T_) * lda;

    const float* brow_ptr = nullptr;
    if (BTRANS == 1) {
        int bncol = bn + (tid >> 2);
        int ridx = b_idx ? b_idx[bncol] : bncol;
        brow_ptr = Bm + (size_t)ridx * ldb;
    }

    for (int k0 = 0; k0 < K; k0 += 16) {
        {
            float4 va = *(const float4*)(arow_ptr + k0 + akk);
            As[akk + 0][arow_local] = va.x;
            As[akk + 1][arow_local] = va.y;
            As[akk + 2][arow_local] = va.z;
            As[akk + 3][arow_local] = va.w;
        }
        if (BTRANS == 0) {
            int kr = tid >> 4;
            int nn = (tid & 15) * 4;
            float4 vb = *(const float4*)(Bm + (size_t)(k0 + kr) * ldb + bn + nn);
            *(float4*)&Bs[kr][nn] = vb;
        } else {
            float4 vb = *(const float4*)(brow_ptr + k0 + akk);
            int nl = tid >> 2;
            Bs[akk + 0][nl] = vb.x;
            Bs[akk + 1][nl] = vb.y;
            Bs[akk + 2][nl] = vb.z;
            Bs[akk + 3][nl] = vb.w;
        }
        __syncthreads();
#pragma unroll
        for (int k = 0; k < 16; k++) {
            float a[4], b[4];
            *(float4*)a = *(const float4*)&As[k][ty * 4];
            *(float4*)b = *(const float4*)&Bs[k][tx * 4];
#pragma unroll
            for (int i = 0; i < 4; i++)
#pragma unroll
                for (int j = 0; j < 4; j++)
                    acc[i][j] = fmaf(a[i], b[j], acc[i][j]);
        }
        __syncthreads();
    }

#pragma unroll
    for (int i = 0; i < 4; i++) {
        int row = bm + ty * 4 + i;
#pragma unroll
        for (int j = 0; j < 4; j++) {
            int col = bn + tx * 4 + j;
            C[(size_t)row * ldc + col] = acc[i][j] + (bias ? bias[col] : 0.f);
        }
    }
}

// ---------------------------------------------------------------------------
// Persistent recurrence: register-direct fragment loads, K split across warps.
// ---------------------------------------------------------------------------
__global__ __launch_bounds__(RTHR, 1)
void rec_mma_kernel(const uint32_t* __restrict__ Wf,
                    uint32_t* __restrict__ Sf,
                    const int* __restrict__ input_data,
                    const float* __restrict__ Eh, const float* __restrict__ Et,
                    const float* __restrict__ bh, const float* __restrict__ bt,
                    float* __restrict__ states) {
    __shared__ float part[8][16][68];   // per-warp D partials
    __shared__ float sold[64][9];
    __shared__ float bias_s[32];        // [l-1][gate][8 cols]
    __shared__ int vids[64];

    const int tid = threadIdx.x;
    const int lane = tid & 31;
    const int w = tid >> 5;
    const int cta = blockIdx.x;
    const int cbase = cta * 8;

    for (int i = tid; i < 64 * 9; i += RTHR) ((float*)sold)[i] = 0.f;
    if (tid < 32) {
        int l2 = tid >> 4, g = (tid >> 3) & 1, c = tid & 7;
        bias_s[tid] = (g ? bt : bh)[l2 * R_ + cbase + c];
    }
    __syncthreads();

    unsigned int pc = 0;
    int t = 0, l = 0;

    for (int p = 0; p < 3 * T_; p++) {
        const int rbuf = p & 1;
        const uint4* SB = (const uint4*)(Sf + rbuf * 65536);
        uint32_t* sOut = Sf + (rbuf ^ 1) * 65536;
        const uint4* WA = (const uint4*)Wf + (size_t)(l * 128 + cta) * 4096;

        if (l == 0 && tid < 64) vids[tid] = input_data[tid * T_ + t];

        float d[8][4];
#pragma unroll
        for (int g = 0; g < 8; g++)
#pragma unroll
            for (int r = 0; r < 4; r++) d[g][r] = 0.f;

        const int ks0 = w * 8;
#pragma unroll 2
        for (int j = 0; j < 8; j++) {
            int ks = ks0 + j;
            uint4 aH = __ldg(WA + (ks * 2 + 0) * 32 + lane);
            uint4 aL = __ldg(WA + (ks * 2 + 1) * 32 + lane);
            uint4 bH[4], bL[4];
#pragma unroll
            for (int gp = 0; gp < 4; gp++) {
                bH[gp] = ldg128cg(SB + ((ks * 2 + 0) * 4 + gp) * 32 + lane);
                bL[gp] = ldg128cg(SB + ((ks * 2 + 1) * 4 + gp) * 32 + lane);
            }
#pragma unroll
            for (int gp = 0; gp < 4; gp++) {
                mma_acc(d[2 * gp],     aH, bH[gp].x, bH[gp].y);
                mma_acc(d[2 * gp + 1], aH, bH[gp].z, bH[gp].w);
                mma_acc(d[2 * gp],     aH, bL[gp].x, bL[gp].y);
                mma_acc(d[2 * gp + 1], aH, bL[gp].z, bL[gp].w);
                mma_acc(d[2 * gp],     aL, bH[gp].x, bH[gp].y);
                mma_acc(d[2 * gp + 1], aL, bH[gp].z, bH[gp].w);
            }
        }

        // store partials
        {
            int row = lane >> 2;
            int nb = (lane & 3) * 2;
#pragma unroll
            for (int g = 0; g < 8; g++) {
                *(float2*)&part[w][row][nb + g * 8]     = make_float2(d[g][0], d[g][1]);
                *(float2*)&part[w][row + 8][nb + g * 8] = make_float2(d[g][2], d[g][3]);
            }
        }
        __syncthreads();

        // epilogue: 256 threads cover (4 col-pairs) x (64 batch)
        {
            int c0 = (tid >> 6) * 2;
            int b = tid & 63;
            uint16_t sh[2], sl[2];
#pragma unroll
            for (int s = 0; s < 2; s++) {
                int c = c0 + s;
                float zh = 0.f, zt = 0.f;
#pragma unroll
                for (int q = 0; q < 8; q++) {
                    zh += part[q][c][b];
                    zt += part[q][8 + c][b];
                }
                if (l == 0) {
                    int vid = vids[b];
                    zh += __ldg(&Eh[(size_t)vid * R_ + cbase + c]);
                    zt += __ldg(&Et[(size_t)vid * R_ + cbase + c]);
                } else {
                    zh += bias_s[(l - 1) * 16 + c];
                    zt += bias_s[(l - 1) * 16 + 8 + c];
                }
                float so = sold[b][c];
                float hh = tanhf(zh);
                float tg = 1.f / (1.f + expf(-zt));
                float sn = (hh - so) * tg + so;
                sold[b][c] = sn;
                __nv_bfloat16 hb = __float2bfloat16(sn);
                sh[s] = __bfloat16_as_ushort(hb);
                sl[s] = __bfloat16_as_ushort(__float2bfloat16(sn - __bfloat162float(hb)));
                if (l == 2)
                    states[((size_t)t * B_ + b) * R_ + cbase + c] = sn;
            }
            // scatter into B-fragment layout
            int kk0 = (cta & 1) * 8 + c0;
            int q = (kk0 >> 1) & 3;
            int reg = cta & 1;
            int g = b >> 3;
            int lt = (b & 7) * 4 + q;
            int ks = cta >> 1;
            int slot = (g & 1) * 2 + reg;
            int gp = g >> 1;
            uint32_t idx_hi = (uint32_t)((((ks * 2 + 0) * 4 + gp) * 32 + lt) * 4 + slot);
            uint32_t idx_lo = (uint32_t)((((ks * 2 + 1) * 4 + gp) * 32 + lt) * 4 + slot);
            sOut[idx_hi] = ((uint32_t)sh[1] << 16) | sh[0];
            sOut[idx_lo] = ((uint32_t)sl[1] << 16) | sl[0];
        }

        pc++;
        grid_sync(RCTA * pc, &g_bar);
        if (++l == 3) { l = 0; t++; }
    }
}

// ---------------------------------------------------------------------------
// Loss + mean
// ---------------------------------------------------------------------------
__global__ __launch_bounds__(256)
void loss_kernel(const float* __restrict__ outb,
                 const float* __restrict__ logits,
                 const int* __restrict__ targets,
                 const int* __restrict__ sampled,
                 const float* __restrict__ true_counts,
                 const float* __restrict__ sw,
                 const float* __restrict__ softmax_b,
                 float* __restrict__ loss) {
    __shared__ float red[256];
    __shared__ float sh_true, sh_max;
    const int i = blockIdx.x;
    const int tid = threadIdx.x;
    const int label = targets[i];

    float p = 0.f;
    for (int u = tid; u < U_; u += 256)
        p += outb[(size_t)i * U_ + u] * sw[(size_t)label * U_ + u];
    red[tid] = p; __syncthreads();
    for (int s = 128; s > 0; s >>= 1) {
        if (tid < s) red[tid] += red[tid + s];
        __syncthreads();
    }
    if (tid == 0) sh_true = red[0] + softmax_b[label] - logf(true_counts[i]);
    __syncthreads();
    const float tl = sh_true;

    float mx = -1e30f;
    for (int j = tid; j < S_; j += 256) {
        float v = logits[(size_t)i * S_ + j];
        if (sampled[j] == label) v -= 1e9f;
        mx = fmaxf(mx, v);
    }
    red[tid] = mx; __syncthreads();
    for (int s = 128; s > 0; s >>= 1) {
        if (tid < s) red[tid] = fmaxf(red[tid], red[tid + s]);
        __syncthreads();
    }
    if (tid == 0) sh_max = fmaxf(red[0], tl);
    __syncthreads();
    const float mval = sh_max;

    float sm = 0.f;
    for (int j = tid; j < S_; j += 256) {
        float v = logits[(size_t)i * S_ + j];
        if (sampled[j] == label) v -= 1e9f;
        sm += expf(v - mval);
    }
    red[tid] = sm; __syncthreads();
    for (int s = 128; s > 0; s >>= 1) {
        if (tid < s) red[tid] += red[tid + s];
        __syncthreads();
    }
    if (tid == 0) {
        float total = red[0] + expf(tl - mval);
        loss[i] = mval + logf(total) - tl;
    }
}

__global__ void reduce_mean_kernel(const float* __restrict__ loss, float* __restrict__ out) {
    __shared__ float red[256];
    const int tid = threadIdx.x;
    float s = 0.f;
    for (int i = tid; i < N_; i += 256) s += loss[i];
    red[tid] = s; __syncthreads();
    for (int st = 128; st > 0; st >>= 1) {
        if (tid < st) red[tid] += red[tid + st];
        __syncthreads();
    }
    if (tid == 0) out[0] = red[0] / (float)N_;
}

// ---------------------------------------------------------------------------
// Launch
// ---------------------------------------------------------------------------
extern "C" void kernel_launch(void* const* d_in, const int* in_sizes, int n_in,
                              void* d_out, int out_size) {
    const int*   input_data = (const int*)d_in[0];
    const int*   targets    = (const int*)d_in[1];
    const int*   sampled    = (const int*)d_in[2];
    const float* true_cnt   = (const float*)d_in[3];
    const float* samp_cnt   = (const float*)d_in[4];
    const float* embedding  = (const float*)d_in[5];
    const float* Wh0        = (const float*)d_in[6];
    const float* bh0        = (const float*)d_in[7];
    const float* Wt0        = (const float*)d_in[8];
    const float* bt0        = (const float*)d_in[9];
    const float* Wh         = (const float*)d_in[10];
    const float* bh         = (const float*)d_in[11];
    const float* Wt         = (const float*)d_in[12];
    const float* bt         = (const float*)d_in[13];
    const float* Wp         = (const float*)d_in[14];
    const float* bp         = (const float*)d_in[15];
    const float* sw         = (const float*)d_in[16];
    const float* smb        = (const float*)d_in[17];
    float* out = (float*)d_out;

    float *Eh, *Et, *states, *outb, *logits, *sbv, *lossv;
    uint32_t *Wf, *Sf;
    cudaGetSymbolAddress((void**)&Eh, g_Eh);
    cudaGetSymbolAddress((void**)&Et, g_Et);
    cudaGetSymbolAddress((void**)&states, g_states);
    cudaGetSymbolAddress((void**)&outb, g_outb);
    cudaGetSymbolAddress((void**)&logits, g_logits);
    cudaGetSymbolAddress((void**)&sbv, g_sbv);
    cudaGetSymbolAddress((void**)&lossv, g_loss);
    cudaGetSymbolAddress((void**)&Wf, g_Wf);
    cudaGetSymbolAddress((void**)&Sf, g_Sf);

    init_kernel<<<(2 * 65536 + 255) / 256, 256>>>(Sf);
    sb_kernel<<<(S_ + 255) / 256, 256>>>(sampled, smb, samp_cnt, sbv);
    wcvt_kernel<<<384, 256>>>(Wh0, Wt0, Wh, Wt, Wf);

    // Vocab-space x-part precompute for layer 0
    {
        dim3 grid(R_ / 64, V_ / 64);
        sgemm_kernel<0, 0><<<grid, 256>>>(embedding, Wh0, bh0, Eh,
                                          V_, R_, U_, U_, R_, R_, nullptr);
        sgemm_kernel<0, 0><<<grid, 256>>>(embedding, Wt0, bt0, Et,
                                          V_, R_, U_, U_, R_, R_, nullptr);
    }

    // Persistent recurrence (register-direct warp MMA)
    rec_mma_kernel<<<RCTA, RTHR>>>(Wf, Sf, input_data, Eh, Et, bh, bt, states);

    // outputs[b*T+t,:] = states[t*B+b,:] @ Wp + bp
    {
        dim3 grid(U_ / 64, N_ / 64);
        sgemm_kernel<2, 0><<<grid, 256>>>(states, Wp, bp, outb,
                                          N_, U_, R_, R_, U_, U_, nullptr);
    }
    // sampled logits
    {
        dim3 grid(S_ / 64, N_ / 64);
        sgemm_kernel<0, 1><<<grid, 256>>>(outb, sw, sbv, logits,
                                          N_, S_, U_, U_, U_, S_, sampled);
    }

    loss_kernel<<<N_, 256>>>(outb, logits, targets, sampled, true_cnt, sw, smb, lossv);
    reduce_mean_kernel<<<1, 256>>>(lossv, out);
}

// round 9
// speedup vs baseline: 4.0470x; 1.7455x over previous
#include <cuda_runtime.h>
#include <cuda_bf16.h>
#include <math.h>
#include <stdint.h>

#define V_ 8000
#define B_ 64
#define T_ 256
#define R_ 1024
#define U_ 512
#define S_ 1024
#define N_ (B_ * T_)

// Recurrence: 128 persistent CTAs x 256 threads; CTA owns 8 state columns.
#define RCTA 128
#define RTHR 256

// ---------------------------------------------------------------------------
// Device global scratch
// ---------------------------------------------------------------------------
__device__ float g_Eh[(size_t)V_ * R_];
__device__ float g_Et[(size_t)V_ * R_];
__device__ float g_states[(size_t)T_ * B_ * R_];
// W fragments: [l][cta 128][ks 64][term 2][lane 32][4 u32]
__device__ uint32_t g_Wf[(size_t)3 * 128 * 16384];
// S fragments (hi only) ping-pong: [buf][ks 64][gp 4][lane 32][4 u32]
__device__ uint32_t g_Sf[2 * 32768];
__device__ float g_outb[(size_t)N_ * U_];
__device__ float g_logits[(size_t)N_ * S_];
__device__ float g_sbv[S_];
__device__ float g_loss[N_];
__device__ unsigned int g_bar;

// ---------------------------------------------------------------------------
// PTX helpers
// ---------------------------------------------------------------------------
__device__ __forceinline__ void mma_acc(float* d, const uint4& a, uint32_t b0, uint32_t b1) {
    asm volatile(
        "mma.sync.aligned.m16n8k16.row.col.f32.bf16.bf16.f32 "
        "{%0,%1,%2,%3},{%4,%5,%6,%7},{%8,%9},{%0,%1,%2,%3};"
        : "+f"(d[0]), "+f"(d[1]), "+f"(d[2]), "+f"(d[3])
        : "r"(a.x), "r"(a.y), "r"(a.z), "r"(a.w), "r"(b0), "r"(b1));
}
__device__ __forceinline__ uint4 ldg128cg(const uint4* p) {
    uint4 v;
    asm volatile("ld.global.cg.v4.u32 {%0,%1,%2,%3}, [%4];"
                 : "=r"(v.x), "=r"(v.y), "=r"(v.z), "=r"(v.w) : "l"(p));
    return v;
}
__device__ __forceinline__ float2 ldcg64f(const float* p) {
    float2 v;
    asm volatile("ld.global.cg.v2.f32 {%0,%1}, [%2];" : "=f"(v.x), "=f"(v.y) : "l"(p));
    return v;
}
__device__ __forceinline__ void grid_sync(unsigned int target, unsigned int* bar) {
    __syncthreads();
    if (threadIdx.x == 0) {
        asm volatile("red.release.gpu.global.add.u32 [%0], 1;" :: "l"(bar) : "memory");
        unsigned int v;
        do {
            asm volatile("ld.acquire.gpu.global.u32 %0, [%1];" : "=r"(v) : "l"(bar) : "memory");
        } while (v < target);
    }
    __syncthreads();
}

// ---------------------------------------------------------------------------
// Setup kernels
// ---------------------------------------------------------------------------
__global__ void init_kernel(uint32_t* sf) {
    int i = blockIdx.x * 256 + threadIdx.x;
    if (i == 0) g_bar = 0u;
    if (i < 2 * 32768) sf[i] = 0u;
}

__global__ void sb_kernel(const int* __restrict__ sampled,
                          const float* __restrict__ softmax_b,
                          const float* __restrict__ scounts,
                          float* __restrict__ sbv) {
    int j = blockIdx.x * 256 + threadIdx.x;
    if (j < S_) sbv[j] = softmax_b[sampled[j]] - logf(scounts[j]);
}

// Weight -> fragment-linear bf16 hi/lo. Block = (l*128 + cta); 8 cols, 2 gates.
__global__ __launch_bounds__(256)
void wcvt_kernel(const float* __restrict__ Wh0, const float* __restrict__ Wt0,
                 const float* __restrict__ Wh,  const float* __restrict__ Wt,
                 uint32_t* __restrict__ Wf) {
    __shared__ float ws[256][17];
    int b = blockIdx.x;
    int cta = b & 127;
    int l = b >> 7;
    int cbase = cta * 8;
    int tid = threadIdx.x;
    uint32_t* outp = Wf + (size_t)(l * 128 + cta) * 16384;

    for (int kb = 0; kb < 4; kb++) {
#pragma unroll
        for (int e = 0; e < 16; e++) {
            int idx = tid + e * 256;
            int k = idx >> 4, cg = idx & 15;
            int g = cg >> 3, c = cg & 7;
            int kg = kb * 256 + k;
            float v;
            if (l == 0) v = (g ? Wt0 : Wh0)[(size_t)(U_ + kg) * R_ + cbase + c];
            else        v = (g ? Wt : Wh)[((size_t)(l - 1) * R_ + kg) * R_ + cbase + c];
            ws[k][g * 8 + c] = v;
        }
        __syncthreads();
#pragma unroll
        for (int e = 0; e < 16; e++) {
            int o = tid + e * 256;
            int ksl = o >> 8;
            int rem = o & 255;
            int term = rem >> 7;
            int rem2 = rem & 127;
            int lane = rem2 >> 2;
            int r = rem2 & 3;
            int gate = r & 1;
            int c = lane >> 2;
            int kk = (lane & 3) * 2 + (r >> 1) * 8;
            int kl = ksl * 16 + kk;
            float w0 = ws[kl][gate * 8 + c];
            float w1 = ws[kl + 1][gate * 8 + c];
            uint16_t p0, p1;
            if (term == 0) {
                p0 = __bfloat16_as_ushort(__float2bfloat16(w0));
                p1 = __bfloat16_as_ushort(__float2bfloat16(w1));
            } else {
                float h0 = __bfloat162float(__float2bfloat16(w0));
                float h1 = __bfloat162float(__float2bfloat16(w1));
                p0 = __bfloat16_as_ushort(__float2bfloat16(w0 - h0));
                p1 = __bfloat16_as_ushort(__float2bfloat16(w1 - h1));
            }
            int ks = kb * 16 + ksl;
            outp[((ks * 2 + term) * 32 + lane) * 4 + r] = ((uint32_t)p1 << 16) | p0;
        }
        __syncthreads();
    }
}

// ---------------------------------------------------------------------------
// fp32 tiled GEMM (parallel pre/post parts)
// ---------------------------------------------------------------------------
template <int AMODE, int BTRANS>
__global__ __launch_bounds__(256)
void sgemm_kernel(const float* __restrict__ A, const float* __restrict__ Bm,
                  const float* __restrict__ bias, float* __restrict__ C,
                  int M, int N, int K, int lda, int ldb, int ldc,
                  const int* __restrict__ b_idx) {
    __shared__ float As[16][68];
    __shared__ float Bs[16][68];
    const int bm = blockIdx.y * 64;
    const int bn = blockIdx.x * 64;
    const int tid = threadIdx.x;
    const int tx = tid & 15;
    const int ty = tid >> 4;

    float acc[4][4];
#pragma unroll
    for (int i = 0; i < 4; i++)
#pragma unroll
        for (int j = 0; j < 4; j++) acc[i][j] = 0.f;

    const int arow_local = tid >> 2;
    const int akk = (tid & 3) * 4;
    const int grow = bm + arow_local;
    const float* arow_ptr;
    if (AMODE == 0)      arow_ptr = A + (size_t)grow * lda;
    else                 arow_ptr = A + (size_t)((grow % T_) * B_ + grow / T_) * lda;

    const float* brow_ptr = nullptr;
    if (BTRANS == 1) {
        int bncol = bn + (tid >> 2);
        int ridx = b_idx ? b_idx[bncol] : bncol;
        brow_ptr = Bm + (size_t)ridx * ldb;
    }

    for (int k0 = 0; k0 < K; k0 += 16) {
        {
            float4 va = *(const float4*)(arow_ptr + k0 + akk);
            As[akk + 0][arow_local] = va.x;
            As[akk + 1][arow_local] = va.y;
            As[akk + 2][arow_local] = va.z;
            As[akk + 3][arow_local] = va.w;
        }
        if (BTRANS == 0) {
            int kr = tid >> 4;
            int nn = (tid & 15) * 4;
            float4 vb = *(const float4*)(Bm + (size_t)(k0 + kr) * ldb + bn + nn);
            *(float4*)&Bs[kr][nn] = vb;
        } else {
            float4 vb = *(const float4*)(brow_ptr + k0 + akk);
            int nl = tid >> 2;
            Bs[akk + 0][nl] = vb.x;
            Bs[akk + 1][nl] = vb.y;
            Bs[akk + 2][nl] = vb.z;
            Bs[akk + 3][nl] = vb.w;
        }
        __syncthreads();
#pragma unroll
        for (int k = 0; k < 16; k++) {
            float a[4], b[4];
            *(float4*)a = *(const float4*)&As[k][ty * 4];
            *(float4*)b = *(const float4*)&Bs[k][tx * 4];
#pragma unroll
            for (int i = 0; i < 4; i++)
#pragma unroll
                for (int j = 0; j < 4; j++)
                    acc[i][j] = fmaf(a[i], b[j], acc[i][j]);
        }
        __syncthreads();
    }

#pragma unroll
    for (int i = 0; i < 4; i++) {
        int row = bm + ty * 4 + i;
#pragma unroll
        for (int j = 0; j < 4; j++) {
            int col = bn + tx * 4 + j;
            C[(size_t)row * ldc + col] = acc[i][j] + (bias ? bias[col] : 0.f);
        }
    }
}

// ---------------------------------------------------------------------------
// Persistent recurrence: register-direct fragment loads, K split across warps.
// State in bf16-hi only; W in hi/lo (2 MMA terms).
// ---------------------------------------------------------------------------
__global__ __launch_bounds__(RTHR, 1)
void rec_mma_kernel(const uint32_t* __restrict__ Wf,
                    uint32_t* __restrict__ Sf,
                    const int* __restrict__ input_data,
                    const float* __restrict__ Eh, const float* __restrict__ Et,
                    const float* __restrict__ bh, const float* __restrict__ bt,
                    float* __restrict__ states) {
    __shared__ float part[8][16][68];   // per-warp D partials
    __shared__ float sold[64][9];
    __shared__ float bias_s[32];        // [l-1][gate][8 cols]
    __shared__ float stage_st[64][8];   // states staging (coalesced copy-out)

    const int tid = threadIdx.x;
    const int lane = tid & 31;
    const int w = tid >> 5;
    const int cta = blockIdx.x;
    const int cbase = cta * 8;
    const int eb = tid & 63;            // epilogue batch row
    const int ec0 = (tid >> 6) * 2;     // epilogue column pair

    for (int i = tid; i < 64 * 9; i += RTHR) ((float*)sold)[i] = 0.f;
    if (tid < 32) {
        int l2 = tid >> 4, g = (tid >> 3) & 1, c = tid & 7;
        bias_s[tid] = (g ? bt : bh)[l2 * R_ + cbase + c];
    }
    __syncthreads();

    // register prefetch of Eh/Et rows for t=0 (consumed at next l==0 epilogue)
    float2 pe_h, pe_t;
    {
        int vid = __ldg(&input_data[eb * T_ + 0]);
        pe_h = ldcg64f(&Eh[(size_t)vid * R_ + cbase + ec0]);
        pe_t = ldcg64f(&Et[(size_t)vid * R_ + cbase + ec0]);
    }

    unsigned int pc = 0;
    int t = 0, l = 0;

    for (int p = 0; p < 3 * T_; p++) {
        const int rbuf = p & 1;
        const uint4* SB = (const uint4*)(Sf + rbuf * 32768);
        uint32_t* sOut = Sf + (rbuf ^ 1) * 32768;
        const uint4* WA = (const uint4*)Wf + (size_t)(l * 128 + cta) * 4096;

        float dH[8][4], dL[8][4];
#pragma unroll
        for (int g = 0; g < 8; g++)
#pragma unroll
            for (int r = 0; r < 4; r++) { dH[g][r] = 0.f; dL[g][r] = 0.f; }

        const int ks0 = w * 8;
#pragma unroll 4
        for (int j = 0; j < 8; j++) {
            int ks = ks0 + j;
            uint4 aH = __ldg(WA + (ks * 2 + 0) * 32 + lane);
            uint4 aL = __ldg(WA + (ks * 2 + 1) * 32 + lane);
            uint4 bF[4];
#pragma unroll
            for (int gp = 0; gp < 4; gp++)
                bF[gp] = ldg128cg(SB + (ks * 4 + gp) * 32 + lane);
#pragma unroll
            for (int gp = 0; gp < 4; gp++) {
                mma_acc(dH[2 * gp],     aH, bF[gp].x, bF[gp].y);
                mma_acc(dH[2 * gp + 1], aH, bF[gp].z, bF[gp].w);
                mma_acc(dL[2 * gp],     aL, bF[gp].x, bF[gp].y);
                mma_acc(dL[2 * gp + 1], aL, bF[gp].z, bF[gp].w);
            }
        }

        // store partials (combine W hi/lo terms)
        {
            int row = lane >> 2;
            int nb = (lane & 3) * 2;
#pragma unroll
            for (int g = 0; g < 8; g++) {
                *(float2*)&part[w][row][nb + g * 8] =
                    make_float2(dH[g][0] + dL[g][0], dH[g][1] + dL[g][1]);
                *(float2*)&part[w][row + 8][nb + g * 8] =
                    make_float2(dH[g][2] + dL[g][2], dH[g][3] + dL[g][3]);
            }
        }
        __syncthreads();

        // epilogue: (4 col-pairs) x (64 batch)
        {
            uint16_t sh[2];
#pragma unroll
            for (int s = 0; s < 2; s++) {
                int c = ec0 + s;
                float zh = 0.f, zt = 0.f;
#pragma unroll
                for (int q = 0; q < 8; q++) {
                    zh += part[q][c][eb];
                    zt += part[q][8 + c][eb];
                }
                if (l == 0) {
                    zh += (s == 0) ? pe_h.x : pe_h.y;
                    zt += (s == 0) ? pe_t.x : pe_t.y;
                } else {
                    zh += bias_s[(l - 1) * 16 + c];
                    zt += bias_s[(l - 1) * 16 + 8 + c];
                }
                float so = sold[eb][c];
                float hh = tanhf(zh);
                float tg = 1.f / (1.f + expf(-zt));
                float sn = (hh - so) * tg + so;
                sold[eb][c] = sn;
                sh[s] = __bfloat16_as_ushort(__float2bfloat16(sn));
                if (l == 2) stage_st[eb][c] = sn;
            }
            // scatter into B-fragment layout (hi only)
            int kk0 = (cta & 1) * 8 + ec0;
            int q = (kk0 >> 1) & 3;
            int reg = cta & 1;
            int g = eb >> 3;
            int lt = (eb & 7) * 4 + q;
            int ks = cta >> 1;
            int slot = (g & 1) * 2 + reg;
            int gp = g >> 1;
            sOut[(uint32_t)(((ks * 4 + gp) * 32 + lt) * 4 + slot)] =
                ((uint32_t)sh[1] << 16) | sh[0];
        }

        // register prefetch for next timestep's l==0 epilogue
        if (l == 1) {
            int tq = (t < T_ - 1) ? t + 1 : t;
            int vid = __ldg(&input_data[eb * T_ + tq]);
            pe_h = ldcg64f(&Eh[(size_t)vid * R_ + cbase + ec0]);
            pe_t = ldcg64f(&Et[(size_t)vid * R_ + cbase + ec0]);
        }

        if (l == 2) {
            __syncthreads();
            if (tid < 128) {
                int rb = tid >> 1, half = tid & 1;
                *(float4*)&states[((size_t)t * B_ + rb) * R_ + cbase + half * 4] =
                    *(float4*)&stage_st[rb][half * 4];
            }
        }

        pc++;
        grid_sync(RCTA * pc, &g_bar);
        if (++l == 3) { l = 0; t++; }
    }
}

// ---------------------------------------------------------------------------
// Loss + mean
// ---------------------------------------------------------------------------
__global__ __launch_bounds__(256)
void loss_kernel(const float* __restrict__ outb,
                 const float* __restrict__ logits,
                 const int* __restrict__ targets,
                 const int* __restrict__ sampled,
                 const float* __restrict__ true_counts,
                 const float* __restrict__ sw,
                 const float* __restrict__ softmax_b,
                 float* __restrict__ loss) {
    __shared__ float red[256];
    __shared__ float sh_true, sh_max;
    const int i = blockIdx.x;
    const int tid = threadIdx.x;
    const int label = targets[i];

    float p = 0.f;
    for (int u = tid; u < U_; u += 256)
        p += outb[(size_t)i * U_ + u] * sw[(size_t)label * U_ + u];
    red[tid] = p; __syncthreads();
    for (int s = 128; s > 0; s >>= 1) {
        if (tid < s) red[tid] += red[tid + s];
        __syncthreads();
    }
    if (tid == 0) sh_true = red[0] + softmax_b[label] - logf(true_counts[i]);
    __syncthreads();
    const float tl = sh_true;

    float mx = -1e30f;
    for (int j = tid; j < S_; j += 256) {
        float v = logits[(size_t)i * S_ + j];
        if (sampled[j] == label) v -= 1e9f;
        mx = fmaxf(mx, v);
    }
    red[tid] = mx; __syncthreads();
    for (int s = 128; s > 0; s >>= 1) {
        if (tid < s) red[tid] = fmaxf(red[tid], red[tid + s]);
        __syncthreads();
    }
    if (tid == 0) sh_max = fmaxf(red[0], tl);
    __syncthreads();
    const float mval = sh_max;

    float sm = 0.f;
    for (int j = tid; j < S_; j += 256) {
        float v = logits[(size_t)i * S_ + j];
        if (sampled[j] == label) v -= 1e9f;
        sm += expf(v - mval);
    }
    red[tid] = sm; __syncthreads();
    for (int s = 128; s > 0; s >>= 1) {
        if (tid < s) red[tid] += red[tid + s];
        __syncthreads();
    }
    if (tid == 0) {
        float total = red[0] + expf(tl - mval);
        loss[i] = mval + logf(total) - tl;
    }
}

__global__ void reduce_mean_kernel(const float* __restrict__ loss, float* __restrict__ out) {
    __shared__ float red[256];
    const int tid = threadIdx.x;
    float s = 0.f;
    for (int i = tid; i < N_; i += 256) s += loss[i];
    red[tid] = s; __syncthreads();
    for (int st = 128; st > 0; st >>= 1) {
        if (tid < st) red[tid] += red[tid + st];
        __syncthreads();
    }
    if (tid == 0) out[0] = red[0] / (float)N_;
}

// ---------------------------------------------------------------------------
// Launch
// ---------------------------------------------------------------------------
extern "C" void kernel_launch(void* const* d_in, const int* in_sizes, int n_in,
                              void* d_out, int out_size) {
    const int*   input_data = (const int*)d_in[0];
    const int*   targets    = (const int*)d_in[1];
    const int*   sampled    = (const int*)d_in[2];
    const float* true_cnt   = (const float*)d_in[3];
    const float* samp_cnt   = (const float*)d_in[4];
    const float* embedding  = (const float*)d_in[5];
    const float* Wh0        = (const float*)d_in[6];
    const float* bh0        = (const float*)d_in[7];
    const float* Wt0        = (const float*)d_in[8];
    const float* bt0        = (const float*)d_in[9];
    const float* Wh         = (const float*)d_in[10];
    const float* bh         = (const float*)d_in[11];
    const float* Wt         = (const float*)d_in[12];
    const float* bt         = (const float*)d_in[13];
    const float* Wp         = (const float*)d_in[14];
    const float* bp         = (const float*)d_in[15];
    const float* sw         = (const float*)d_in[16];
    const float* smb        = (const float*)d_in[17];
    float* out = (float*)d_out;

    float *Eh, *Et, *states, *outb, *logits, *sbv, *lossv;
    uint32_t *Wf, *Sf;
    cudaGetSymbolAddress((void**)&Eh, g_Eh);
    cudaGetSymbolAddress((void**)&Et, g_Et);
    cudaGetSymbolAddress((void**)&states, g_states);
    cudaGetSymbolAddress((void**)&outb, g_outb);
    cudaGetSymbolAddress((void**)&logits, g_logits);
    cudaGetSymbolAddress((void**)&sbv, g_sbv);
    cudaGetSymbolAddress((void**)&lossv, g_loss);
    cudaGetSymbolAddress((void**)&Wf, g_Wf);
    cudaGetSymbolAddress((void**)&Sf, g_Sf);

    init_kernel<<<(2 * 32768 + 255) / 256, 256>>>(Sf);
    sb_kernel<<<(S_ + 255) / 256, 256>>>(sampled, smb, samp_cnt, sbv);
    wcvt_kernel<<<384, 256>>>(Wh0, Wt0, Wh, Wt, Wf);

    // Vocab-space x-part precompute for layer 0
    {
        dim3 grid(R_ / 64, V_ / 64);
        sgemm_kernel<0, 0><<<grid, 256>>>(embedding, Wh0, bh0, Eh,
                                          V_, R_, U_, U_, R_, R_, nullptr);
        sgemm_kernel<0, 0><<<grid, 256>>>(embedding, Wt0, bt0, Et,
                                          V_, R_, U_, U_, R_, R_, nullptr);
    }

    // Persistent recurrence (register-direct warp MMA, hi-only state)
    rec_mma_kernel<<<RCTA, RTHR>>>(Wf, Sf, input_data, Eh, Et, bh, bt, states);

    // outputs[b*T+t,:] = states[t*B+b,:] @ Wp + bp
    {
        dim3 grid(U_ / 64, N_ / 64);
        sgemm_kernel<2, 0><<<grid, 256>>>(states, Wp, bp, outb,
                                          N_, U_, R_, R_, U_, U_, nullptr);
    }
    // sampled logits
    {
        dim3 grid(S_ / 64, N_ / 64);
        sgemm_kernel<0, 1><<<grid, 256>>>(outb, sw, sbv, logits,
                                          N_, S_, U_, U_, U_, S_, sampled);
    }

    loss_kernel<<<N_, 256>>>(outb, logits, targets, sampled, true_cnt, sw, smb, lossv);
    reduce_mean_kernel<<<1, 256>>>(lossv, out);
}

// round 10
// speedup vs baseline: 4.1834x; 1.0337x over previous
#include <cuda_runtime.h>
#include <cuda_bf16.h>
#include <math.h>
#include <stdint.h>

#define V_ 8000
#define B_ 64
#define T_ 256
#define R_ 1024
#define U_ 512
#define S_ 1024
#define N_ (B_ * T_)

#define RCTA 128
#define RTHR 256

// ---------------------------------------------------------------------------
// Device global scratch
// ---------------------------------------------------------------------------
__device__ float g_Eh[(size_t)V_ * R_];
__device__ float g_Et[(size_t)V_ * R_];
__device__ float g_states[(size_t)T_ * B_ * R_];
__device__ uint32_t g_Wf[(size_t)3 * 128 * 16384];
__device__ uint32_t g_Sf[2 * 32768];
__device__ float g_outb[(size_t)N_ * U_];
__device__ float g_logits[(size_t)N_ * S_];
__device__ float g_sbv[S_];
__device__ float g_loss[N_];
__device__ unsigned int g_bar;
// B fragment buffers for tensor GEMMs: [K/16][N/8][lane32] x uint4{hi0,hi1,lo0,lo1}
__device__ uint4 g_Bf_eh[131072];   // Wh0[0:U] :  K=512,  N=1024
__device__ uint4 g_Bf_et[131072];   // Wt0[0:U]
__device__ uint4 g_Bf_op[131072];   // Wp      :  K=1024, N=512
__device__ uint4 g_Bf_lg[131072];   // sw[sampled].T : K=512, N=1024

// ---------------------------------------------------------------------------
// PTX helpers
// ---------------------------------------------------------------------------
__device__ __forceinline__ void mma_acc(float* d, const uint4& a, uint32_t b0, uint32_t b1) {
    asm volatile(
        "mma.sync.aligned.m16n8k16.row.col.f32.bf16.bf16.f32 "
        "{%0,%1,%2,%3},{%4,%5,%6,%7},{%8,%9},{%0,%1,%2,%3};"
        : "+f"(d[0]), "+f"(d[1]), "+f"(d[2]), "+f"(d[3])
        : "r"(a.x), "r"(a.y), "r"(a.z), "r"(a.w), "r"(b0), "r"(b1));
}
__device__ __forceinline__ uint4 ldg128cg(const uint4* p) {
    uint4 v;
    asm volatile("ld.global.cg.v4.u32 {%0,%1,%2,%3}, [%4];"
                 : "=r"(v.x), "=r"(v.y), "=r"(v.z), "=r"(v.w) : "l"(p));
    return v;
}
__device__ __forceinline__ float2 ldcg64f(const float* p) {
    float2 v;
    asm volatile("ld.global.cg.v2.f32 {%0,%1}, [%2];" : "=f"(v.x), "=f"(v.y) : "l"(p));
    return v;
}
__device__ __forceinline__ void grid_sync(unsigned int target, unsigned int* bar) {
    __syncthreads();
    if (threadIdx.x == 0) {
        asm volatile("red.release.gpu.global.add.u32 [%0], 1;" :: "l"(bar) : "memory");
        unsigned int v;
        do {
            asm volatile("ld.acquire.gpu.global.u32 %0, [%1];" : "=r"(v) : "l"(bar) : "memory");
        } while (v < target);
    }
    __syncthreads();
}
__device__ __forceinline__ uint32_t pack_hi(float x0, float x1) {
    uint16_t h0 = __bfloat16_as_ushort(__float2bfloat16(x0));
    uint16_t h1 = __bfloat16_as_ushort(__float2bfloat16(x1));
    return ((uint32_t)h1 << 16) | h0;
}
__device__ __forceinline__ uint32_t pack_lo(float x0, float x1) {
    float r0 = x0 - __bfloat162float(__float2bfloat16(x0));
    float r1 = x1 - __bfloat162float(__float2bfloat16(x1));
    return pack_hi(r0, r1);
}

// ---------------------------------------------------------------------------
// Setup kernels
// ---------------------------------------------------------------------------
__global__ void init_kernel(uint32_t* sf) {
    int i = blockIdx.x * 256 + threadIdx.x;
    if (i == 0) g_bar = 0u;
    if (i < 2 * 32768) sf[i] = 0u;
}

__global__ void sb_kernel(const int* __restrict__ sampled,
                          const float* __restrict__ softmax_b,
                          const float* __restrict__ scounts,
                          float* __restrict__ sbv) {
    int j = blockIdx.x * 256 + threadIdx.x;
    if (j < S_) sbv[j] = softmax_b[sampled[j]] - logf(scounts[j]);
}

// B-fragment prep from row-major src[k][n] (row stride ldb). total = (K/16)*(N/8)*32.
__global__ __launch_bounds__(256)
void prep_b_kn(const float* __restrict__ src, uint4* __restrict__ out,
               int K, int N, int ldb) {
    int idx = blockIdx.x * 256 + threadIdx.x;
    int total = (K >> 4) * (N >> 3) * 32;
    if (idx >= total) return;
    int lane = idx & 31;
    int nt = (idx >> 5) % (N >> 3);
    int gks = (idx >> 5) / (N >> 3);
    int g = lane >> 2, tg = lane & 3;
    int n = nt * 8 + g;
    int k0 = gks * 16 + tg * 2;
    float a0 = src[(size_t)k0 * ldb + n];
    float a1 = src[(size_t)(k0 + 1) * ldb + n];
    float a2 = src[(size_t)(k0 + 8) * ldb + n];
    float a3 = src[(size_t)(k0 + 9) * ldb + n];
    out[idx] = make_uint4(pack_hi(a0, a1), pack_hi(a2, a3),
                          pack_lo(a0, a1), pack_lo(a2, a3));
}

// B-fragment prep for logits: B[k][n] = sw[sampled[n]*U + k]
__global__ __launch_bounds__(256)
void prep_b_gather(const float* __restrict__ sw, const int* __restrict__ sampled,
                   uint4* __restrict__ out) {
    int idx = blockIdx.x * 256 + threadIdx.x;
    const int K = U_, N = S_;
    int total = (K >> 4) * (N >> 3) * 32;
    if (idx >= total) return;
    int lane = idx & 31;
    int nt = (idx >> 5) % (N >> 3);
    int gks = (idx >> 5) / (N >> 3);
    int g = lane >> 2, tg = lane & 3;
    int n = nt * 8 + g;
    int k0 = gks * 16 + tg * 2;
    const float* row = sw + (size_t)sampled[n] * U_;
    float a0 = row[k0], a1 = row[k0 + 1], a2 = row[k0 + 8], a3 = row[k0 + 9];
    out[idx] = make_uint4(pack_hi(a0, a1), pack_hi(a2, a3),
                          pack_lo(a0, a1), pack_lo(a2, a3));
}

// Weight -> fragment-linear bf16 hi/lo for recurrence (unchanged from R8).
__global__ __launch_bounds__(256)
void wcvt_kernel(const float* __restrict__ Wh0, const float* __restrict__ Wt0,
                 const float* __restrict__ Wh,  const float* __restrict__ Wt,
                 uint32_t* __restrict__ Wf) {
    __shared__ float ws[256][17];
    int b = blockIdx.x;
    int cta = b & 127;
    int l = b >> 7;
    int cbase = cta * 8;
    int tid = threadIdx.x;
    uint32_t* outp = Wf + (size_t)(l * 128 + cta) * 16384;

    for (int kb = 0; kb < 4; kb++) {
#pragma unroll
        for (int e = 0; e < 16; e++) {
            int idx = tid + e * 256;
            int k = idx >> 4, cg = idx & 15;
            int g = cg >> 3, c = cg & 7;
            int kg = kb * 256 + k;
            float v;
            if (l == 0) v = (g ? Wt0 : Wh0)[(size_t)(U_ + kg) * R_ + cbase + c];
            else        v = (g ? Wt : Wh)[((size_t)(l - 1) * R_ + kg) * R_ + cbase + c];
            ws[k][g * 8 + c] = v;
        }
        __syncthreads();
#pragma unroll
        for (int e = 0; e < 16; e++) {
            int o = tid + e * 256;
            int ksl = o >> 8;
            int rem = o & 255;
            int term = rem >> 7;
            int rem2 = rem & 127;
            int lane = rem2 >> 2;
            int r = rem2 & 3;
            int gate = r & 1;
            int c = lane >> 2;
            int kk = (lane & 3) * 2 + (r >> 1) * 8;
            int kl = ksl * 16 + kk;
            float w0 = ws[kl][gate * 8 + c];
            float w1 = ws[kl + 1][gate * 8 + c];
            uint32_t val = term ? pack_lo(w0, w1) : pack_hi(w0, w1);
            int ks = kb * 16 + ksl;
            outp[((ks * 2 + term) * 32 + lane) * 4 + r] = val;
        }
        __syncthreads();
    }
}

// ---------------------------------------------------------------------------
// Tensor-core GEMM: C[M,N] = op(A)[M,K] @ B[K,N] + bias
// A fp32 converted on-the-fly to bf16 hi/lo fragments in smem.
// B pre-converted fragment buffer. 3-term split, fp32 accum.
// AMODE 0: A[row]; AMODE 2: A[(row%T)*B + row/T]  (states remap)
// Grid: (N/64, M/64), 256 threads.
// ---------------------------------------------------------------------------
template <int AMODE>
__global__ __launch_bounds__(256)
void tgemm_kernel(const float* __restrict__ A, const uint4* __restrict__ Bf,
                  const float* __restrict__ bias, float* __restrict__ C,
                  int M, int N, int K, int lda, int ldc) {
    __shared__ uint32_t afrag[4 * 4 * 2 * 32 * 4];   // [ks][mt][term][lane][reg]
    const int tid = threadIdx.x;
    const int lane = tid & 31;
    const int w = tid >> 5;
    const int mh = w >> 2;          // 0..1
    const int nq = w & 3;           // 0..3
    const int bm = blockIdx.y * 64;
    const int bn = blockIdx.x * 64;
    const int ntiles = N >> 3;

    // A loader: thread covers row arow, kstep ks_local (16 floats)
    const int arow = tid >> 2;
    const int ksl = tid & 3;
    const int grow = bm + arow;
    const float* aptr;
    if (AMODE == 0) aptr = A + (size_t)grow * lda;
    else            aptr = A + (size_t)((grow % T_) * B_ + grow / T_) * lda;
    aptr += ksl * 16;

    // scatter constants for this thread's row
    const int r = arow & 15, mt = arow >> 4;
    const int laneb = (r & 7) * 4, regb = r >> 3;
    uint32_t* afr_h = &afrag[(((ksl * 4 + mt) * 2 + 0) * 32) * 4];
    uint32_t* afr_l = &afrag[(((ksl * 4 + mt) * 2 + 1) * 32) * 4];

    float d[2][2][4];
#pragma unroll
    for (int i = 0; i < 2; i++)
#pragma unroll
        for (int j = 0; j < 2; j++)
#pragma unroll
            for (int q = 0; q < 4; q++) d[i][j][q] = 0.f;

    for (int k0 = 0; k0 < K; k0 += 64) {
        float4 v[4];
#pragma unroll
        for (int i = 0; i < 4; i++)
            v[i] = *(const float4*)(aptr + k0 + i * 4);
        __syncthreads();
        const float* vv = (const float*)v;
#pragma unroll
        for (int pi = 0; pi < 8; pi++) {
            float x0 = vv[2 * pi], x1 = vv[2 * pi + 1];
            int off = (laneb + (pi & 3)) * 4 + regb + 2 * (pi >> 2);
            afr_h[off] = pack_hi(x0, x1);
            afr_l[off] = pack_lo(x0, x1);
        }
        __syncthreads();

#pragma unroll
        for (int s = 0; s < 4; s++) {
            int gks = (k0 >> 4) + s;
            uint4 b0 = ldg128cg(&Bf[((size_t)gks * ntiles + (bn >> 3) + nq * 2 + 0) * 32 + lane]);
            uint4 b1 = ldg128cg(&Bf[((size_t)gks * ntiles + (bn >> 3) + nq * 2 + 1) * 32 + lane]);
            uint4 aH0 = *(const uint4*)&afrag[(((s * 4 + mh * 2 + 0) * 2 + 0) * 32 + lane) * 4];
            uint4 aL0 = *(const uint4*)&afrag[(((s * 4 + mh * 2 + 0) * 2 + 1) * 32 + lane) * 4];
            uint4 aH1 = *(const uint4*)&afrag[(((s * 4 + mh * 2 + 1) * 2 + 0) * 32 + lane) * 4];
            uint4 aL1 = *(const uint4*)&afrag[(((s * 4 + mh * 2 + 1) * 2 + 1) * 32 + lane) * 4];
            // mtile 0
            mma_acc(d[0][0], aH0, b0.x, b0.y);
            mma_acc(d[0][0], aH0, b0.z, b0.w);
            mma_acc(d[0][0], aL0, b0.x, b0.y);
            mma_acc(d[0][1], aH0, b1.x, b1.y);
            mma_acc(d[0][1], aH0, b1.z, b1.w);
            mma_acc(d[0][1], aL0, b1.x, b1.y);
            // mtile 1
            mma_acc(d[1][0], aH1, b0.x, b0.y);
            mma_acc(d[1][0], aH1, b0.z, b0.w);
            mma_acc(d[1][0], aL1, b0.x, b0.y);
            mma_acc(d[1][1], aH1, b1.x, b1.y);
            mma_acc(d[1][1], aH1, b1.z, b1.w);
            mma_acc(d[1][1], aL1, b1.x, b1.y);
        }
    }

    // epilogue
    const int g = lane >> 2, tg = lane & 3;
#pragma unroll
    for (int mti = 0; mti < 2; mti++) {
        int row0 = bm + (mh * 2 + mti) * 16 + g;
#pragma unroll
        for (int nti = 0; nti < 2; nti++) {
            int col = bn + (nq * 2 + nti) * 8 + tg * 2;
            float b0v = bias ? bias[col] : 0.f;
            float b1v = bias ? bias[col + 1] : 0.f;
            C[(size_t)row0 * ldc + col]           = d[mti][nti][0] + b0v;
            C[(size_t)row0 * ldc + col + 1]       = d[mti][nti][1] + b1v;
            C[(size_t)(row0 + 8) * ldc + col]     = d[mti][nti][2] + b0v;
            C[(size_t)(row0 + 8) * ldc + col + 1] = d[mti][nti][3] + b1v;
        }
    }
}

// ---------------------------------------------------------------------------
// Persistent recurrence (unchanged from R8)
// ---------------------------------------------------------------------------
__global__ __launch_bounds__(RTHR, 1)
void rec_mma_kernel(const uint32_t* __restrict__ Wf,
                    uint32_t* __restrict__ Sf,
                    const int* __restrict__ input_data,
                    const float* __restrict__ Eh, const float* __restrict__ Et,
                    const float* __restrict__ bh, const float* __restrict__ bt,
                    float* __restrict__ states) {
    __shared__ float part[8][16][68];
    __shared__ float sold[64][9];
    __shared__ float bias_s[32];
    __shared__ float stage_st[64][8];

    const int tid = threadIdx.x;
    const int lane = tid & 31;
    const int w = tid >> 5;
    const int cta = blockIdx.x;
    const int cbase = cta * 8;
    const int eb = tid & 63;
    const int ec0 = (tid >> 6) * 2;

    for (int i = tid; i < 64 * 9; i += RTHR) ((float*)sold)[i] = 0.f;
    if (tid < 32) {
        int l2 = tid >> 4, g = (tid >> 3) & 1, c = tid & 7;
        bias_s[tid] = (g ? bt : bh)[l2 * R_ + cbase + c];
    }
    __syncthreads();

    float2 pe_h, pe_t;
    {
        int vid = __ldg(&input_data[eb * T_ + 0]);
        pe_h = ldcg64f(&Eh[(size_t)vid * R_ + cbase + ec0]);
        pe_t = ldcg64f(&Et[(size_t)vid * R_ + cbase + ec0]);
    }

    unsigned int pc = 0;
    int t = 0, l = 0;

    for (int p = 0; p < 3 * T_; p++) {
        const int rbuf = p & 1;
        const uint4* SB = (const uint4*)(Sf + rbuf * 32768);
        uint32_t* sOut = Sf + (rbuf ^ 1) * 32768;
        const uint4* WA = (const uint4*)Wf + (size_t)(l * 128 + cta) * 4096;

        float dH[8][4], dL[8][4];
#pragma unroll
        for (int g = 0; g < 8; g++)
#pragma unroll
            for (int q = 0; q < 4; q++) { dH[g][q] = 0.f; dL[g][q] = 0.f; }

        const int ks0 = w * 8;
#pragma unroll 4
        for (int j = 0; j < 8; j++) {
            int ks = ks0 + j;
            uint4 aH = __ldg(WA + (ks * 2 + 0) * 32 + lane);
            uint4 aL = __ldg(WA + (ks * 2 + 1) * 32 + lane);
            uint4 bF[4];
#pragma unroll
            for (int gp = 0; gp < 4; gp++)
                bF[gp] = ldg128cg(SB + (ks * 4 + gp) * 32 + lane);
#pragma unroll
            for (int gp = 0; gp < 4; gp++) {
                mma_acc(dH[2 * gp],     aH, bF[gp].x, bF[gp].y);
                mma_acc(dH[2 * gp + 1], aH, bF[gp].z, bF[gp].w);
                mma_acc(dL[2 * gp],     aL, bF[gp].x, bF[gp].y);
                mma_acc(dL[2 * gp + 1], aL, bF[gp].z, bF[gp].w);
            }
        }

        {
            int row = lane >> 2;
            int nb = (lane & 3) * 2;
#pragma unroll
            for (int g = 0; g < 8; g++) {
                *(float2*)&part[w][row][nb + g * 8] =
                    make_float2(dH[g][0] + dL[g][0], dH[g][1] + dL[g][1]);
                *(float2*)&part[w][row + 8][nb + g * 8] =
                    make_float2(dH[g][2] + dL[g][2], dH[g][3] + dL[g][3]);
            }
        }
        __syncthreads();

        {
            uint16_t sh[2];
#pragma unroll
            for (int s = 0; s < 2; s++) {
                int c = ec0 + s;
                float zh = 0.f, zt = 0.f;
#pragma unroll
                for (int q = 0; q < 8; q++) {
                    zh += part[q][c][eb];
                    zt += part[q][8 + c][eb];
                }
                if (l == 0) {
                    zh += (s == 0) ? pe_h.x : pe_h.y;
                    zt += (s == 0) ? pe_t.x : pe_t.y;
                } else {
                    zh += bias_s[(l - 1) * 16 + c];
                    zt += bias_s[(l - 1) * 16 + 8 + c];
                }
                float so = sold[eb][c];
                float hh = tanhf(zh);
                float tg = 1.f / (1.f + expf(-zt));
                float sn = (hh - so) * tg + so;
                sold[eb][c] = sn;
                sh[s] = __bfloat16_as_ushort(__float2bfloat16(sn));
                if (l == 2) stage_st[eb][c] = sn;
            }
            int kk0 = (cta & 1) * 8 + ec0;
            int q = (kk0 >> 1) & 3;
            int reg = cta & 1;
            int g = eb >> 3;
            int lt = (eb & 7) * 4 + q;
            int ks = cta >> 1;
            int slot = (g & 1) * 2 + reg;
            int gp = g >> 1;
            sOut[(uint32_t)(((ks * 4 + gp) * 32 + lt) * 4 + slot)] =
                ((uint32_t)sh[1] << 16) | sh[0];
        }

        if (l == 1) {
            int tq = (t < T_ - 1) ? t + 1 : t;
            int vid = __ldg(&input_data[eb * T_ + tq]);
            pe_h = ldcg64f(&Eh[(size_t)vid * R_ + cbase + ec0]);
            pe_t = ldcg64f(&Et[(size_t)vid * R_ + cbase + ec0]);
        }

        if (l == 2) {
            __syncthreads();
            if (tid < 128) {
                int rb = tid >> 1, half = tid & 1;
                *(float4*)&states[((size_t)t * B_ + rb) * R_ + cbase + half * 4] =
                    *(float4*)&stage_st[rb][half * 4];
            }
        }

        pc++;
        grid_sync(RCTA * pc, &g_bar);
        if (++l == 3) { l = 0; t++; }
    }
}

// ---------------------------------------------------------------------------
// Loss + mean
// ---------------------------------------------------------------------------
__global__ __launch_bounds__(256)
void loss_kernel(const float* __restrict__ outb,
                 const float* __restrict__ logits,
                 const int* __restrict__ targets,
                 const int* __restrict__ sampled,
                 const float* __restrict__ true_counts,
                 const float* __restrict__ sw,
                 const float* __restrict__ softmax_b,
                 float* __restrict__ loss) {
    __shared__ float red[256];
    __shared__ float sh_true, sh_max;
    const int i = blockIdx.x;
    const int tid = threadIdx.x;
    const int label = targets[i];

    float p = 0.f;
    for (int u = tid; u < U_; u += 256)
        p += outb[(size_t)i * U_ + u] * sw[(size_t)label * U_ + u];
    red[tid] = p; __syncthreads();
    for (int s = 128; s > 0; s >>= 1) {
        if (tid < s) red[tid] += red[tid + s];
        __syncthreads();
    }
    if (tid == 0) sh_true = red[0] + softmax_b[label] - logf(true_counts[i]);
    __syncthreads();
    const float tl = sh_true;

    float mx = -1e30f;
    for (int j = tid; j < S_; j += 256) {
        float v = logits[(size_t)i * S_ + j];
        if (sampled[j] == label) v -= 1e9f;
        mx = fmaxf(mx, v);
    }
    red[tid] = mx; __syncthreads();
    for (int s = 128; s > 0; s >>= 1) {
        if (tid < s) red[tid] = fmaxf(red[tid], red[tid + s]);
        __syncthreads();
    }
    if (tid == 0) sh_max = fmaxf(red[0], tl);
    __syncthreads();
    const float mval = sh_max;

    float sm = 0.f;
    for (int j = tid; j < S_; j += 256) {
        float v = logits[(size_t)i * S_ + j];
        if (sampled[j] == label) v -= 1e9f;
        sm += expf(v - mval);
    }
    red[tid] = sm; __syncthreads();
    for (int s = 128; s > 0; s >>= 1) {
        if (tid < s) red[tid] += red[tid + s];
        __syncthreads();
    }
    if (tid == 0) {
        float total = red[0] + expf(tl - mval);
        loss[i] = mval + logf(total) - tl;
    }
}

__global__ void reduce_mean_kernel(const float* __restrict__ loss, float* __restrict__ out) {
    __shared__ float red[256];
    const int tid = threadIdx.x;
    float s = 0.f;
    for (int i = tid; i < N_; i += 256) s += loss[i];
    red[tid] = s; __syncthreads();
    for (int st = 128; st > 0; st >>= 1) {
        if (tid < st) red[tid] += red[tid + st];
        __syncthreads();
    }
    if (tid == 0) out[0] = red[0] / (float)N_;
}

// ---------------------------------------------------------------------------
// Launch
// ---------------------------------------------------------------------------
extern "C" void kernel_launch(void* const* d_in, const int* in_sizes, int n_in,
                              void* d_out, int out_size) {
    const int*   input_data = (const int*)d_in[0];
    const int*   targets    = (const int*)d_in[1];
    const int*   sampled    = (const int*)d_in[2];
    const float* true_cnt   = (const float*)d_in[3];
    const float* samp_cnt   = (const float*)d_in[4];
    const float* embedding  = (const float*)d_in[5];
    const float* Wh0        = (const float*)d_in[6];
    const float* bh0        = (const float*)d_in[7];
    const float* Wt0        = (const float*)d_in[8];
    const float* bt0        = (const float*)d_in[9];
    const float* Wh         = (const float*)d_in[10];
    const float* bh         = (const float*)d_in[11];
    const float* Wt         = (const float*)d_in[12];
    const float* bt         = (const float*)d_in[13];
    const float* Wp         = (const float*)d_in[14];
    const float* bp         = (const float*)d_in[15];
    const float* sw         = (const float*)d_in[16];
    const float* smb        = (const float*)d_in[17];
    float* out = (float*)d_out;

    float *Eh, *Et, *states, *outb, *logits, *sbv, *lossv;
    uint32_t *Wf, *Sf;
    uint4 *BfEh, *BfEt, *BfOp, *BfLg;
    cudaGetSymbolAddress((void**)&Eh, g_Eh);
    cudaGetSymbolAddress((void**)&Et, g_Et);
    cudaGetSymbolAddress((void**)&states, g_states);
    cudaGetSymbolAddress((void**)&outb, g_outb);
    cudaGetSymbolAddress((void**)&logits, g_logits);
    cudaGetSymbolAddress((void**)&sbv, g_sbv);
    cudaGetSymbolAddress((void**)&lossv, g_loss);
    cudaGetSymbolAddress((void**)&Wf, g_Wf);
    cudaGetSymbolAddress((void**)&Sf, g_Sf);
    cudaGetSymbolAddress((void**)&BfEh, g_Bf_eh);
    cudaGetSymbolAddress((void**)&BfEt, g_Bf_et);
    cudaGetSymbolAddress((void**)&BfOp, g_Bf_op);
    cudaGetSymbolAddress((void**)&BfLg, g_Bf_lg);

    init_kernel<<<(2 * 32768 + 255) / 256, 256>>>(Sf);
    sb_kernel<<<(S_ + 255) / 256, 256>>>(sampled, smb, samp_cnt, sbv);
    wcvt_kernel<<<384, 256>>>(Wh0, Wt0, Wh, Wt, Wf);

    // B fragment preps
    prep_b_kn<<<512, 256>>>(Wh0, BfEh, U_, R_, R_);
    prep_b_kn<<<512, 256>>>(Wt0, BfEt, U_, R_, R_);
    prep_b_kn<<<512, 256>>>(Wp, BfOp, R_, U_, U_);
    prep_b_gather<<<512, 256>>>(sw, sampled, BfLg);

    // Vocab-space x-part precompute (tensor cores)
    {
        dim3 grid(R_ / 64, V_ / 64);
        tgemm_kernel<0><<<grid, 256>>>(embedding, BfEh, bh0, Eh, V_, R_, U_, U_, R_);
        tgemm_kernel<0><<<grid, 256>>>(embedding, BfEt, bt0, Et, V_, R_, U_, U_, R_);
    }

    // Persistent recurrence
    rec_mma_kernel<<<RCTA, RTHR>>>(Wf, Sf, input_data, Eh, Et, bh, bt, states);

    // outputs = states(remap) @ Wp + bp   (tensor cores)
    {
        dim3 grid(U_ / 64, N_ / 64);
        tgemm_kernel<2><<<grid, 256>>>(states, BfOp, bp, outb, N_, U_, R_, R_, U_);
    }
    // sampled logits = outb @ sw[sampled].T + sbv   (tensor cores)
    {
        dim3 grid(S_ / 64, N_ / 64);
        tgemm_kernel<0><<<grid, 256>>>(outb, BfLg, sbv, logits, N_, S_, U_, U_, S_);
    }

    loss_kernel<<<N_, 256>>>(outb, logits, targets, sampled, true_cnt, sw, smb, lossv);
    reduce_mean_kernel<<<1, 256>>>(lossv, out);
}

// round 11
// speedup vs baseline: 4.8984x; 1.1709x over previous
#include <cuda_runtime.h>
#include <cuda_bf16.h>
#include <math.h>
#include <stdint.h>

#define V_ 8000
#define B_ 64
#define T_ 256
#define R_ 1024
#define U_ 512
#define S_ 1024
#define N_ (B_ * T_)

#define RCTA 128
#define RTHR 256

// ---------------------------------------------------------------------------
// Device global scratch
// ---------------------------------------------------------------------------
__device__ float g_Eh[(size_t)V_ * R_];
__device__ float g_Et[(size_t)V_ * R_];
__device__ float g_states[(size_t)T_ * B_ * R_];
__device__ uint32_t g_Wf[(size_t)3 * 128 * 16384];
__device__ uint32_t g_Sf[2 * 32768];
__device__ float g_outb[(size_t)N_ * U_];
__device__ float g_logits[(size_t)N_ * S_];
__device__ float g_sbv[S_];
__device__ float g_loss[N_];
__device__ unsigned int g_bar;
// B fragment buffers: [K/16][N/8][lane32] uint4{hi0,hi1,lo0,lo1}
__device__ uint4 g_Bf_eh[131072];   // Wh0[0:U]:       K=512,  N=1024
__device__ uint4 g_Bf_et[131072];   // Wt0[0:U]
__device__ uint4 g_Bf_op[131072];   // Wp:             K=1024, N=512
__device__ uint4 g_Bf_lg[131072];   // sw[sampled].T:  K=512,  N=1024
// A fragment planes: [M/16][K/16][lane32] uint4 (hi plane, lo plane)
__device__ uint4 g_Aemb_h[512000],  g_Aemb_l[512000];   // embedding 8000x512
__device__ uint4 g_Ast_h[2097152],  g_Ast_l[2097152];   // states(remap) 16384x1024
__device__ uint4 g_Aob_h[1048576],  g_Aob_l[1048576];   // outb 16384x512

// ---------------------------------------------------------------------------
// PTX helpers
// ---------------------------------------------------------------------------
__device__ __forceinline__ void mma_acc(float* d, const uint4& a, uint32_t b0, uint32_t b1) {
    asm volatile(
        "mma.sync.aligned.m16n8k16.row.col.f32.bf16.bf16.f32 "
        "{%0,%1,%2,%3},{%4,%5,%6,%7},{%8,%9},{%0,%1,%2,%3};"
        : "+f"(d[0]), "+f"(d[1]), "+f"(d[2]), "+f"(d[3])
        : "r"(a.x), "r"(a.y), "r"(a.z), "r"(a.w), "r"(b0), "r"(b1));
}
__device__ __forceinline__ uint4 ldg128cg(const uint4* p) {
    uint4 v;
    asm volatile("ld.global.cg.v4.u32 {%0,%1,%2,%3}, [%4];"
                 : "=r"(v.x), "=r"(v.y), "=r"(v.z), "=r"(v.w) : "l"(p));
    return v;
}
__device__ __forceinline__ float2 ldcg64f(const float* p) {
    float2 v;
    asm volatile("ld.global.cg.v2.f32 {%0,%1}, [%2];" : "=f"(v.x), "=f"(v.y) : "l"(p));
    return v;
}
__device__ __forceinline__ void grid_sync(unsigned int target, unsigned int* bar) {
    __syncthreads();
    if (threadIdx.x == 0) {
        asm volatile("red.release.gpu.global.add.u32 [%0], 1;" :: "l"(bar) : "memory");
        unsigned int v;
        do {
            asm volatile("ld.acquire.gpu.global.u32 %0, [%1];" : "=r"(v) : "l"(bar) : "memory");
        } while (v < target);
    }
    __syncthreads();
}
__device__ __forceinline__ uint32_t pack_hi(float x0, float x1) {
    uint16_t h0 = __bfloat16_as_ushort(__float2bfloat16(x0));
    uint16_t h1 = __bfloat16_as_ushort(__float2bfloat16(x1));
    return ((uint32_t)h1 << 16) | h0;
}
__device__ __forceinline__ uint32_t pack_lo(float x0, float x1) {
    float r0 = x0 - __bfloat162float(__float2bfloat16(x0));
    float r1 = x1 - __bfloat162float(__float2bfloat16(x1));
    return pack_hi(r0, r1);
}

// ---------------------------------------------------------------------------
// Setup kernels
// ---------------------------------------------------------------------------
__global__ void init_kernel(uint32_t* sf) {
    int i = blockIdx.x * 256 + threadIdx.x;
    if (i == 0) g_bar = 0u;
    if (i < 2 * 32768) sf[i] = 0u;
}

__global__ void sb_kernel(const int* __restrict__ sampled,
                          const float* __restrict__ softmax_b,
                          const float* __restrict__ scounts,
                          float* __restrict__ sbv) {
    int j = blockIdx.x * 256 + threadIdx.x;
    if (j < S_) sbv[j] = softmax_b[sampled[j]] - logf(scounts[j]);
}

// B-fragment prep from row-major src[k][n]
__global__ __launch_bounds__(256)
void prep_b_kn(const float* __restrict__ src, uint4* __restrict__ out,
               int K, int N, int ldb) {
    int idx = blockIdx.x * 256 + threadIdx.x;
    int total = (K >> 4) * (N >> 3) * 32;
    if (idx >= total) return;
    int lane = idx & 31;
    int nt = (idx >> 5) % (N >> 3);
    int gks = (idx >> 5) / (N >> 3);
    int g = lane >> 2, tg = lane & 3;
    int n = nt * 8 + g;
    int k0 = gks * 16 + tg * 2;
    float a0 = src[(size_t)k0 * ldb + n];
    float a1 = src[(size_t)(k0 + 1) * ldb + n];
    float a2 = src[(size_t)(k0 + 8) * ldb + n];
    float a3 = src[(size_t)(k0 + 9) * ldb + n];
    out[idx] = make_uint4(pack_hi(a0, a1), pack_hi(a2, a3),
                          pack_lo(a0, a1), pack_lo(a2, a3));
}

__global__ __launch_bounds__(256)
void prep_b_gather(const float* __restrict__ sw, const int* __restrict__ sampled,
                   uint4* __restrict__ out) {
    int idx = blockIdx.x * 256 + threadIdx.x;
    const int K = U_, N = S_;
    int total = (K >> 4) * (N >> 3) * 32;
    if (idx >= total) return;
    int lane = idx & 31;
    int nt = (idx >> 5) % (N >> 3);
    int gks = (idx >> 5) / (N >> 3);
    int g = lane >> 2, tg = lane & 3;
    int n = nt * 8 + g;
    int k0 = gks * 16 + tg * 2;
    const float* row = sw + (size_t)sampled[n] * U_;
    float a0 = row[k0], a1 = row[k0 + 1], a2 = row[k0 + 8], a3 = row[k0 + 9];
    out[idx] = make_uint4(pack_hi(a0, a1), pack_hi(a2, a3),
                          pack_lo(a0, a1), pack_lo(a2, a3));
}

// A-fragment prep: row-major src[M][K] -> hi/lo planes [mt][kt][lane].
// REMAP 1: source row = (row % T)*B + row/T  (states -> outb order)
template <int REMAP>
__global__ __launch_bounds__(256)
void prep_a(const float* __restrict__ src, uint4* __restrict__ hi,
            uint4* __restrict__ lo, int M, int K, int lda) {
    int idx = blockIdx.x * 256 + threadIdx.x;
    int total = (M >> 4) * (K >> 4) * 32;
    if (idx >= total) return;
    int lane = idx & 31;
    int kt = (idx >> 5) % (K >> 4);
    int mt = (idx >> 5) / (K >> 4);
    int r = lane >> 2;
    int k0 = kt * 16 + (lane & 3) * 2;
    int row0 = mt * 16 + r, row1 = row0 + 8;
    const float *p0, *p1;
    if (REMAP) {
        p0 = src + (size_t)((row0 % T_) * B_ + row0 / T_) * lda;
        p1 = src + (size_t)((row1 % T_) * B_ + row1 / T_) * lda;
    } else {
        p0 = src + (size_t)row0 * lda;
        p1 = src + (size_t)row1 * lda;
    }
    float2 v0 = *(const float2*)(p0 + k0);
    float2 v1 = *(const float2*)(p1 + k0);
    float2 v2 = *(const float2*)(p0 + k0 + 8);
    float2 v3 = *(const float2*)(p1 + k0 + 8);
    hi[idx] = make_uint4(pack_hi(v0.x, v0.y), pack_hi(v1.x, v1.y),
                         pack_hi(v2.x, v2.y), pack_hi(v3.x, v3.y));
    lo[idx] = make_uint4(pack_lo(v0.x, v0.y), pack_lo(v1.x, v1.y),
                         pack_lo(v2.x, v2.y), pack_lo(v3.x, v3.y));
}

// Weight -> fragment-linear bf16 hi/lo for recurrence (unchanged).
__global__ __launch_bounds__(256)
void wcvt_kernel(const float* __restrict__ Wh0, const float* __restrict__ Wt0,
                 const float* __restrict__ Wh,  const float* __restrict__ Wt,
                 uint32_t* __restrict__ Wf) {
    __shared__ float ws[256][17];
    int b = blockIdx.x;
    int cta = b & 127;
    int l = b >> 7;
    int cbase = cta * 8;
    int tid = threadIdx.x;
    uint32_t* outp = Wf + (size_t)(l * 128 + cta) * 16384;

    for (int kb = 0; kb < 4; kb++) {
#pragma unroll
        for (int e = 0; e < 16; e++) {
            int idx = tid + e * 256;
            int k = idx >> 4, cg = idx & 15;
            int g = cg >> 3, c = cg & 7;
            int kg = kb * 256 + k;
            float v;
            if (l == 0) v = (g ? Wt0 : Wh0)[(size_t)(U_ + kg) * R_ + cbase + c];
            else        v = (g ? Wt : Wh)[((size_t)(l - 1) * R_ + kg) * R_ + cbase + c];
            ws[k][g * 8 + c] = v;
        }
        __syncthreads();
#pragma unroll
        for (int e = 0; e < 16; e++) {
            int o = tid + e * 256;
            int ksl = o >> 8;
            int rem = o & 255;
            int term = rem >> 7;
            int rem2 = rem & 127;
            int lane = rem2 >> 2;
            int r = rem2 & 3;
            int gate = r & 1;
            int c = lane >> 2;
            int kk = (lane & 3) * 2 + (r >> 1) * 8;
            int kl = ksl * 16 + kk;
            float w0 = ws[kl][gate * 8 + c];
            float w1 = ws[kl + 1][gate * 8 + c];
            uint32_t val = term ? pack_lo(w0, w1) : pack_hi(w0, w1);
            int ks = kb * 16 + ksl;
            outp[((ks * 2 + term) * 32 + lane) * 4 + r] = val;
        }
        __syncthreads();
    }
}

// ---------------------------------------------------------------------------
// Fragment-resident tensor GEMM: C[M,N] = A @ B + bias.
// A hi/lo planes + B fragment buffer; no smem, no syncthreads.
// EMITC 1: also emit C as A-fragment planes (for the next GEMM).
// Grid: (N/64, M/64), 256 threads.
// ---------------------------------------------------------------------------
template <int EMITC>
__global__ __launch_bounds__(256)
void tgemm_f(const uint4* __restrict__ Ah, const uint4* __restrict__ Al,
             const uint4* __restrict__ Bf, const float* __restrict__ bias,
             float* __restrict__ C, uint4* __restrict__ Ch, uint4* __restrict__ Cl,
             int M, int N, int K, int ldc) {
    const int tid = threadIdx.x;
    const int lane = tid & 31;
    const int w = tid >> 5;
    const int mh = w >> 2;
    const int nq = w & 3;
    const int bm = blockIdx.y * 64;
    const int bn = blockIdx.x * 64;
    const int KT = K >> 4, NT = N >> 3;

    const int mt0 = (bm >> 4) + mh * 2;
    const uint4* A0h = Ah + ((size_t)mt0 * KT) * 32 + lane;
    const uint4* A0l = Al + ((size_t)mt0 * KT) * 32 + lane;
    const uint4* A1h = A0h + (size_t)KT * 32;
    const uint4* A1l = A0l + (size_t)KT * 32;
    const uint4* Bp0 = Bf + ((size_t)(bn >> 3) + nq * 2) * 32 + lane;

    float d[2][2][4];
#pragma unroll
    for (int i = 0; i < 2; i++)
#pragma unroll
        for (int j = 0; j < 2; j++)
#pragma unroll
            for (int q = 0; q < 4; q++) d[i][j][q] = 0.f;

#pragma unroll 4
    for (int kt = 0; kt < KT; kt++) {
        uint4 aH0 = __ldg(A0h + kt * 32);
        uint4 aL0 = __ldg(A0l + kt * 32);
        uint4 aH1 = __ldg(A1h + kt * 32);
        uint4 aL1 = __ldg(A1l + kt * 32);
        uint4 b0 = ldg128cg(Bp0 + (size_t)kt * NT * 32);
        uint4 b1 = ldg128cg(Bp0 + (size_t)kt * NT * 32 + 32);
        mma_acc(d[0][0], aH0, b0.x, b0.y);
        mma_acc(d[0][0], aH0, b0.z, b0.w);
        mma_acc(d[0][0], aL0, b0.x, b0.y);
        mma_acc(d[0][1], aH0, b1.x, b1.y);
        mma_acc(d[0][1], aH0, b1.z, b1.w);
        mma_acc(d[0][1], aL0, b1.x, b1.y);
        mma_acc(d[1][0], aH1, b0.x, b0.y);
        mma_acc(d[1][0], aH1, b0.z, b0.w);
        mma_acc(d[1][0], aL1, b0.x, b0.y);
        mma_acc(d[1][1], aH1, b1.x, b1.y);
        mma_acc(d[1][1], aH1, b1.z, b1.w);
        mma_acc(d[1][1], aL1, b1.x, b1.y);
    }

    const int g = lane >> 2, tg = lane & 3;
#pragma unroll
    for (int mti = 0; mti < 2; mti++) {
        int row0 = bm + (mh * 2 + mti) * 16 + g;
        float v[2][4];
#pragma unroll
        for (int nti = 0; nti < 2; nti++) {
            int col = bn + nq * 16 + nti * 8 + tg * 2;
            float b0v = bias ? bias[col] : 0.f;
            float b1v = bias ? bias[col + 1] : 0.f;
            v[nti][0] = d[mti][nti][0] + b0v;
            v[nti][1] = d[mti][nti][1] + b1v;
            v[nti][2] = d[mti][nti][2] + b0v;
            v[nti][3] = d[mti][nti][3] + b1v;
            C[(size_t)row0 * ldc + col]           = v[nti][0];
            C[(size_t)row0 * ldc + col + 1]       = v[nti][1];
            C[(size_t)(row0 + 8) * ldc + col]     = v[nti][2];
            C[(size_t)(row0 + 8) * ldc + col + 1] = v[nti][3];
        }
        if (EMITC) {
            // emit C as next-GEMM A-fragments: mtile=row0/16, ktile=(bn+nq*16)/16
            int KT2 = N >> 4;
            int mtile = (bm >> 4) + mh * 2 + mti;
            int ktile = (bn >> 4) + nq;
            size_t fi = ((size_t)mtile * KT2 + ktile) * 32 + lane;
            Ch[fi] = make_uint4(pack_hi(v[0][0], v[0][1]), pack_hi(v[0][2], v[0][3]),
                                pack_hi(v[1][0], v[1][1]), pack_hi(v[1][2], v[1][3]));
            Cl[fi] = make_uint4(pack_lo(v[0][0], v[0][1]), pack_lo(v[0][2], v[0][3]),
                                pack_lo(v[1][0], v[1][1]), pack_lo(v[1][2], v[1][3]));
        }
    }
}

// ---------------------------------------------------------------------------
// Persistent recurrence (unchanged from R8)
// ---------------------------------------------------------------------------
__global__ __launch_bounds__(RTHR, 1)
void rec_mma_kernel(const uint32_t* __restrict__ Wf,
                    uint32_t* __restrict__ Sf,
                    const int* __restrict__ input_data,
                    const float* __restrict__ Eh, const float* __restrict__ Et,
                    const float* __restrict__ bh, const float* __restrict__ bt,
                    float* __restrict__ states) {
    __shared__ float part[8][16][68];
    __shared__ float sold[64][9];
    __shared__ float bias_s[32];
    __shared__ float stage_st[64][8];

    const int tid = threadIdx.x;
    const int lane = tid & 31;
    const int w = tid >> 5;
    const int cta = blockIdx.x;
    const int cbase = cta * 8;
    const int eb = tid & 63;
    const int ec0 = (tid >> 6) * 2;

    for (int i = tid; i < 64 * 9; i += RTHR) ((float*)sold)[i] = 0.f;
    if (tid < 32) {
        int l2 = tid >> 4, g = (tid >> 3) & 1, c = tid & 7;
        bias_s[tid] = (g ? bt : bh)[l2 * R_ + cbase + c];
    }
    __syncthreads();

    float2 pe_h, pe_t;
    {
        int vid = __ldg(&input_data[eb * T_ + 0]);
        pe_h = ldcg64f(&Eh[(size_t)vid * R_ + cbase + ec0]);
        pe_t = ldcg64f(&Et[(size_t)vid * R_ + cbase + ec0]);
    }

    unsigned int pc = 0;
    int t = 0, l = 0;

    for (int p = 0; p < 3 * T_; p++) {
        const int rbuf = p & 1;
        const uint4* SB = (const uint4*)(Sf + rbuf * 32768);
        uint32_t* sOut = Sf + (rbuf ^ 1) * 32768;
        const uint4* WA = (const uint4*)Wf + (size_t)(l * 128 + cta) * 4096;

        float dH[8][4], dL[8][4];
#pragma unroll
        for (int g = 0; g < 8; g++)
#pragma unroll
            for (int q = 0; q < 4; q++) { dH[g][q] = 0.f; dL[g][q] = 0.f; }

        const int ks0 = w * 8;
#pragma unroll 4
        for (int j = 0; j < 8; j++) {
            int ks = ks0 + j;
            uint4 aH = __ldg(WA + (ks * 2 + 0) * 32 + lane);
            uint4 aL = __ldg(WA + (ks * 2 + 1) * 32 + lane);
            uint4 bF[4];
#pragma unroll
            for (int gp = 0; gp < 4; gp++)
                bF[gp] = ldg128cg(SB + (ks * 4 + gp) * 32 + lane);
#pragma unroll
            for (int gp = 0; gp < 4; gp++) {
                mma_acc(dH[2 * gp],     aH, bF[gp].x, bF[gp].y);
                mma_acc(dH[2 * gp + 1], aH, bF[gp].z, bF[gp].w);
                mma_acc(dL[2 * gp],     aL, bF[gp].x, bF[gp].y);
                mma_acc(dL[2 * gp + 1], aL, bF[gp].z, bF[gp].w);
            }
        }

        {
            int row = lane >> 2;
            int nb = (lane & 3) * 2;
#pragma unroll
            for (int g = 0; g < 8; g++) {
                *(float2*)&part[w][row][nb + g * 8] =
                    make_float2(dH[g][0] + dL[g][0], dH[g][1] + dL[g][1]);
                *(float2*)&part[w][row + 8][nb + g * 8] =
                    make_float2(dH[g][2] + dL[g][2], dH[g][3] + dL[g][3]);
            }
        }
        __syncthreads();

        {
            uint16_t sh[2];
#pragma unroll
            for (int s = 0; s < 2; s++) {
                int c = ec0 + s;
                float zh = 0.f, zt = 0.f;
#pragma unroll
                for (int q = 0; q < 8; q++) {
                    zh += part[q][c][eb];
                    zt += part[q][8 + c][eb];
                }
                if (l == 0) {
                    zh += (s == 0) ? pe_h.x : pe_h.y;
                    zt += (s == 0) ? pe_t.x : pe_t.y;
                } else {
                    zh += bias_s[(l - 1) * 16 + c];
                    zt += bias_s[(l - 1) * 16 + 8 + c];
                }
                float so = sold[eb][c];
                float hh = tanhf(zh);
                float tg = 1.f / (1.f + expf(-zt));
                float sn = (hh - so) * tg + so;
                sold[eb][c] = sn;
                sh[s] = __bfloat16_as_ushort(__float2bfloat16(sn));
                if (l == 2) stage_st[eb][c] = sn;
            }
            int kk0 = (cta & 1) * 8 + ec0;
            int q = (kk0 >> 1) & 3;
            int reg = cta & 1;
            int g = eb >> 3;
            int lt = (eb & 7) * 4 + q;
            int ks = cta >> 1;
            int slot = (g & 1) * 2 + reg;
            int gp = g >> 1;
            sOut[(uint32_t)(((ks * 4 + gp) * 32 + lt) * 4 + slot)] =
                ((uint32_t)sh[1] << 16) | sh[0];
        }

        if (l == 1) {
            int tq = (t < T_ - 1) ? t + 1 : t;
            int vid = __ldg(&input_data[eb * T_ + tq]);
            pe_h = ldcg64f(&Eh[(size_t)vid * R_ + cbase + ec0]);
            pe_t = ldcg64f(&Et[(size_t)vid * R_ + cbase + ec0]);
        }

        if (l == 2) {
            __syncthreads();
            if (tid < 128) {
                int rb = tid >> 1, half = tid & 1;
                *(float4*)&states[((size_t)t * B_ + rb) * R_ + cbase + half * 4] =
                    *(float4*)&stage_st[rb][half * 4];
            }
        }

        pc++;
        grid_sync(RCTA * pc, &g_bar);
        if (++l == 3) { l = 0; t++; }
    }
}

// ---------------------------------------------------------------------------
// Loss + mean
// ---------------------------------------------------------------------------
__global__ __launch_bounds__(256)
void loss_kernel(const float* __restrict__ outb,
                 const float* __restrict__ logits,
                 const int* __restrict__ targets,
                 const int* __restrict__ sampled,
                 const float* __restrict__ true_counts,
                 const float* __restrict__ sw,
                 const float* __restrict__ softmax_b,
                 float* __restrict__ loss) {
    __shared__ float red[256];
    __shared__ float sh_true, sh_max;
    const int i = blockIdx.x;
    const int tid = threadIdx.x;
    const int label = targets[i];

    float p = 0.f;
    for (int u = tid; u < U_; u += 256)
        p += outb[(size_t)i * U_ + u] * sw[(size_t)label * U_ + u];
    red[tid] = p; __syncthreads();
    for (int s = 128; s > 0; s >>= 1) {
        if (tid < s) red[tid] += red[tid + s];
        __syncthreads();
    }
    if (tid == 0) sh_true = red[0] + softmax_b[label] - logf(true_counts[i]);
    __syncthreads();
    const float tl = sh_true;

    float mx = -1e30f;
    for (int j = tid; j < S_; j += 256) {
        float v = logits[(size_t)i * S_ + j];
        if (sampled[j] == label) v -= 1e9f;
        mx = fmaxf(mx, v);
    }
    red[tid] = mx; __syncthreads();
    for (int s = 128; s > 0; s >>= 1) {
        if (tid < s) red[tid] = fmaxf(red[tid], red[tid + s]);
        __syncthreads();
    }
    if (tid == 0) sh_max = fmaxf(red[0], tl);
    __syncthreads();
    const float mval = sh_max;

    float sm = 0.f;
    for (int j = tid; j < S_; j += 256) {
        float v = logits[(size_t)i * S_ + j];
        if (sampled[j] == label) v -= 1e9f;
        sm += expf(v - mval);
    }
    red[tid] = sm; __syncthreads();
    for (int s = 128; s > 0; s >>= 1) {
        if (tid < s) red[tid] += red[tid + s];
        __syncthreads();
    }
    if (tid == 0) {
        float total = red[0] + expf(tl - mval);
        loss[i] = mval + logf(total) - tl;
    }
}

__global__ void reduce_mean_kernel(const float* __restrict__ loss, float* __restrict__ out) {
    __shared__ float red[256];
    const int tid = threadIdx.x;
    float s = 0.f;
    for (int i = tid; i < N_; i += 256) s += loss[i];
    red[tid] = s; __syncthreads();
    for (int st = 128; st > 0; st >>= 1) {
        if (tid < st) red[tid] += red[tid + st];
        __syncthreads();
    }
    if (tid == 0) out[0] = red[0] / (float)N_;
}

// ---------------------------------------------------------------------------
// Launch
// ---------------------------------------------------------------------------
extern "C" void kernel_launch(void* const* d_in, const int* in_sizes, int n_in,
                              void* d_out, int out_size) {
    const int*   input_data = (const int*)d_in[0];
    const int*   targets    = (const int*)d_in[1];
    const int*   sampled    = (const int*)d_in[2];
    const float* true_cnt   = (const float*)d_in[3];
    const float* samp_cnt   = (const float*)d_in[4];
    const float* embedding  = (const float*)d_in[5];
    const float* Wh0        = (const float*)d_in[6];
    const float* bh0        = (const float*)d_in[7];
    const float* Wt0        = (const float*)d_in[8];
    const float* bt0        = (const float*)d_in[9];
    const float* Wh         = (const float*)d_in[10];
    const float* bh         = (const float*)d_in[11];
    const float* Wt         = (const float*)d_in[12];
    const float* bt         = (const float*)d_in[13];
    const float* Wp         = (const float*)d_in[14];
    const float* bp         = (const float*)d_in[15];
    const float* sw         = (const float*)d_in[16];
    const float* smb        = (const float*)d_in[17];
    float* out = (float*)d_out;

    float *Eh, *Et, *states, *outb, *logits, *sbv, *lossv;
    uint32_t *Wf, *Sf;
    uint4 *BfEh, *BfEt, *BfOp, *BfLg;
    uint4 *AembH, *AembL, *AstH, *AstL, *AobH, *AobL;
    cudaGetSymbolAddress((void**)&Eh, g_Eh);
    cudaGetSymbolAddress((void**)&Et, g_Et);
    cudaGetSymbolAddress((void**)&states, g_states);
    cudaGetSymbolAddress((void**)&outb, g_outb);
    cudaGetSymbolAddress((void**)&logits, g_logits);
    cudaGetSymbolAddress((void**)&sbv, g_sbv);
    cudaGetSymbolAddress((void**)&lossv, g_loss);
    cudaGetSymbolAddress((void**)&Wf, g_Wf);
    cudaGetSymbolAddress((void**)&Sf, g_Sf);
    cudaGetSymbolAddress((void**)&BfEh, g_Bf_eh);
    cudaGetSymbolAddress((void**)&BfEt, g_Bf_et);
    cudaGetSymbolAddress((void**)&BfOp, g_Bf_op);
    cudaGetSymbolAddress((void**)&BfLg, g_Bf_lg);
    cudaGetSymbolAddress((void**)&AembH, g_Aemb_h);
    cudaGetSymbolAddress((void**)&AembL, g_Aemb_l);
    cudaGetSymbolAddress((void**)&AstH, g_Ast_h);
    cudaGetSymbolAddress((void**)&AstL, g_Ast_l);
    cudaGetSymbolAddress((void**)&AobH, g_Aob_h);
    cudaGetSymbolAddress((void**)&AobL, g_Aob_l);

    init_kernel<<<(2 * 32768 + 255) / 256, 256>>>(Sf);
    sb_kernel<<<(S_ + 255) / 256, 256>>>(sampled, smb, samp_cnt, sbv);
    wcvt_kernel<<<384, 256>>>(Wh0, Wt0, Wh, Wt, Wf);

    // B fragment preps
    prep_b_kn<<<512, 256>>>(Wh0, BfEh, U_, R_, R_);
    prep_b_kn<<<512, 256>>>(Wt0, BfEt, U_, R_, R_);
    prep_b_kn<<<512, 256>>>(Wp, BfOp, R_, U_, U_);
    prep_b_gather<<<512, 256>>>(sw, sampled, BfLg);

    // A fragment prep: embedding (shared by Eh and Et GEMMs)
    prep_a<0><<<2000, 256>>>(embedding, AembH, AembL, V_, U_, U_);

    // Vocab-space x-part precompute (fragment tensor GEMM)
    {
        dim3 grid(R_ / 64, V_ / 64);
        tgemm_f<0><<<grid, 256>>>(AembH, AembL, BfEh, bh0, Eh, nullptr, nullptr,
                                  V_, R_, U_, R_);
        tgemm_f<0><<<grid, 256>>>(AembH, AembL, BfEt, bt0, Et, nullptr, nullptr,
                                  V_, R_, U_, R_);
    }

    // Persistent recurrence
    rec_mma_kernel<<<RCTA, RTHR>>>(Wf, Sf, input_data, Eh, Et, bh, bt, states);

    // states -> A fragments (with (t,b)->row remap)
    prep_a<1><<<8192, 256>>>(states, AstH, AstL, N_, R_, R_);

    // outputs = states @ Wp + bp ; also emits outb A-fragments
    {
        dim3 grid(U_ / 64, N_ / 64);
        tgemm_f<1><<<grid, 256>>>(AstH, AstL, BfOp, bp, outb, AobH, AobL,
                                  N_, U_, R_, U_);
    }
    // sampled logits = outb @ sw[sampled].T + sbv
    {
        dim3 grid(S_ / 64, N_ / 64);
        tgemm_f<0><<<grid, 256>>>(AobH, AobL, BfLg, sbv, logits, nullptr, nullptr,
                                  N_, S_, U_, S_);
    }

    loss_kernel<<<N_, 256>>>(outb, logits, targets, sampled, true_cnt, sw, smb, lossv);
    reduce_mean_kernel<<<1, 256>>>(lossv, out);
}

// round 12
// speedup vs baseline: 5.3272x; 1.0875x over previous
#include <cuda_runtime.h>
#include <cuda_bf16.h>
#include <math.h>
#include <stdint.h>

#define V_ 8000
#define B_ 64
#define T_ 256
#define R_ 1024
#define U_ 512
#define S_ 1024
#define N_ (B_ * T_)

#define RCTA 128
#define RTHR 256

// ---------------------------------------------------------------------------
// Device global scratch
// ---------------------------------------------------------------------------
__device__ float g_Eh[(size_t)V_ * R_];
__device__ float g_Et[(size_t)V_ * R_];
__device__ float g_states[(size_t)T_ * B_ * R_];
__device__ uint32_t g_Wf[(size_t)3 * 128 * 16384];
__device__ uint32_t g_Sf[2 * 32768];
__device__ float g_outb[(size_t)N_ * U_];
__device__ float g_logits[(size_t)N_ * S_];
__device__ float g_sbv[S_];
__device__ float g_loss[N_];
__device__ unsigned int g_bar;
// B fragment buffers: [K/16][N/8][lane32] uint4{hi0,hi1,lo0,lo1}
__device__ uint4 g_Bf_eh[131072];   // Wh0[0:U]:       K=512,  N=1024
__device__ uint4 g_Bf_et[131072];   // Wt0[0:U]
__device__ uint4 g_Bf_op[131072];   // Wp:             K=1024, N=512
__device__ uint4 g_Bf_lg[131072];   // sw[sampled].T:  K=512,  N=1024
// A fragment planes (bf16 hi only): [M/16][K/16][lane32] uint4
__device__ uint4 g_Aemb_h[512000];    // embedding 8000x512
__device__ uint4 g_Ast_h[2097152];    // states(remap) 16384x1024
__device__ uint4 g_Aob_h[1048576];    // outb 16384x512

// ---------------------------------------------------------------------------
// PTX helpers
// ---------------------------------------------------------------------------
__device__ __forceinline__ void mma_acc(float* d, const uint4& a, uint32_t b0, uint32_t b1) {
    asm volatile(
        "mma.sync.aligned.m16n8k16.row.col.f32.bf16.bf16.f32 "
        "{%0,%1,%2,%3},{%4,%5,%6,%7},{%8,%9},{%0,%1,%2,%3};"
        : "+f"(d[0]), "+f"(d[1]), "+f"(d[2]), "+f"(d[3])
        : "r"(a.x), "r"(a.y), "r"(a.z), "r"(a.w), "r"(b0), "r"(b1));
}
__device__ __forceinline__ uint4 ldg128cg(const uint4* p) {
    uint4 v;
    asm volatile("ld.global.cg.v4.u32 {%0,%1,%2,%3}, [%4];"
                 : "=r"(v.x), "=r"(v.y), "=r"(v.z), "=r"(v.w) : "l"(p));
    return v;
}
__device__ __forceinline__ float2 ldcg64f(const float* p) {
    float2 v;
    asm volatile("ld.global.cg.v2.f32 {%0,%1}, [%2];" : "=f"(v.x), "=f"(v.y) : "l"(p));
    return v;
}
__device__ __forceinline__ void grid_sync(unsigned int target, unsigned int* bar) {
    __syncthreads();
    if (threadIdx.x == 0) {
        asm volatile("red.release.gpu.global.add.u32 [%0], 1;" :: "l"(bar) : "memory");
        unsigned int v;
        do {
            asm volatile("ld.acquire.gpu.global.u32 %0, [%1];" : "=r"(v) : "l"(bar) : "memory");
        } while (v < target);
    }
    __syncthreads();
}
__device__ __forceinline__ uint32_t pack_hi(float x0, float x1) {
    uint16_t h0 = __bfloat16_as_ushort(__float2bfloat16(x0));
    uint16_t h1 = __bfloat16_as_ushort(__float2bfloat16(x1));
    return ((uint32_t)h1 << 16) | h0;
}
__device__ __forceinline__ uint32_t pack_lo(float x0, float x1) {
    float r0 = x0 - __bfloat162float(__float2bfloat16(x0));
    float r1 = x1 - __bfloat162float(__float2bfloat16(x1));
    return pack_hi(r0, r1);
}
__device__ __forceinline__ float tanh_ap(float x) {
    float y;
    asm("tanh.approx.f32 %0, %1;" : "=f"(y) : "f"(x));
    return y;
}
__device__ __forceinline__ float sigm_ap(float x) {
    float e;
    asm("ex2.approx.f32 %0, %1;" : "=f"(e) : "f"(-x * 1.4426950408889634f));
    float r;
    asm("rcp.approx.f32 %0, %1;" : "=f"(r) : "f"(1.f + e));
    return r;
}

// ---------------------------------------------------------------------------
// Setup kernels
// ---------------------------------------------------------------------------
__global__ void init_kernel(uint32_t* sf) {
    int i = blockIdx.x * 256 + threadIdx.x;
    if (i == 0) g_bar = 0u;
    if (i < 2 * 32768) sf[i] = 0u;
}

__global__ void sb_kernel(const int* __restrict__ sampled,
                          const float* __restrict__ softmax_b,
                          const float* __restrict__ scounts,
                          float* __restrict__ sbv) {
    int j = blockIdx.x * 256 + threadIdx.x;
    if (j < S_) sbv[j] = softmax_b[sampled[j]] - logf(scounts[j]);
}

// B-fragment prep from row-major src[k][n]
__global__ __launch_bounds__(256)
void prep_b_kn(const float* __restrict__ src, uint4* __restrict__ out,
               int K, int N, int ldb) {
    int idx = blockIdx.x * 256 + threadIdx.x;
    int total = (K >> 4) * (N >> 3) * 32;
    if (idx >= total) return;
    int lane = idx & 31;
    int nt = (idx >> 5) % (N >> 3);
    int gks = (idx >> 5) / (N >> 3);
    int g = lane >> 2, tg = lane & 3;
    int n = nt * 8 + g;
    int k0 = gks * 16 + tg * 2;
    float a0 = src[(size_t)k0 * ldb + n];
    float a1 = src[(size_t)(k0 + 1) * ldb + n];
    float a2 = src[(size_t)(k0 + 8) * ldb + n];
    float a3 = src[(size_t)(k0 + 9) * ldb + n];
    out[idx] = make_uint4(pack_hi(a0, a1), pack_hi(a2, a3),
                          pack_lo(a0, a1), pack_lo(a2, a3));
}

__global__ __launch_bounds__(256)
void prep_b_gather(const float* __restrict__ sw, const int* __restrict__ sampled,
                   uint4* __restrict__ out) {
    int idx = blockIdx.x * 256 + threadIdx.x;
    const int K = U_, N = S_;
    int total = (K >> 4) * (N >> 3) * 32;
    if (idx >= total) return;
    int lane = idx & 31;
    int nt = (idx >> 5) % (N >> 3);
    int gks = (idx >> 5) / (N >> 3);
    int g = lane >> 2, tg = lane & 3;
    int n = nt * 8 + g;
    int k0 = gks * 16 + tg * 2;
    const float* row = sw + (size_t)sampled[n] * U_;
    float a0 = row[k0], a1 = row[k0 + 1], a2 = row[k0 + 8], a3 = row[k0 + 9];
    out[idx] = make_uint4(pack_hi(a0, a1), pack_hi(a2, a3),
                          pack_lo(a0, a1), pack_lo(a2, a3));
}

// A-fragment prep (hi plane only). REMAP 1: row = (row%T)*B + row/T
template <int REMAP>
__global__ __launch_bounds__(256)
void prep_a(const float* __restrict__ src, uint4* __restrict__ hi,
            int M, int K, int lda) {
    int idx = blockIdx.x * 256 + threadIdx.x;
    int total = (M >> 4) * (K >> 4) * 32;
    if (idx >= total) return;
    int lane = idx & 31;
    int kt = (idx >> 5) % (K >> 4);
    int mt = (idx >> 5) / (K >> 4);
    int r = lane >> 2;
    int k0 = kt * 16 + (lane & 3) * 2;
    int row0 = mt * 16 + r, row1 = row0 + 8;
    const float *p0, *p1;
    if (REMAP) {
        p0 = src + (size_t)((row0 % T_) * B_ + row0 / T_) * lda;
        p1 = src + (size_t)((row1 % T_) * B_ + row1 / T_) * lda;
    } else {
        p0 = src + (size_t)row0 * lda;
        p1 = src + (size_t)row1 * lda;
    }
    float2 v0 = *(const float2*)(p0 + k0);
    float2 v1 = *(const float2*)(p1 + k0);
    float2 v2 = *(const float2*)(p0 + k0 + 8);
    float2 v3 = *(const float2*)(p1 + k0 + 8);
    hi[idx] = make_uint4(pack_hi(v0.x, v0.y), pack_hi(v1.x, v1.y),
                         pack_hi(v2.x, v2.y), pack_hi(v3.x, v3.y));
}

// Weight -> fragment-linear bf16 hi/lo for recurrence (unchanged).
__global__ __launch_bounds__(256)
void wcvt_kernel(const float* __restrict__ Wh0, const float* __restrict__ Wt0,
                 const float* __restrict__ Wh,  const float* __restrict__ Wt,
                 uint32_t* __restrict__ Wf) {
    __shared__ float ws[256][17];
    int b = blockIdx.x;
    int cta = b & 127;
    int l = b >> 7;
    int cbase = cta * 8;
    int tid = threadIdx.x;
    uint32_t* outp = Wf + (size_t)(l * 128 + cta) * 16384;

    for (int kb = 0; kb < 4; kb++) {
#pragma unroll
        for (int e = 0; e < 16; e++) {
            int idx = tid + e * 256;
            int k = idx >> 4, cg = idx & 15;
            int g = cg >> 3, c = cg & 7;
            int kg = kb * 256 + k;
            float v;
            if (l == 0) v = (g ? Wt0 : Wh0)[(size_t)(U_ + kg) * R_ + cbase + c];
            else        v = (g ? Wt : Wh)[((size_t)(l - 1) * R_ + kg) * R_ + cbase + c];
            ws[k][g * 8 + c] = v;
        }
        __syncthreads();
#pragma unroll
        for (int e = 0; e < 16; e++) {
            int o = tid + e * 256;
            int ksl = o >> 8;
            int rem = o & 255;
            int term = rem >> 7;
            int rem2 = rem & 127;
            int lane = rem2 >> 2;
            int r = rem2 & 3;
            int gate = r & 1;
            int c = lane >> 2;
            int kk = (lane & 3) * 2 + (r >> 1) * 8;
            int kl = ksl * 16 + kk;
            float w0 = ws[kl][gate * 8 + c];
            float w1 = ws[kl + 1][gate * 8 + c];
            uint32_t val = term ? pack_lo(w0, w1) : pack_hi(w0, w1);
            int ks = kb * 16 + ksl;
            outp[((ks * 2 + term) * 32 + lane) * 4 + r] = val;
        }
        __syncthreads();
    }
}

// ---------------------------------------------------------------------------
// Fragment tensor GEMM (2-term: Ahi*Bhi + Ahi*Blo). No smem, no syncs.
// EMITC 1: also emit C as A-fragment hi plane.
// ---------------------------------------------------------------------------
template <int EMITC>
__global__ __launch_bounds__(256)
void tgemm_f(const uint4* __restrict__ Ah, const uint4* __restrict__ Bf,
             const float* __restrict__ bias, float* __restrict__ C,
             uint4* __restrict__ Ch, int M, int N, int K, int ldc) {
    const int tid = threadIdx.x;
    const int lane = tid & 31;
    const int w = tid >> 5;
    const int mh = w >> 2;
    const int nq = w & 3;
    const int bm = blockIdx.y * 64;
    const int bn = blockIdx.x * 64;
    const int KT = K >> 4, NT = N >> 3;

    const int mt0 = (bm >> 4) + mh * 2;
    const uint4* A0h = Ah + ((size_t)mt0 * KT) * 32 + lane;
    const uint4* A1h = A0h + (size_t)KT * 32;
    const uint4* Bp0 = Bf + ((size_t)(bn >> 3) + nq * 2) * 32 + lane;

    float d[2][2][4];
#pragma unroll
    for (int i = 0; i < 2; i++)
#pragma unroll
        for (int j = 0; j < 2; j++)
#pragma unroll
            for (int q = 0; q < 4; q++) d[i][j][q] = 0.f;

#pragma unroll 4
    for (int kt = 0; kt < KT; kt++) {
        uint4 aH0 = __ldg(A0h + kt * 32);
        uint4 aH1 = __ldg(A1h + kt * 32);
        uint4 b0 = ldg128cg(Bp0 + (size_t)kt * NT * 32);
        uint4 b1 = ldg128cg(Bp0 + (size_t)kt * NT * 32 + 32);
        mma_acc(d[0][0], aH0, b0.x, b0.y);
        mma_acc(d[0][0], aH0, b0.z, b0.w);
        mma_acc(d[0][1], aH0, b1.x, b1.y);
        mma_acc(d[0][1], aH0, b1.z, b1.w);
        mma_acc(d[1][0], aH1, b0.x, b0.y);
        mma_acc(d[1][0], aH1, b0.z, b0.w);
        mma_acc(d[1][1], aH1, b1.x, b1.y);
        mma_acc(d[1][1], aH1, b1.z, b1.w);
    }

    const int g = lane >> 2, tg = lane & 3;
#pragma unroll
    for (int mti = 0; mti < 2; mti++) {
        int row0 = bm + (mh * 2 + mti) * 16 + g;
        float v[2][4];
#pragma unroll
        for (int nti = 0; nti < 2; nti++) {
            int col = bn + nq * 16 + nti * 8 + tg * 2;
            float b0v = bias ? bias[col] : 0.f;
            float b1v = bias ? bias[col + 1] : 0.f;
            v[nti][0] = d[mti][nti][0] + b0v;
            v[nti][1] = d[mti][nti][1] + b1v;
            v[nti][2] = d[mti][nti][2] + b0v;
            v[nti][3] = d[mti][nti][3] + b1v;
            C[(size_t)row0 * ldc + col]           = v[nti][0];
            C[(size_t)row0 * ldc + col + 1]       = v[nti][1];
            C[(size_t)(row0 + 8) * ldc + col]     = v[nti][2];
            C[(size_t)(row0 + 8) * ldc + col + 1] = v[nti][3];
        }
        if (EMITC) {
            int KT2 = N >> 4;
            int mtile = (bm >> 4) + mh * 2 + mti;
            int ktile = (bn >> 4) + nq;
            size_t fi = ((size_t)mtile * KT2 + ktile) * 32 + lane;
            Ch[fi] = make_uint4(pack_hi(v[0][0], v[0][1]), pack_hi(v[0][2], v[0][3]),
                                pack_hi(v[1][0], v[1][1]), pack_hi(v[1][2], v[1][3]));
        }
    }
}

// ---------------------------------------------------------------------------
// Persistent recurrence (R8 structure + approx activations)
// ---------------------------------------------------------------------------
__global__ __launch_bounds__(RTHR, 1)
void rec_mma_kernel(const uint32_t* __restrict__ Wf,
                    uint32_t* __restrict__ Sf,
                    const int* __restrict__ input_data,
                    const float* __restrict__ Eh, const float* __restrict__ Et,
                    const float* __restrict__ bh, const float* __restrict__ bt,
                    float* __restrict__ states) {
    __shared__ float part[8][16][68];
    __shared__ float sold[64][9];
    __shared__ float bias_s[32];
    __shared__ float stage_st[64][8];

    const int tid = threadIdx.x;
    const int lane = tid & 31;
    const int w = tid >> 5;
    const int cta = blockIdx.x;
    const int cbase = cta * 8;
    const int eb = tid & 63;
    const int ec0 = (tid >> 6) * 2;

    for (int i = tid; i < 64 * 9; i += RTHR) ((float*)sold)[i] = 0.f;
    if (tid < 32) {
        int l2 = tid >> 4, g = (tid >> 3) & 1, c = tid & 7;
        bias_s[tid] = (g ? bt : bh)[l2 * R_ + cbase + c];
    }
    __syncthreads();

    float2 pe_h, pe_t;
    {
        int vid = __ldg(&input_data[eb * T_ + 0]);
        pe_h = ldcg64f(&Eh[(size_t)vid * R_ + cbase + ec0]);
        pe_t = ldcg64f(&Et[(size_t)vid * R_ + cbase + ec0]);
    }

    unsigned int pc = 0;
    int t = 0, l = 0;

    for (int p = 0; p < 3 * T_; p++) {
        const int rbuf = p & 1;
        const uint4* SB = (const uint4*)(Sf + rbuf * 32768);
        uint32_t* sOut = Sf + (rbuf ^ 1) * 32768;
        const uint4* WA = (const uint4*)Wf + (size_t)(l * 128 + cta) * 4096;

        float dH[8][4], dL[8][4];
#pragma unroll
        for (int g = 0; g < 8; g++)
#pragma unroll
            for (int q = 0; q < 4; q++) { dH[g][q] = 0.f; dL[g][q] = 0.f; }

        const int ks0 = w * 8;
#pragma unroll 4
        for (int j = 0; j < 8; j++) {
            int ks = ks0 + j;
            uint4 aH = __ldg(WA + (ks * 2 + 0) * 32 + lane);
            uint4 aL = __ldg(WA + (ks * 2 + 1) * 32 + lane);
            uint4 bF[4];
#pragma unroll
            for (int gp = 0; gp < 4; gp++)
                bF[gp] = ldg128cg(SB + (ks * 4 + gp) * 32 + lane);
#pragma unroll
            for (int gp = 0; gp < 4; gp++) {
                mma_acc(dH[2 * gp],     aH, bF[gp].x, bF[gp].y);
                mma_acc(dH[2 * gp + 1], aH, bF[gp].z, bF[gp].w);
                mma_acc(dL[2 * gp],     aL, bF[gp].x, bF[gp].y);
                mma_acc(dL[2 * gp + 1], aL, bF[gp].z, bF[gp].w);
            }
        }

        {
            int row = lane >> 2;
            int nb = (lane & 3) * 2;
#pragma unroll
            for (int g = 0; g < 8; g++) {
                *(float2*)&part[w][row][nb + g * 8] =
                    make_float2(dH[g][0] + dL[g][0], dH[g][1] + dL[g][1]);
                *(float2*)&part[w][row + 8][nb + g * 8] =
                    make_float2(dH[g][2] + dL[g][2], dH[g][3] + dL[g][3]);
            }
        }
        __syncthreads();

        {
            uint16_t sh[2];
#pragma unroll
            for (int s = 0; s < 2; s++) {
                int c = ec0 + s;
                float zh = 0.f, zt = 0.f;
#pragma unroll
                for (int q = 0; q < 8; q++) {
                    zh += part[q][c][eb];
                    zt += part[q][8 + c][eb];
                }
                if (l == 0) {
                    zh += (s == 0) ? pe_h.x : pe_h.y;
                    zt += (s == 0) ? pe_t.x : pe_t.y;
                } else {
                    zh += bias_s[(l - 1) * 16 + c];
                    zt += bias_s[(l - 1) * 16 + 8 + c];
                }
                float so = sold[eb][c];
                float hh = tanh_ap(zh);
                float tg = sigm_ap(zt);
                float sn = (hh - so) * tg + so;
                sold[eb][c] = sn;
                sh[s] = __bfloat16_as_ushort(__float2bfloat16(sn));
                if (l == 2) stage_st[eb][c] = sn;
            }
            int kk0 = (cta & 1) * 8 + ec0;
            int q = (kk0 >> 1) & 3;
            int reg = cta & 1;
            int g = eb >> 3;
            int lt = (eb & 7) * 4 + q;
            int ks = cta >> 1;
            int slot = (g & 1) * 2 + reg;
            int gp = g >> 1;
            sOut[(uint32_t)(((ks * 4 + gp) * 32 + lt) * 4 + slot)] =
                ((uint32_t)sh[1] << 16) | sh[0];
        }

        if (l == 1) {
            int tq = (t < T_ - 1) ? t + 1 : t;
            int vid = __ldg(&input_data[eb * T_ + tq]);
            pe_h = ldcg64f(&Eh[(size_t)vid * R_ + cbase + ec0]);
            pe_t = ldcg64f(&Et[(size_t)vid * R_ + cbase + ec0]);
        }

        if (l == 2) {
            __syncthreads();
            if (tid < 128) {
                int rb = tid >> 1, half = tid & 1;
                *(float4*)&states[((size_t)t * B_ + rb) * R_ + cbase + half * 4] =
                    *(float4*)&stage_st[rb][half * 4];
            }
        }

        pc++;
        grid_sync(RCTA * pc, &g_bar);
        if (++l == 3) { l = 0; t++; }
    }
}

// ---------------------------------------------------------------------------
// Loss (single-pass online softmax) + mean
// ---------------------------------------------------------------------------
__global__ __launch_bounds__(256)
void loss_kernel(const float* __restrict__ outb,
                 const float* __restrict__ logits,
                 const int* __restrict__ targets,
                 const int* __restrict__ sampled,
                 const float* __restrict__ true_counts,
                 const float* __restrict__ sw,
                 const float* __restrict__ softmax_b,
                 float* __restrict__ loss) {
    __shared__ float rm[256], rs[256];
    __shared__ float sh_true;
    const int i = blockIdx.x;
    const int tid = threadIdx.x;
    const int label = targets[i];

    // true logit
    float pdot = 0.f;
    for (int u = tid; u < U_; u += 256)
        pdot += outb[(size_t)i * U_ + u] * sw[(size_t)label * U_ + u];
    rm[tid] = pdot; __syncthreads();
    for (int s = 128; s > 0; s >>= 1) {
        if (tid < s) rm[tid] += rm[tid + s];
        __syncthreads();
    }
    if (tid == 0) sh_true = rm[0] + softmax_b[label] - logf(true_counts[i]);
    __syncthreads();
    const float tl = sh_true;

    // online softmax over sampled logits (single pass)
    float m = -1e30f, ssum = 0.f;
    for (int j = tid; j < S_; j += 256) {
        float v = logits[(size_t)i * S_ + j];
        if (sampled[j] == label) v -= 1e9f;
        if (v <= m) {
            ssum += __expf(v - m);
        } else {
            ssum = ssum * __expf(m - v) + 1.f;
            m = v;
        }
    }
    rm[tid] = m; rs[tid] = ssum;
    __syncthreads();
    for (int s = 128; s > 0; s >>= 1) {
        if (tid < s) {
            float m2 = rm[tid + s], s2 = rs[tid + s];
            float m1 = rm[tid], s1 = rs[tid];
            float nm = fmaxf(m1, m2);
            rs[tid] = s1 * __expf(m1 - nm) + s2 * __expf(m2 - nm);
            rm[tid] = nm;
        }
        __syncthreads();
    }
    if (tid == 0) {
        float m0 = rm[0], s0 = rs[0];
        float nm = fmaxf(m0, tl);
        float total = s0 * __expf(m0 - nm) + __expf(tl - nm);
        loss[i] = nm + logf(total) - tl;
    }
}

__global__ void reduce_mean_kernel(const float* __restrict__ loss, float* __restrict__ out) {
    __shared__ float red[256];
    const int tid = threadIdx.x;
    float s = 0.f;
    for (int i = tid; i < N_; i += 256) s += loss[i];
    red[tid] = s; __syncthreads();
    for (int st = 128; st > 0; st >>= 1) {
        if (tid < st) red[tid] += red[tid + st];
        __syncthreads();
    }
    if (tid == 0) out[0] = red[0] / (float)N_;
}

// ---------------------------------------------------------------------------
// Launch
// ---------------------------------------------------------------------------
extern "C" void kernel_launch(void* const* d_in, const int* in_sizes, int n_in,
                              void* d_out, int out_size) {
    const int*   input_data = (const int*)d_in[0];
    const int*   targets    = (const int*)d_in[1];
    const int*   sampled    = (const int*)d_in[2];
    const float* true_cnt   = (const float*)d_in[3];
    const float* samp_cnt   = (const float*)d_in[4];
    const float* embedding  = (const float*)d_in[5];
    const float* Wh0        = (const float*)d_in[6];
    const float* bh0        = (const float*)d_in[7];
    const float* Wt0        = (const float*)d_in[8];
    const float* bt0        = (const float*)d_in[9];
    const float* Wh         = (const float*)d_in[10];
    const float* bh         = (const float*)d_in[11];
    const float* Wt         = (const float*)d_in[12];
    const float* bt         = (const float*)d_in[13];
    const float* Wp         = (const float*)d_in[14];
    const float* bp         = (const float*)d_in[15];
    const float* sw         = (const float*)d_in[16];
    const float* smb        = (const float*)d_in[17];
    float* out = (float*)d_out;

    float *Eh, *Et, *states, *outb, *logits, *sbv, *lossv;
    uint32_t *Wf, *Sf;
    uint4 *BfEh, *BfEt, *BfOp, *BfLg;
    uint4 *AembH, *AstH, *AobH;
    cudaGetSymbolAddress((void**)&Eh, g_Eh);
    cudaGetSymbolAddress((void**)&Et, g_Et);
    cudaGetSymbolAddress((void**)&states, g_states);
    cudaGetSymbolAddress((void**)&outb, g_outb);
    cudaGetSymbolAddress((void**)&logits, g_logits);
    cudaGetSymbolAddress((void**)&sbv, g_sbv);
    cudaGetSymbolAddress((void**)&lossv, g_loss);
    cudaGetSymbolAddress((void**)&Wf, g_Wf);
    cudaGetSymbolAddress((void**)&Sf, g_Sf);
    cudaGetSymbolAddress((void**)&BfEh, g_Bf_eh);
    cudaGetSymbolAddress((void**)&BfEt, g_Bf_et);
    cudaGetSymbolAddress((void**)&BfOp, g_Bf_op);
    cudaGetSymbolAddress((void**)&BfLg, g_Bf_lg);
    cudaGetSymbolAddress((void**)&AembH, g_Aemb_h);
    cudaGetSymbolAddress((void**)&AstH, g_Ast_h);
    cudaGetSymbolAddress((void**)&AobH, g_Aob_h);

    init_kernel<<<(2 * 32768 + 255) / 256, 256>>>(Sf);
    sb_kernel<<<(S_ + 255) / 256, 256>>>(sampled, smb, samp_cnt, sbv);
    wcvt_kernel<<<384, 256>>>(Wh0, Wt0, Wh, Wt, Wf);

    // B fragment preps
    prep_b_kn<<<512, 256>>>(Wh0, BfEh, U_, R_, R_);
    prep_b_kn<<<512, 256>>>(Wt0, BfEt, U_, R_, R_);
    prep_b_kn<<<512, 256>>>(Wp, BfOp, R_, U_, U_);
    prep_b_gather<<<512, 256>>>(sw, sampled, BfLg);

    // A fragment prep: embedding (shared by Eh and Et GEMMs)
    prep_a<0><<<2000, 256>>>(embedding, AembH, V_, U_, U_);

    // Vocab-space x-part precompute
    {
        dim3 grid(R_ / 64, V_ / 64);
        tgemm_f<0><<<grid, 256>>>(AembH, BfEh, bh0, Eh, nullptr, V_, R_, U_, R_);
        tgemm_f<0><<<grid, 256>>>(AembH, BfEt, bt0, Et, nullptr, V_, R_, U_, R_);
    }

    // Persistent recurrence
    rec_mma_kernel<<<RCTA, RTHR>>>(Wf, Sf, input_data, Eh, Et, bh, bt, states);

    // states -> A fragments (remap)
    prep_a<1><<<8192, 256>>>(states, AstH, N_, R_, R_);

    // outputs = states @ Wp + bp ; emits outb A-fragments
    {
        dim3 grid(U_ / 64, N_ / 64);
        tgemm_f<1><<<grid, 256>>>(AstH, BfOp, bp, outb, AobH, N_, U_, R_, U_);
    }
    // sampled logits = outb @ sw[sampled].T + sbv
    {
        dim3 grid(S_ / 64, N_ / 64);
        tgemm_f<0><<<grid, 256>>>(AobH, BfLg, sbv, logits, nullptr, N_, S_, U_, S_);
    }

    loss_kernel<<<N_, 256>>>(outb, logits, targets, sampled, true_cnt, sw, smb, lossv);
    reduce_mean_kernel<<<1, 256>>>(lossv, out);
}